// round 1
// baseline (speedup 1.0000x reference)
#include <cuda_runtime.h>
#include <math.h>

#define TOK   65536     // B*H*W tokens
#define NSEQ  16384     // tokens per batch
#define CDIM  256
#define INNERD 512
#define NHEAD 8
#define DHEAD 64
#define NF    256
#define NZ    32        // B*NHEAD
#define KCHUNKS 16

// ---------------- scratch (static device globals; no allocation) -------------
__device__ float g_Q[TOK * INNERD];
__device__ float g_K[TOK * INNERD];
__device__ float g_V[TOK * INNERD];
__device__ float g_QP[(long long)NZ * NSEQ * NF];
__device__ float g_KP[(long long)NZ * NSEQ * NF];
__device__ float g_ATT[TOK * INNERD];
__device__ float g_Y1[TOK * CDIM];
__device__ float g_projT[DHEAD * NF];
__device__ float g_kmax[NZ];
__device__ float g_ksumP[NZ * KCHUNKS * NF];
__device__ float g_ksum[NZ * NF];
__device__ float g_ctx[NZ * NF * DHEAD];
__device__ float g_dinv[NZ * NSEQ];

// ---------------- small helpers ----------------------------------------------
__device__ __forceinline__ void atomicMaxFloat(float* addr, float val) {
    if (val >= 0.f) atomicMax((int*)addr, __float_as_int(val));
    else            atomicMin((unsigned int*)addr, (unsigned int)__float_as_int(val));
}

__global__ void init_kernel() {
    int t = threadIdx.x;
    if (t < NZ) g_kmax[t] = -INFINITY;
}

__global__ void transpose_proj(const float* __restrict__ proj) {
    int t = blockIdx.x * 256 + threadIdx.x;   // 64*256 elems, grid=64
    int d = t >> 8, f = t & 255;
    g_projT[d * NF + f] = proj[f * DHEAD + d];
}

// ---------------- generic batched strided SGEMM -------------------------------
// C[M,N] = alpha * A[M,K] @ B[K,N]  (+epilogue), tiles 128x64, BK=16, 256 thr
// EPI: 0 none | 1 +bias[n] | 2 +bias[n]+relbias(aux table) | 3 *aux[row]
template <int EPI>
__global__ __launch_bounds__(256) void sgemm(
    const float* __restrict__ A, const float* __restrict__ B, float* __restrict__ C,
    int M, int N, int K, int lda, int ldb, int ldc,
    int zdiv,
    long long aAb, long long aAh, long long aBb, long long aBh,
    long long aCb, long long aCh,
    float alpha,
    const float* __restrict__ bias, const float* __restrict__ aux,
    long long aXb, long long aXh)
{
    int z = blockIdx.z;
    int zb = z / zdiv, zh = z % zdiv;
    A += zb * aAb + zh * aAh;
    B += zb * aBb + zh * aBh;
    C += zb * aCb + zh * aCh;
    if (aux) aux += zb * aXb + zh * aXh;

    __shared__ float As[16][128];
    __shared__ float Bs[16][64];

    int tid = threadIdx.x;
    int tx = tid & 15, ty = tid >> 4;
    int m0 = blockIdx.y * 128, n0 = blockIdx.x * 64;

    float acc[8][4];
#pragma unroll
    for (int i = 0; i < 8; i++)
#pragma unroll
        for (int j = 0; j < 4; j++) acc[i][j] = 0.f;

    for (int k0 = 0; k0 < K; k0 += 16) {
#pragma unroll
        for (int i = 0; i < 2; i++) {
            int idx = tid + i * 256;
            int m = idx >> 2, kq = idx & 3;
            const float4 av = *(const float4*)&A[(long long)(m0 + m) * lda + k0 + kq * 4];
            As[kq * 4 + 0][m] = av.x;
            As[kq * 4 + 1][m] = av.y;
            As[kq * 4 + 2][m] = av.z;
            As[kq * 4 + 3][m] = av.w;
        }
        {
            int k = tid >> 4, nq = tid & 15;
            *(float4*)&Bs[k][nq * 4] =
                *(const float4*)&B[(long long)(k0 + k) * ldb + n0 + nq * 4];
        }
        __syncthreads();
#pragma unroll
        for (int k = 0; k < 16; k++) {
            float4 a0 = *(const float4*)&As[k][ty * 8];
            float4 a1 = *(const float4*)&As[k][ty * 8 + 4];
            float4 b4 = *(const float4*)&Bs[k][tx * 4];
            float a[8] = {a0.x, a0.y, a0.z, a0.w, a1.x, a1.y, a1.z, a1.w};
            float bb[4] = {b4.x, b4.y, b4.z, b4.w};
#pragma unroll
            for (int i = 0; i < 8; i++)
#pragma unroll
                for (int j = 0; j < 4; j++) acc[i][j] += a[i] * bb[j];
        }
        __syncthreads();
    }

    float4 bias4 = make_float4(0.f, 0.f, 0.f, 0.f);
    if (EPI == 1 || EPI == 2) bias4 = *(const float4*)&bias[n0 + tx * 4];

#pragma unroll
    for (int i = 0; i < 8; i++) {
        int gm = m0 + ty * 8 + i;
        float4 v;
        v.x = acc[i][0] * alpha;
        v.y = acc[i][1] * alpha;
        v.z = acc[i][2] * alpha;
        v.w = acc[i][3] * alpha;
        if (EPI == 1 || EPI == 2) {
            v.x += bias4.x; v.y += bias4.y; v.z += bias4.z; v.w += bias4.w;
        }
        if (EPI == 2) {
            int h = (gm >> 7) & 127, w = gm & 127;
            int rel = h - w;
            rel = rel < -7 ? -7 : (rel > 7 ? 7 : rel);
            float t = aux[rel + 7];
            v.x += t; v.y += t; v.z += t; v.w += t;
        }
        if (EPI == 3) {
            float s = aux[gm];
            v.x *= s; v.y *= s; v.z *= s; v.w *= s;
        }
        *(float4*)&C[(long long)gm * ldc + n0 + tx * 4] = v;
    }
}

// ---------------- FAVOR+ feature finalization --------------------------------
// block = one (z, nloc) row, 256 threads (one per feature f)
__device__ __forceinline__ float blockReduce256(float v, float* sred, bool isMax) {
    int f = threadIdx.x;
#pragma unroll
    for (int o = 16; o > 0; o >>= 1) {
        float t = __shfl_xor_sync(0xffffffff, v, o);
        v = isMax ? fmaxf(v, t) : (v + t);
    }
    if ((f & 31) == 0) sred[f >> 5] = v;
    __syncthreads();
    if (f < 32) {
        float t = (f < 8) ? sred[f] : (isMax ? -INFINITY : 0.f);
#pragma unroll
        for (int o = 4; o > 0; o >>= 1) {
            float u = __shfl_xor_sync(0xffffffff, t, o);
            t = isMax ? fmaxf(t, u) : (t + u);
        }
        if (f == 0) sred[0] = t;
    }
    __syncthreads();
    float r = sred[0];
    __syncthreads();
    return r;
}

__global__ __launch_bounds__(256) void finalize_q() {
    __shared__ float sred[8];
    long long row = blockIdx.x;                 // z*NSEQ + nloc
    int z = (int)(row >> 14), nloc = (int)(row & (NSEQ - 1));
    int b = z >> 3, hd = z & 7;
    int f = threadIdx.x;
    float d = g_QP[row * NF + f];
    const float* qrow = g_Q + ((long long)b * NSEQ + nloc) * INNERD + hd * DHEAD;
    float qv = 0.f;
    if (f < DHEAD) { float x = qrow[f]; qv = x * x; }
    float s = blockReduce256(qv, sred, false);
    float diag = 0.0625f * s;                   // 0.5 * dn^2, dn^2 = 1/8
    float m = blockReduce256(d, sred, true);
    g_QP[row * NF + f] = 0.0625f * (__expf(d - diag - m) + 1e-4f);  // ratio=1/16
}

__global__ __launch_bounds__(256) void finalize_k_a() {
    __shared__ float sred[8];
    long long row = blockIdx.x;
    int z = (int)(row >> 14), nloc = (int)(row & (NSEQ - 1));
    int b = z >> 3, hd = z & 7;
    int f = threadIdx.x;
    float d = g_KP[row * NF + f];
    const float* krow = g_K + ((long long)b * NSEQ + nloc) * INNERD + hd * DHEAD;
    float kv = 0.f;
    if (f < DHEAD) { float x = krow[f]; kv = x * x; }
    float s = blockReduce256(kv, sred, false);
    float diag = 0.0625f * s;
    float m = blockReduce256(d, sred, true);    // max of RAW dd
    if (f == 0) atomicMaxFloat(&g_kmax[z], m);
    g_KP[row * NF + f] = d - diag;
}

__global__ __launch_bounds__(256) void k_exp_sum() {
    int blk = blockIdx.x;                        // z*KCHUNKS + c
    int z = blk >> 4, c = blk & 15;
    int f = threadIdx.x;
    float m = g_kmax[z];
    float s = 0.f;
    const int CH = NSEQ / KCHUNKS;               // 1024
    long long base = ((long long)z * NSEQ + (long long)c * CH) * NF + f;
    for (int n = 0; n < CH; n++) {
        long long idx = base + (long long)n * NF;
        float t = g_KP[idx];
        float v = 0.0625f * (__expf(t - m) + 1e-4f);
        g_KP[idx] = v;
        s += v;
    }
    g_ksumP[(z * KCHUNKS + c) * NF + f] = s;
}

__global__ void ksum_reduce() {
    int z = blockIdx.x, f = threadIdx.x;
    float s = 0.f;
#pragma unroll
    for (int c = 0; c < KCHUNKS; c++) s += g_ksumP[(z * KCHUNKS + c) * NF + f];
    g_ksum[z * NF + f] = s;
}

// ---------------- context: C[f,d] = sum_n kp[n,f] * v[n,d] per z --------------
__global__ __launch_bounds__(256) void ctx_gemm() {
    int z = blockIdx.z;
    int f0 = blockIdx.y * 64;
    const float* A = g_KP + (long long)z * NSEQ * NF;
    const float* Bp = g_V + ((long long)(z >> 3) * NSEQ) * INNERD + (z & 7) * DHEAD;
    float* C = g_ctx + z * NF * DHEAD;

    __shared__ float As[32][64];
    __shared__ float Bs[32][64];
    int tid = threadIdx.x, tx = tid & 15, ty = tid >> 4;
    float acc[4][4];
#pragma unroll
    for (int i = 0; i < 4; i++)
#pragma unroll
        for (int j = 0; j < 4; j++) acc[i][j] = 0.f;

    for (int n0 = 0; n0 < NSEQ; n0 += 32) {
#pragma unroll
        for (int i = 0; i < 2; i++) {
            int idx = tid + i * 256;
            int n = idx >> 4, q = idx & 15;
            *(float4*)&As[n][q * 4] = *(const float4*)&A[(long long)(n0 + n) * NF + f0 + q * 4];
            *(float4*)&Bs[n][q * 4] = *(const float4*)&Bp[(long long)(n0 + n) * INNERD + q * 4];
        }
        __syncthreads();
#pragma unroll
        for (int n = 0; n < 32; n++) {
            float4 a = *(const float4*)&As[n][ty * 4];
            float4 b = *(const float4*)&Bs[n][tx * 4];
            float av[4] = {a.x, a.y, a.z, a.w};
            float bv[4] = {b.x, b.y, b.z, b.w};
#pragma unroll
            for (int i = 0; i < 4; i++)
#pragma unroll
                for (int j = 0; j < 4; j++) acc[i][j] += av[i] * bv[j];
        }
        __syncthreads();
    }
#pragma unroll
    for (int i = 0; i < 4; i++) {
        float4 v = make_float4(acc[i][0], acc[i][1], acc[i][2], acc[i][3]);
        *(float4*)&C[(f0 + ty * 4 + i) * DHEAD + tx * 4] = v;
    }
}

// ---------------- d_inv = 1 / (qp_row . ksum_z) -------------------------------
__global__ __launch_bounds__(256) void dinv_kernel() {
    int wid = threadIdx.x >> 5, lane = threadIdx.x & 31;
    long long row = (long long)blockIdx.x * 8 + wid;   // z*NSEQ + nloc
    int z = (int)(row >> 14);
    const float* qp = g_QP + row * NF;
    const float* ks = g_ksum + z * NF;
    float s = 0.f;
#pragma unroll
    for (int j = 0; j < 8; j++) {
        int f = lane + 32 * j;
        s += qp[f] * ks[f];
    }
#pragma unroll
    for (int o = 16; o > 0; o >>= 1) s += __shfl_xor_sync(0xffffffff, s, o);
    if (lane == 0) g_dinv[row] = 1.0f / s;
}

// ---------------- launcher ----------------------------------------------------
extern "C" void kernel_launch(void* const* d_in, const int* in_sizes, int n_in,
                              void* d_out, int out_size) {
    const float* x     = (const float*)d_in[0];
    const float* Wq    = (const float*)d_in[1];
    const float* Wk    = (const float*)d_in[2];
    const float* Wv    = (const float*)d_in[3];
    const float* Wo    = (const float*)d_in[4];
    const float* bo    = (const float*)d_in[5];
    const float* proj  = (const float*)d_in[6];
    const float* Wp    = (const float*)d_in[7];
    const float* bp    = (const float*)d_in[8];
    const float* btab  = (const float*)d_in[9];
    float* out = (float*)d_out;

    float *pQ, *pK, *pV, *pQP, *pKP, *pATT, *pY1, *pPT, *pCTX, *pDINV;
    cudaGetSymbolAddress((void**)&pQ,   g_Q);
    cudaGetSymbolAddress((void**)&pK,   g_K);
    cudaGetSymbolAddress((void**)&pV,   g_V);
    cudaGetSymbolAddress((void**)&pQP,  g_QP);
    cudaGetSymbolAddress((void**)&pKP,  g_KP);
    cudaGetSymbolAddress((void**)&pATT, g_ATT);
    cudaGetSymbolAddress((void**)&pY1,  g_Y1);
    cudaGetSymbolAddress((void**)&pPT,  g_projT);
    cudaGetSymbolAddress((void**)&pCTX, g_ctx);
    cudaGetSymbolAddress((void**)&pDINV, g_dinv);

    const float DN = 0.35355339059327373f;   // 64^-0.25

    init_kernel<<<1, 32>>>();
    transpose_proj<<<64, 256>>>(proj);

    // QKV projections: [65536,256]@[256,512]
    dim3 gqkv(INNERD / 64, TOK / 128, 1);
    sgemm<0><<<gqkv, 256>>>(x, Wq, pQ, TOK, INNERD, CDIM, CDIM, INNERD, INNERD,
                            1, 0, 0, 0, 0, 0, 0, 1.f, nullptr, nullptr, 0, 0);
    sgemm<0><<<gqkv, 256>>>(x, Wk, pK, TOK, INNERD, CDIM, CDIM, INNERD, INNERD,
                            1, 0, 0, 0, 0, 0, 0, 1.f, nullptr, nullptr, 0, 0);
    sgemm<0><<<gqkv, 256>>>(x, Wv, pV, TOK, INNERD, CDIM, CDIM, INNERD, INNERD,
                            1, 0, 0, 0, 0, 0, 0, 1.f, nullptr, nullptr, 0, 0);

    // dd = dn * Qh @ projT, per z = b*8+hd (batched, 32)
    dim3 gdd(NF / 64, NSEQ / 128, NZ);
    sgemm<0><<<gdd, 256>>>(pQ, pPT, pQP, NSEQ, NF, DHEAD, INNERD, NF, NF,
                           8,
                           (long long)NSEQ * INNERD, DHEAD,          // A: b, hd
                           0, 0,                                      // B shared
                           8LL * NSEQ * NF, (long long)NSEQ * NF,     // C
                           DN, nullptr, nullptr, 0, 0);
    sgemm<0><<<gdd, 256>>>(pK, pPT, pKP, NSEQ, NF, DHEAD, INNERD, NF, NF,
                           8,
                           (long long)NSEQ * INNERD, DHEAD,
                           0, 0,
                           8LL * NSEQ * NF, (long long)NSEQ * NF,
                           DN, nullptr, nullptr, 0, 0);

    finalize_q<<<NZ * NSEQ, 256>>>();
    finalize_k_a<<<NZ * NSEQ, 256>>>();
    k_exp_sum<<<NZ * KCHUNKS, 256>>>();
    ksum_reduce<<<NZ, 256>>>();

    ctx_gemm<<<dim3(1, NF / 64, NZ), 256>>>();
    dinv_kernel<<<NZ * NSEQ / 8, 256>>>();

    // attn = (qp @ ctx) * dinv, scattered into [tok, 512] head slices
    dim3 gattn(1, NSEQ / 128, NZ);
    sgemm<3><<<gattn, 256>>>(pQP, pCTX, pATT, NSEQ, DHEAD, NF, NF, DHEAD, INNERD,
                             8,
                             8LL * NSEQ * NF, (long long)NSEQ * NF,   // A
                             8LL * NF * DHEAD, (long long)NF * DHEAD, // B
                             (long long)NSEQ * INNERD, DHEAD,          // C
                             1.f, nullptr, pDINV, 8LL * NSEQ, NSEQ);

    // y1 = attn @ Wo + bo + relbias
    dim3 gwo(CDIM / 64, TOK / 128, 1);
    sgemm<2><<<gwo, 256>>>(pATT, Wo, pY1, TOK, CDIM, INNERD, INNERD, CDIM, CDIM,
                           1, 0, 0, 0, 0, 0, 0, 1.f, bo, btab, 0, 0);

    // out = y1 @ Wp + bp
    sgemm<1><<<gwo, 256>>>(pY1, Wp, out, TOK, CDIM, CDIM, CDIM, CDIM, CDIM,
                           1, 0, 0, 0, 0, 0, 0, 1.f, bp, nullptr, 0, 0);

    (void)in_sizes; (void)n_in; (void)out_size;
}

// round 2
// speedup vs baseline: 1.4322x; 1.4322x over previous
#include <cuda_runtime.h>
#include <math.h>

#define TOK    65536
#define NSEQ   16384
#define CDIM   256
#define INNERD 512
#define NHEAD  8
#define DHEAD  64
#define NF     256
#define NZ     32
#define NCHUNK 16
#define CHROWS (NSEQ / NCHUNK)   // 1024

// ---------------- scratch (static device globals) ----------------------------
__device__ float g_Q[(long long)TOK * INNERD];
__device__ float g_K[(long long)TOK * INNERD];
__device__ float g_V[(long long)TOK * INNERD];
__device__ float g_KP[(long long)NZ * NSEQ * NF];
__device__ float g_ATT[(long long)TOK * INNERD];
__device__ float g_projT[DHEAD * NF];
__device__ float g_kmax[NZ];
__device__ float g_ctxP[(long long)NZ * NCHUNK * NF * DHEAD];
__device__ float g_ctx[NZ * NF * DHEAD];
__device__ float g_ksumP[NZ * NCHUNK * NF];
__device__ float g_ksum[NZ * NF];
__device__ float g_WoWp[INNERD * CDIM];
__device__ float g_bias2[CDIM];
__device__ float g_colsum[CDIM];

__device__ __forceinline__ void atomicMaxFloat(float* addr, float val) {
    if (val >= 0.f) atomicMax((int*)addr, __float_as_int(val));
    else            atomicMin((unsigned int*)addr, (unsigned int)__float_as_int(val));
}

__global__ void init_kernel() {
    int t = threadIdx.x;
    if (t < NZ) g_kmax[t] = __int_as_float(0xff800000);
}

__global__ void transpose_proj(const float* __restrict__ proj) {
    int t = blockIdx.x * 256 + threadIdx.x;
    int d = t >> 8, f = t & 255;
    g_projT[d * NF + f] = proj[f * DHEAD + d];
}

// bias2[n] = bo@Wp + bp ; colsum[n] = sum_c Wp[c,n]
__global__ void bias2_kernel(const float* __restrict__ bo,
                             const float* __restrict__ Wp,
                             const float* __restrict__ bp) {
    int n = threadIdx.x;
    float s = 0.f, cs = 0.f;
    for (int c = 0; c < CDIM; c++) {
        float w = Wp[c * CDIM + n];
        s += bo[c] * w;
        cs += w;
    }
    g_bias2[n] = s + bp[n];
    g_colsum[n] = cs;
}

// ---------------- 128x128x16 double-buffered SGEMM ---------------------------
// EPI 0: none.  EPI 2: + bias2[n] + relbias(token)*colsum[n]
template <int EPI>
__global__ __launch_bounds__(256, 2) void sgemm128(
    const float* __restrict__ A, const float* __restrict__ B, float* __restrict__ C,
    int lda, int ldb, int ldc, int K,
    const float* __restrict__ bias, const float* __restrict__ btab,
    const float* __restrict__ colsum)
{
    __shared__ float As[2][16][132];
    __shared__ float Bs[2][16][128];
    int tid = threadIdx.x;
    int tx = tid & 15, ty = tid >> 4;
    long long m0 = (long long)blockIdx.y * 128;
    int n0 = blockIdx.x * 128;
    const float* Ab = A + m0 * lda;
    const float* Bb = B + n0;

    // prologue: stage 0
#pragma unroll
    for (int i = 0; i < 2; i++) {
        int idx = tid + i * 256;
        int m = idx >> 2, kq = idx & 3;
        float4 v = *(const float4*)&Ab[(long long)m * lda + kq * 4];
        As[0][kq * 4 + 0][m] = v.x; As[0][kq * 4 + 1][m] = v.y;
        As[0][kq * 4 + 2][m] = v.z; As[0][kq * 4 + 3][m] = v.w;
    }
#pragma unroll
    for (int i = 0; i < 2; i++) {
        int idx = tid + i * 256;
        int k = idx >> 5, nq = idx & 31;
        *(float4*)&Bs[0][k][nq * 4] = *(const float4*)&Bb[(long long)k * ldb + nq * 4];
    }
    __syncthreads();

    float acc[8][8];
#pragma unroll
    for (int i = 0; i < 8; i++)
#pragma unroll
        for (int j = 0; j < 8; j++) acc[i][j] = 0.f;

    int nk = K >> 4;
    int buf = 0;
    for (int it = 0; it < nk; ++it) {
        float4 pa[2], pbv[2];
        bool nxt = (it + 1 < nk);
        if (nxt) {
            int k0 = (it + 1) << 4;
#pragma unroll
            for (int i = 0; i < 2; i++) {
                int idx = tid + i * 256;
                int m = idx >> 2, kq = idx & 3;
                pa[i] = *(const float4*)&Ab[(long long)m * lda + k0 + kq * 4];
            }
#pragma unroll
            for (int i = 0; i < 2; i++) {
                int idx = tid + i * 256;
                int k = idx >> 5, nq = idx & 31;
                pbv[i] = *(const float4*)&Bb[(long long)(k0 + k) * ldb + nq * 4];
            }
        }
#pragma unroll
        for (int k = 0; k < 16; k++) {
            float4 a0 = *(const float4*)&As[buf][k][ty * 4];
            float4 a1 = *(const float4*)&As[buf][k][ty * 4 + 64];
            float4 b0 = *(const float4*)&Bs[buf][k][tx * 4];
            float4 b1 = *(const float4*)&Bs[buf][k][tx * 4 + 64];
            float av[8] = {a0.x, a0.y, a0.z, a0.w, a1.x, a1.y, a1.z, a1.w};
            float bv[8] = {b0.x, b0.y, b0.z, b0.w, b1.x, b1.y, b1.z, b1.w};
#pragma unroll
            for (int i = 0; i < 8; i++)
#pragma unroll
                for (int j = 0; j < 8; j++) acc[i][j] += av[i] * bv[j];
        }
        if (nxt) {
            int nb = buf ^ 1;
#pragma unroll
            for (int i = 0; i < 2; i++) {
                int idx = tid + i * 256;
                int m = idx >> 2, kq = idx & 3;
                As[nb][kq * 4 + 0][m] = pa[i].x; As[nb][kq * 4 + 1][m] = pa[i].y;
                As[nb][kq * 4 + 2][m] = pa[i].z; As[nb][kq * 4 + 3][m] = pa[i].w;
            }
#pragma unroll
            for (int i = 0; i < 2; i++) {
                int idx = tid + i * 256;
                int k = idx >> 5, nq = idx & 31;
                *(float4*)&Bs[nb][k][nq * 4] = pbv[i];
            }
            __syncthreads();
            buf = nb;
        }
    }

    float cb[8], csm[8];
    if (EPI == 2) {
#pragma unroll
        for (int j = 0; j < 8; j++) {
            int n = n0 + (j < 4 ? tx * 4 + j : 64 + tx * 4 + j - 4);
            cb[j] = bias[n];
            csm[j] = colsum[n];
        }
    }
#pragma unroll
    for (int i = 0; i < 8; i++) {
        long long gm = m0 + (i < 4 ? ty * 4 + i : 64 + ty * 4 + (i - 4));
        float t = 0.f;
        if (EPI == 2) {
            int hh = ((int)gm >> 7) & 127, ww = (int)gm & 127;
            int rel = hh - ww;
            rel = rel < -7 ? -7 : (rel > 7 ? 7 : rel);
            t = btab[rel + 7];
        }
        float4 v0, v1;
        if (EPI == 2) {
            v0.x = acc[i][0] + cb[0] + t * csm[0];
            v0.y = acc[i][1] + cb[1] + t * csm[1];
            v0.z = acc[i][2] + cb[2] + t * csm[2];
            v0.w = acc[i][3] + cb[3] + t * csm[3];
            v1.x = acc[i][4] + cb[4] + t * csm[4];
            v1.y = acc[i][5] + cb[5] + t * csm[5];
            v1.z = acc[i][6] + cb[6] + t * csm[6];
            v1.w = acc[i][7] + cb[7] + t * csm[7];
        } else {
            v0 = make_float4(acc[i][0], acc[i][1], acc[i][2], acc[i][3]);
            v1 = make_float4(acc[i][4], acc[i][5], acc[i][6], acc[i][7]);
        }
        *(float4*)&C[gm * ldc + n0 + tx * 4] = v0;
        *(float4*)&C[gm * ldc + n0 + tx * 4 + 64] = v1;
    }
}

// ---------------- K feature pass: dd = dn*k@projT, store dd-diag, atomic max -
__global__ __launch_bounds__(512, 1) void dd_k_kernel() {
    int z = blockIdx.y;
    int b = z >> 3, hd = z & 7;
    long long m0 = (long long)blockIdx.x * 128;
    const float* A = g_K + ((long long)b * NSEQ + m0) * INNERD + hd * DHEAD;

    __shared__ float As[64][132];
    __shared__ float Bs[16][256];
    __shared__ float red[128 * 4];
    __shared__ float rss[128];
    __shared__ float redm[16];

    int tid = threadIdx.x;
    int tx = tid & 31, ty = tid >> 5;

    // load K head tile [128 rows x 64 d] -> As[k][m]
#pragma unroll
    for (int i = 0; i < 4; i++) {
        int idx = tid + i * 512;
        int m = idx >> 4, kq = idx & 15;
        float4 v = *(const float4*)&A[(long long)m * INNERD + kq * 4];
        As[kq * 4 + 0][m] = v.x; As[kq * 4 + 1][m] = v.y;
        As[kq * 4 + 2][m] = v.z; As[kq * 4 + 3][m] = v.w;
    }
    __syncthreads();

    // row sum-of-squares
    {
        int r = tid >> 2, p = tid & 3;
        float s = 0.f;
        for (int k = p * 16; k < p * 16 + 16; k++) { float x = As[k][r]; s += x * x; }
        red[r * 4 + p] = s;
    }
    __syncthreads();
    if (tid < 128) rss[tid] = 0.0625f * (red[tid * 4] + red[tid * 4 + 1] + red[tid * 4 + 2] + red[tid * 4 + 3]);

    float acc[8][8];
#pragma unroll
    for (int i = 0; i < 8; i++)
#pragma unroll
        for (int j = 0; j < 8; j++) acc[i][j] = 0.f;

    for (int k0 = 0; k0 < 64; k0 += 16) {
        __syncthreads();
#pragma unroll
        for (int i = 0; i < 2; i++) {
            int idx = tid + i * 512;
            int k = idx >> 6, nq = idx & 63;
            *(float4*)&Bs[k][nq * 4] = *(const float4*)&g_projT[(k0 + k) * NF + nq * 4];
        }
        __syncthreads();
#pragma unroll
        for (int k = 0; k < 16; k++) {
            float4 a0 = *(const float4*)&As[k0 + k][ty * 8];
            float4 a1 = *(const float4*)&As[k0 + k][ty * 8 + 4];
            float4 b0 = *(const float4*)&Bs[k][tx * 8];
            float4 b1 = *(const float4*)&Bs[k][tx * 8 + 4];
            float av[8] = {a0.x, a0.y, a0.z, a0.w, a1.x, a1.y, a1.z, a1.w};
            float bv[8] = {b0.x, b0.y, b0.z, b0.w, b1.x, b1.y, b1.z, b1.w};
#pragma unroll
            for (int i = 0; i < 8; i++)
#pragma unroll
                for (int j = 0; j < 8; j++) acc[i][j] += av[i] * bv[j];
        }
    }

    const float DN = 0.35355339059327373f;
    float* KPp = g_KP + ((long long)z * NSEQ + m0) * NF;
    float mx = __int_as_float(0xff800000);
#pragma unroll
    for (int i = 0; i < 8; i++) {
        int m = ty * 8 + i;
        float d = rss[m];
        float4 v0, v1;
        float dd;
        dd = acc[i][0] * DN; mx = fmaxf(mx, dd); v0.x = dd - d;
        dd = acc[i][1] * DN; mx = fmaxf(mx, dd); v0.y = dd - d;
        dd = acc[i][2] * DN; mx = fmaxf(mx, dd); v0.z = dd - d;
        dd = acc[i][3] * DN; mx = fmaxf(mx, dd); v0.w = dd - d;
        dd = acc[i][4] * DN; mx = fmaxf(mx, dd); v1.x = dd - d;
        dd = acc[i][5] * DN; mx = fmaxf(mx, dd); v1.y = dd - d;
        dd = acc[i][6] * DN; mx = fmaxf(mx, dd); v1.z = dd - d;
        dd = acc[i][7] * DN; mx = fmaxf(mx, dd); v1.w = dd - d;
        *(float4*)&KPp[(long long)m * NF + tx * 8] = v0;
        *(float4*)&KPp[(long long)m * NF + tx * 8 + 4] = v1;
    }
#pragma unroll
    for (int o = 16; o > 0; o >>= 1) mx = fmaxf(mx, __shfl_xor_sync(0xffffffff, mx, o));
    if ((tid & 31) == 0) redm[tid >> 5] = mx;
    __syncthreads();
    if (tid == 0) {
        float m2 = redm[0];
#pragma unroll
        for (int i = 1; i < 16; i++) m2 = fmaxf(m2, redm[i]);
        atomicMaxFloat(&g_kmax[z], m2);
    }
}

// ---------------- ctx partials: exp on load + ksum accumulation --------------
__global__ __launch_bounds__(256, 2) void ctx_part_kernel() {
    int z = blockIdx.y, ch = blockIdx.x;
    int b = z >> 3, hd = z & 7;
    const float* KPp = g_KP + ((long long)z * NSEQ + (long long)ch * CHROWS) * NF;
    const float* Vp  = g_V + ((long long)b * NSEQ + (long long)ch * CHROWS) * INNERD + hd * DHEAD;
    float km = g_kmax[z];

    __shared__ float Ks[16][260];
    __shared__ float Vs[16][68];

    int tid = threadIdx.x;
    int tx = tid & 7, ty = tid >> 3;   // tx: d(8 each), ty: f(8 each)

    float acc[8][8];
#pragma unroll
    for (int i = 0; i < 8; i++)
#pragma unroll
        for (int j = 0; j < 8; j++) acc[i][j] = 0.f;
    float ks_acc = 0.f;

    for (int r0 = 0; r0 < CHROWS; r0 += 16) {
        __syncthreads();
        // load kp tile with exp applied
#pragma unroll
        for (int i = 0; i < 4; i++) {
            int idx = tid + i * 256;           // float4 index over 16x256
            int r = idx >> 6, cq = idx & 63;
            float4 v = *(const float4*)&KPp[((long long)(r0 + r)) * NF + cq * 4];
            v.x = 0.0625f * (__expf(v.x - km) + 1e-4f);
            v.y = 0.0625f * (__expf(v.y - km) + 1e-4f);
            v.z = 0.0625f * (__expf(v.z - km) + 1e-4f);
            v.w = 0.0625f * (__expf(v.w - km) + 1e-4f);
            *(float4*)&Ks[r][cq * 4] = v;
        }
        {
            int r = tid >> 4, nq = tid & 15;
            *(float4*)&Vs[r][nq * 4] = *(const float4*)&Vp[((long long)(r0 + r)) * INNERD + nq * 4];
        }
        __syncthreads();
        // ksum partial for feature f = tid
#pragma unroll
        for (int r = 0; r < 16; r++) ks_acc += Ks[r][tid];
        // gemm: ctx[f][d] += kp[r][f]*v[r][d]
#pragma unroll
        for (int r = 0; r < 16; r++) {
            float4 a0 = *(const float4*)&Ks[r][ty * 8];
            float4 a1 = *(const float4*)&Ks[r][ty * 8 + 4];
            float4 b0 = *(const float4*)&Vs[r][tx * 8];
            float4 b1 = *(const float4*)&Vs[r][tx * 8 + 4];
            float av[8] = {a0.x, a0.y, a0.z, a0.w, a1.x, a1.y, a1.z, a1.w};
            float bv[8] = {b0.x, b0.y, b0.z, b0.w, b1.x, b1.y, b1.z, b1.w};
#pragma unroll
            for (int i = 0; i < 8; i++)
#pragma unroll
                for (int j = 0; j < 8; j++) acc[i][j] += av[i] * bv[j];
        }
    }

    long long base = ((long long)(z * NCHUNK + ch)) * (NF * DHEAD);
#pragma unroll
    for (int i = 0; i < 8; i++) {
        int f = ty * 8 + i;
        *(float4*)&g_ctxP[base + (long long)f * DHEAD + tx * 8] =
            make_float4(acc[i][0], acc[i][1], acc[i][2], acc[i][3]);
        *(float4*)&g_ctxP[base + (long long)f * DHEAD + tx * 8 + 4] =
            make_float4(acc[i][4], acc[i][5], acc[i][6], acc[i][7]);
    }
    g_ksumP[(z * NCHUNK + ch) * NF + tid] = ks_acc;
}

__global__ void ctx_reduce() {
    int idx = blockIdx.x * 256 + threadIdx.x;   // over NZ*NF*DHEAD
    int z = idx >> 14, fd = idx & 16383;
    float s = 0.f;
#pragma unroll
    for (int c = 0; c < NCHUNK; c++)
        s += g_ctxP[((long long)(z * NCHUNK + c)) * 16384 + fd];
    g_ctx[(long long)z * 16384 + fd] = s;
}

__global__ void ksum_reduce() {
    int z = blockIdx.x, f = threadIdx.x;
    float s = 0.f;
#pragma unroll
    for (int c = 0; c < NCHUNK; c++) s += g_ksumP[(z * NCHUNK + c) * NF + f];
    g_ksum[z * NF + f] = s;
}

// ---------------- fused Q feature + attention kernel --------------------------
// per (z, 128-row tile): dd = dn*q@projT -> rowmax/diag/exp -> qp (smem)
// -> dinv = 1/(qp.ksum) -> out = (qp@ctx)*dinv
#define QPP 260
__global__ __launch_bounds__(512, 1) void fused_attn_kernel(const float* __restrict__ btab_unused) {
    extern __shared__ float smem[];
    float* qp     = smem;                    // 128*260
    float* qs     = qp + 128 * QPP;          // 64*132
    float* pb     = qs + 64 * 132;           // 16*256
    float* cs     = pb + 16 * 256;           // 16*68
    float* ks     = cs + 16 * 68;            // 256
    float* rowsub = ks + 256;                // 128
    float* sdinv  = rowsub + 128;            // 128
    float* red    = sdinv + 128;             // 512

    int z = blockIdx.y;
    int b = z >> 3, hd = z & 7;
    long long m0 = (long long)blockIdx.x * 128;
    const float* Aq = g_Q + ((long long)b * NSEQ + m0) * INNERD + hd * DHEAD;

    int tid = threadIdx.x;

    // load q tile -> qs[k][m] (pitch 132), and ksum
#pragma unroll
    for (int i = 0; i < 4; i++) {
        int idx = tid + i * 512;
        int m = idx >> 4, kq = idx & 15;
        float4 v = *(const float4*)&Aq[(long long)m * INNERD + kq * 4];
        qs[(kq * 4 + 0) * 132 + m] = v.x; qs[(kq * 4 + 1) * 132 + m] = v.y;
        qs[(kq * 4 + 2) * 132 + m] = v.z; qs[(kq * 4 + 3) * 132 + m] = v.w;
    }
    if (tid < 256) ks[tid] = g_ksum[z * NF + tid];
    __syncthreads();

    // diag
    {
        int r = tid >> 2, p = tid & 3;
        float s = 0.f;
        for (int k = p * 16; k < p * 16 + 16; k++) { float x = qs[k * 132 + r]; s += x * x; }
        red[r * 4 + p] = s;
    }
    __syncthreads();
    if (tid < 128) rowsub[tid] = 0.0625f * (red[tid * 4] + red[tid * 4 + 1] + red[tid * 4 + 2] + red[tid * 4 + 3]);

    // dd gemm: [128m x 256f], K=64
    int tx = tid & 31, ty = tid >> 5;
    {
        float acc[8][8];
#pragma unroll
        for (int i = 0; i < 8; i++)
#pragma unroll
            for (int j = 0; j < 8; j++) acc[i][j] = 0.f;
        for (int k0 = 0; k0 < 64; k0 += 16) {
            __syncthreads();
#pragma unroll
            for (int i = 0; i < 2; i++) {
                int idx = tid + i * 512;
                int k = idx >> 6, nq = idx & 63;
                *(float4*)&pb[k * 256 + nq * 4] = *(const float4*)&g_projT[(k0 + k) * NF + nq * 4];
            }
            __syncthreads();
#pragma unroll
            for (int k = 0; k < 16; k++) {
                float4 a0 = *(const float4*)&qs[(k0 + k) * 132 + ty * 8];
                float4 a1 = *(const float4*)&qs[(k0 + k) * 132 + ty * 8 + 4];
                float4 b0 = *(const float4*)&pb[k * 256 + tx * 8];
                float4 b1 = *(const float4*)&pb[k * 256 + tx * 8 + 4];
                float av[8] = {a0.x, a0.y, a0.z, a0.w, a1.x, a1.y, a1.z, a1.w};
                float bv[8] = {b0.x, b0.y, b0.z, b0.w, b1.x, b1.y, b1.z, b1.w};
#pragma unroll
                for (int i = 0; i < 8; i++)
#pragma unroll
                    for (int j = 0; j < 8; j++) acc[i][j] += av[i] * bv[j];
            }
        }
        const float DN = 0.35355339059327373f;
        __syncthreads();
#pragma unroll
        for (int i = 0; i < 8; i++) {
            int m = ty * 8 + i;
            *(float4*)&qp[m * QPP + tx * 8] =
                make_float4(acc[i][0] * DN, acc[i][1] * DN, acc[i][2] * DN, acc[i][3] * DN);
            *(float4*)&qp[m * QPP + tx * 8 + 4] =
                make_float4(acc[i][4] * DN, acc[i][5] * DN, acc[i][6] * DN, acc[i][7] * DN);
        }
    }
    __syncthreads();

    // row max (over raw dd)
    {
        int r = tid >> 2, p = tid & 3;
        float mx = __int_as_float(0xff800000);
        for (int f = p * 64; f < p * 64 + 64; f++) mx = fmaxf(mx, qp[r * QPP + f]);
        red[r * 4 + p] = mx;
    }
    __syncthreads();
    if (tid < 128) {
        float m = fmaxf(fmaxf(red[tid * 4], red[tid * 4 + 1]), fmaxf(red[tid * 4 + 2], red[tid * 4 + 3]));
        rowsub[tid] += m;   // diag + max
    }
    __syncthreads();

    // transform: qp = ratio*(exp(dd - diag - max)+eps)
#pragma unroll
    for (int i = 0; i < 64; i++) {
        int idx = i * 512 + tid;
        int r = idx >> 8, f = idx & 255;
        float v = qp[r * QPP + f];
        qp[r * QPP + f] = 0.0625f * (__expf(v - rowsub[r]) + 1e-4f);
    }
    __syncthreads();

    // dinv
    {
        int r = tid >> 2, p = tid & 3;
        float s = 0.f;
        for (int f = p * 64; f < p * 64 + 64; f++) s += qp[r * QPP + f] * ks[f];
        red[r * 4 + p] = s;
    }
    __syncthreads();
    if (tid < 128)
        sdinv[tid] = 1.0f / (red[tid * 4] + red[tid * 4 + 1] + red[tid * 4 + 2] + red[tid * 4 + 3]);

    // phase2: out[128m x 64d] = qp @ ctx
    int tx2 = tid & 15, ty2 = tid >> 4;  // d: 4 each, m: 4 each
    float acc2[4][4];
#pragma unroll
    for (int i = 0; i < 4; i++)
#pragma unroll
        for (int j = 0; j < 4; j++) acc2[i][j] = 0.f;

    const float* ctxp = g_ctx + (long long)z * NF * DHEAD;
    for (int f0 = 0; f0 < NF; f0 += 16) {
        __syncthreads();
        if (tid < 256) {
            int k = tid >> 4, nq = tid & 15;
            *(float4*)&cs[k * 68 + nq * 4] = *(const float4*)&ctxp[(long long)(f0 + k) * DHEAD + nq * 4];
        }
        __syncthreads();
#pragma unroll
        for (int k = 0; k < 16; k++) {
            float a0 = qp[(ty2 * 4 + 0) * QPP + f0 + k];
            float a1 = qp[(ty2 * 4 + 1) * QPP + f0 + k];
            float a2 = qp[(ty2 * 4 + 2) * QPP + f0 + k];
            float a3 = qp[(ty2 * 4 + 3) * QPP + f0 + k];
            float4 b4 = *(const float4*)&cs[k * 68 + tx2 * 4];
            float bv[4] = {b4.x, b4.y, b4.z, b4.w};
            float av[4] = {a0, a1, a2, a3};
#pragma unroll
            for (int i = 0; i < 4; i++)
#pragma unroll
                for (int j = 0; j < 4; j++) acc2[i][j] += av[i] * bv[j];
        }
    }

    float* Cp = g_ATT + ((long long)b * NSEQ + m0) * INNERD + hd * DHEAD;
#pragma unroll
    for (int i = 0; i < 4; i++) {
        int m = ty2 * 4 + i;
        float s = sdinv[m];
        *(float4*)&Cp[(long long)m * INNERD + tx2 * 4] =
            make_float4(acc2[i][0] * s, acc2[i][1] * s, acc2[i][2] * s, acc2[i][3] * s);
    }
    (void)btab_unused;
}

#define SMEM_ATTN ((128 * QPP + 64 * 132 + 16 * 256 + 16 * 68 + 256 + 128 + 128 + 512) * 4)

// ---------------- launcher ----------------------------------------------------
extern "C" void kernel_launch(void* const* d_in, const int* in_sizes, int n_in,
                              void* d_out, int out_size) {
    const float* x    = (const float*)d_in[0];
    const float* Wq   = (const float*)d_in[1];
    const float* Wk   = (const float*)d_in[2];
    const float* Wv   = (const float*)d_in[3];
    const float* Wo   = (const float*)d_in[4];
    const float* bo   = (const float*)d_in[5];
    const float* proj = (const float*)d_in[6];
    const float* Wp   = (const float*)d_in[7];
    const float* bp   = (const float*)d_in[8];
    const float* btab = (const float*)d_in[9];
    float* out = (float*)d_out;

    static bool attr_set = false;
    if (!attr_set) {
        cudaFuncSetAttribute(fused_attn_kernel, cudaFuncAttributeMaxDynamicSharedMemorySize, SMEM_ATTN);
        attr_set = true;
    }

    float *pQ, *pK, *pV, *pATT, *pWoWp, *pB2, *pCS;
    cudaGetSymbolAddress((void**)&pQ,    g_Q);
    cudaGetSymbolAddress((void**)&pK,    g_K);
    cudaGetSymbolAddress((void**)&pV,    g_V);
    cudaGetSymbolAddress((void**)&pATT,  g_ATT);
    cudaGetSymbolAddress((void**)&pWoWp, g_WoWp);
    cudaGetSymbolAddress((void**)&pB2,   g_bias2);
    cudaGetSymbolAddress((void**)&pCS,   g_colsum);

    init_kernel<<<1, 32>>>();
    transpose_proj<<<64, 256>>>(proj);
    bias2_kernel<<<1, 256>>>(bo, Wp, bp);

    // WoWp = Wo @ Wp  [512,256] x [256,256]
    sgemm128<0><<<dim3(CDIM / 128, INNERD / 128), 256>>>(
        Wo, Wp, pWoWp, CDIM, CDIM, CDIM, CDIM, nullptr, nullptr, nullptr);

    // QKV projections
    dim3 gqkv(INNERD / 128, TOK / 128);
    sgemm128<0><<<gqkv, 256>>>(x, Wq, pQ, CDIM, INNERD, INNERD, CDIM, nullptr, nullptr, nullptr);
    sgemm128<0><<<gqkv, 256>>>(x, Wk, pK, CDIM, INNERD, INNERD, CDIM, nullptr, nullptr, nullptr);
    sgemm128<0><<<gqkv, 256>>>(x, Wv, pV, CDIM, INNERD, INNERD, CDIM, nullptr, nullptr, nullptr);

    // K feature pass (dd - diag, global max per z)
    dd_k_kernel<<<dim3(NSEQ / 128, NZ), 512>>>();

    // context partials + ksum, then reduce
    ctx_part_kernel<<<dim3(NCHUNK, NZ), 256>>>();
    ctx_reduce<<<(NZ * NF * DHEAD) / 256, 256>>>();
    ksum_reduce<<<NZ, 256>>>();

    // fused q features + attention
    fused_attn_kernel<<<dim3(NSEQ / 128, NZ), 512, SMEM_ATTN>>>(btab);

    // out = ATT @ WoWp + bias2 + rel*colsum
    sgemm128<2><<<dim3(CDIM / 128, TOK / 128), 256>>>(
        pATT, pWoWp, out, INNERD, CDIM, CDIM, INNERD, pB2, btab, pCS);

    (void)in_sizes; (void)n_in; (void)out_size;
}

// round 7
// speedup vs baseline: 1.8187x; 1.2699x over previous
#include <cuda_runtime.h>
#include <cuda_bf16.h>
#include <math.h>
#include <stdint.h>

#define TOK    65536
#define NSEQ   16384
#define CDIM   256
#define INNERD 512
#define QKVLD  1536
#define NHEAD  8
#define DHEAD  64
#define NF     256
#define NZ     32
#define NCHUNK 16
#define CHROWS (NSEQ / NCHUNK)   // 1024

// ---------------- scratch (static device globals) ----------------------------
__device__ float g_QKV[(long long)TOK * QKVLD];          // Q|K|V fp32
__device__ float g_KP[(long long)NZ * NSEQ * NF];
__device__ __nv_bfloat16 g_Xh[(long long)TOK * CDIM];
__device__ __nv_bfloat16 g_Xl[(long long)TOK * CDIM];
__device__ __nv_bfloat16 g_Wch[CDIM * QKVLD];
__device__ __nv_bfloat16 g_Wcl[CDIM * QKVLD];
__device__ __nv_bfloat16 g_ATTh[(long long)TOK * INNERD];
__device__ __nv_bfloat16 g_ATTl[(long long)TOK * INNERD];
__device__ __nv_bfloat16 g_WoWph[INNERD * CDIM];
__device__ __nv_bfloat16 g_WoWpl[INNERD * CDIM];
__device__ float g_projT[DHEAD * NF];
__device__ float g_kmax[NZ];
__device__ float g_ctxP[(long long)NZ * NCHUNK * NF * DHEAD];
__device__ float g_ctx[NZ * NF * DHEAD];
__device__ float g_ksumP[NZ * NCHUNK * NF];
__device__ float g_ksum[NZ * NF];
__device__ float g_WoWp[INNERD * CDIM];
__device__ float g_bias2[CDIM];
__device__ float g_colsum[CDIM];

// ---------------- ptx helpers -------------------------------------------------
__device__ __forceinline__ uint32_t smem_u32(const void* p) {
    uint32_t a;
    asm("{ .reg .u64 t; cvta.to.shared.u64 t, %1; cvt.u32.u64 %0, t; }" : "=r"(a) : "l"(p));
    return a;
}
#define CP_ASYNC16(dst, src) \
    asm volatile("cp.async.cg.shared.global [%0], [%1], 16;\n" :: "r"(dst), "l"(src))
#define CP_COMMIT() asm volatile("cp.async.commit_group;\n")
#define CP_WAIT1()  asm volatile("cp.async.wait_group 1;\n")
#define CP_WAIT0()  asm volatile("cp.async.wait_group 0;\n")

__device__ __forceinline__ void ldsm_x4(uint32_t (&r)[4], uint32_t a) {
    asm volatile("ldmatrix.sync.aligned.m8n8.x4.shared.b16 {%0,%1,%2,%3}, [%4];"
                 : "=r"(r[0]), "=r"(r[1]), "=r"(r[2]), "=r"(r[3]) : "r"(a));
}
__device__ __forceinline__ void ldsm_x4_t(uint32_t (&r)[4], uint32_t a) {
    asm volatile("ldmatrix.sync.aligned.m8n8.x4.trans.shared.b16 {%0,%1,%2,%3}, [%4];"
                 : "=r"(r[0]), "=r"(r[1]), "=r"(r[2]), "=r"(r[3]) : "r"(a));
}
__device__ __forceinline__ void mma_bf16(float (&d)[4], const uint32_t (&a)[4],
                                         uint32_t b0, uint32_t b1) {
    asm volatile("mma.sync.aligned.m16n8k16.row.col.f32.bf16.bf16.f32 "
                 "{%0,%1,%2,%3},{%4,%5,%6,%7},{%8,%9},{%0,%1,%2,%3};"
                 : "+f"(d[0]), "+f"(d[1]), "+f"(d[2]), "+f"(d[3])
                 : "r"(a[0]), "r"(a[1]), "r"(a[2]), "r"(a[3]), "r"(b0), "r"(b1));
}

__device__ __forceinline__ void atomicMaxFloat(float* addr, float val) {
    if (val >= 0.f) atomicMax((int*)addr, __float_as_int(val));
    else            atomicMin((unsigned int*)addr, (unsigned int)__float_as_int(val));
}

// ---------------- small prep kernels ------------------------------------------
__global__ void init_kernel() {
    int t = threadIdx.x;
    if (t < NZ) g_kmax[t] = __int_as_float(0xff800000);
}

__global__ void transpose_proj(const float* __restrict__ proj) {
    int t = blockIdx.x * 256 + threadIdx.x;
    int d = t >> 8, f = t & 255;
    g_projT[d * NF + f] = proj[f * DHEAD + d];
}

__global__ void bias2_kernel(const float* __restrict__ bo,
                             const float* __restrict__ Wp,
                             const float* __restrict__ bp) {
    int n = threadIdx.x;
    float s = 0.f, cs = 0.f;
    for (int c = 0; c < CDIM; c++) {
        float w = Wp[c * CDIM + n];
        s += bo[c] * w;
        cs += w;
    }
    g_bias2[n] = s + bp[n];
    g_colsum[n] = cs;
}

__global__ void split_x_kernel(const float* __restrict__ x) {
    long long i = (long long)blockIdx.x * 256 + threadIdx.x;   // over TOK*CDIM/4
    float4 v = *(const float4*)&x[i * 4];
    float vv[4] = {v.x, v.y, v.z, v.w};
#pragma unroll
    for (int j = 0; j < 4; j++) {
        __nv_bfloat16 h = __float2bfloat16(vv[j]);
        g_Xh[i * 4 + j] = h;
        g_Xl[i * 4 + j] = __float2bfloat16(vv[j] - __bfloat162float(h));
    }
}

__global__ void pack_w_kernel(const float* __restrict__ Wq,
                              const float* __restrict__ Wk,
                              const float* __restrict__ Wv) {
    int i = blockIdx.x * 256 + threadIdx.x;   // over CDIM*QKVLD
    int c = i / QKVLD, n = i % QKVLD;
    float v = (n < 512) ? Wq[c * 512 + n]
            : (n < 1024) ? Wk[c * 512 + n - 512]
                         : Wv[c * 512 + n - 1024];
    __nv_bfloat16 h = __float2bfloat16(v);
    g_Wch[i] = h;
    g_Wcl[i] = __float2bfloat16(v - __bfloat162float(h));
}

__global__ void split_wowp_kernel() {
    int i = blockIdx.x * 256 + threadIdx.x;   // INNERD*CDIM
    float v = g_WoWp[i];
    __nv_bfloat16 h = __float2bfloat16(v);
    g_WoWph[i] = h;
    g_WoWpl[i] = __float2bfloat16(v - __bfloat162float(h));
}

// ---------------- fp32 sgemm128 (small WoWp product only) ---------------------
__global__ __launch_bounds__(256, 2) void sgemm128(
    const float* __restrict__ A, const float* __restrict__ B, float* __restrict__ C,
    int lda, int ldb, int ldc, int K)
{
    __shared__ float As[2][16][132];
    __shared__ float Bs[2][16][128];
    int tid = threadIdx.x;
    int tx = tid & 15, ty = tid >> 4;
    long long m0 = (long long)blockIdx.y * 128;
    int n0 = blockIdx.x * 128;
    const float* Ab = A + m0 * lda;
    const float* Bb = B + n0;

#pragma unroll
    for (int i = 0; i < 2; i++) {
        int idx = tid + i * 256;
        int m = idx >> 2, kq = idx & 3;
        float4 v = *(const float4*)&Ab[(long long)m * lda + kq * 4];
        As[0][kq * 4 + 0][m] = v.x; As[0][kq * 4 + 1][m] = v.y;
        As[0][kq * 4 + 2][m] = v.z; As[0][kq * 4 + 3][m] = v.w;
    }
#pragma unroll
    for (int i = 0; i < 2; i++) {
        int idx = tid + i * 256;
        int k = idx >> 5, nq = idx & 31;
        *(float4*)&Bs[0][k][nq * 4] = *(const float4*)&Bb[(long long)k * ldb + nq * 4];
    }
    __syncthreads();

    float acc[8][8];
#pragma unroll
    for (int i = 0; i < 8; i++)
#pragma unroll
        for (int j = 0; j < 8; j++) acc[i][j] = 0.f;

    int nk = K >> 4, buf = 0;
    for (int it = 0; it < nk; ++it) {
        float4 pa[2], pbv[2];
        bool nxt = (it + 1 < nk);
        if (nxt) {
            int k0 = (it + 1) << 4;
#pragma unroll
            for (int i = 0; i < 2; i++) {
                int idx = tid + i * 256;
                int m = idx >> 2, kq = idx & 3;
                pa[i] = *(const float4*)&Ab[(long long)m * lda + k0 + kq * 4];
            }
#pragma unroll
            for (int i = 0; i < 2; i++) {
                int idx = tid + i * 256;
                int k = idx >> 5, nq = idx & 31;
                pbv[i] = *(const float4*)&Bb[(long long)(k0 + k) * ldb + nq * 4];
            }
        }
#pragma unroll
        for (int k = 0; k < 16; k++) {
            float4 a0 = *(const float4*)&As[buf][k][ty * 4];
            float4 a1 = *(const float4*)&As[buf][k][ty * 4 + 64];
            float4 b0 = *(const float4*)&Bs[buf][k][tx * 4];
            float4 b1 = *(const float4*)&Bs[buf][k][tx * 4 + 64];
            float av[8] = {a0.x, a0.y, a0.z, a0.w, a1.x, a1.y, a1.z, a1.w};
            float bv[8] = {b0.x, b0.y, b0.z, b0.w, b1.x, b1.y, b1.z, b1.w};
#pragma unroll
            for (int i = 0; i < 8; i++)
#pragma unroll
                for (int j = 0; j < 8; j++) acc[i][j] += av[i] * bv[j];
        }
        if (nxt) {
            int nb = buf ^ 1;
#pragma unroll
            for (int i = 0; i < 2; i++) {
                int idx = tid + i * 256;
                int m = idx >> 2, kq = idx & 3;
                As[nb][kq * 4 + 0][m] = pa[i].x; As[nb][kq * 4 + 1][m] = pa[i].y;
                As[nb][kq * 4 + 2][m] = pa[i].z; As[nb][kq * 4 + 3][m] = pa[i].w;
            }
#pragma unroll
            for (int i = 0; i < 2; i++) {
                int idx = tid + i * 256;
                int k = idx >> 5, nq = idx & 31;
                *(float4*)&Bs[nb][k][nq * 4] = pbv[i];
            }
            __syncthreads();
            buf = nb;
        }
    }
#pragma unroll
    for (int i = 0; i < 8; i++) {
        long long gm = m0 + (i < 4 ? ty * 4 + i : 64 + ty * 4 + (i - 4));
        *(float4*)&C[gm * ldc + n0 + tx * 4] =
            make_float4(acc[i][0], acc[i][1], acc[i][2], acc[i][3]);
        *(float4*)&C[gm * ldc + n0 + tx * 4 + 64] =
            make_float4(acc[i][4], acc[i][5], acc[i][6], acc[i][7]);
    }
}

// ---------------- bf16-split tensor-core GEMM ---------------------------------
// C[M,N] = A@B, A=[M,K] row bf16 hi/lo, B=[K,N] row bf16 hi/lo.
// Tiles: 128x128x32, 8 warps (2m x 4n), warp tile 64x32. cp.async 2-stage.
// EPI 0: plain fp32 store. EPI 2: + bias2[n] + relbias(token)*colsum[n]
#define SOFF_AL 10240
#define SOFF_BH 20480
#define SOFF_BL 29184
#define STAGE_B 37888
#define SMEM_MMA (2 * STAGE_B)

template <int EPI>
__global__ __launch_bounds__(256) void mma_gemm(
    const __nv_bfloat16* __restrict__ Ah, const __nv_bfloat16* __restrict__ Al,
    const __nv_bfloat16* __restrict__ Bh, const __nv_bfloat16* __restrict__ Bl,
    float* __restrict__ C, int K, int lda, int ldb, int ldc,
    const float* __restrict__ bias, const float* __restrict__ btab,
    const float* __restrict__ colsum)
{
    extern __shared__ char smem[];
    uint32_t sbase = smem_u32(smem);

    int tid = threadIdx.x;
    int lane = tid & 31, wid = tid >> 5;
    int wm = wid & 1, wn = wid >> 1;
    long long m0 = (long long)blockIdx.y * 128;
    int n0 = blockIdx.x * 128;

    const __nv_bfloat16* Ahb = Ah + m0 * lda;
    const __nv_bfloat16* Alb = Al + m0 * lda;
    const __nv_bfloat16* Bhb = Bh + n0;
    const __nv_bfloat16* Blb = Bl + n0;

    int nk = K >> 5;

    // per-thread load indices
    int ar0 = tid >> 2, ac0 = tid & 3;          // A chunk: tid
    int ar1 = (tid + 256) >> 2, ac1 = tid & 3;  // A chunk: tid+256
    int br0 = tid >> 4, bc0 = tid & 15;
    int br1 = (tid + 256) >> 4, bc1 = tid & 15;

#define LOAD_STAGE(kt, s)                                                          \
    {                                                                              \
        uint32_t sb = sbase + (s) * STAGE_B;                                       \
        long long ka = (long long)(kt) * 32;                                       \
        CP_ASYNC16(sb + ar0 * 80 + ac0 * 16, Ahb + ar0 * lda + ka + ac0 * 8);      \
        CP_ASYNC16(sb + ar1 * 80 + ac1 * 16, Ahb + ar1 * lda + ka + ac1 * 8);      \
        CP_ASYNC16(sb + SOFF_AL + ar0 * 80 + ac0 * 16, Alb + ar0 * lda + ka + ac0 * 8); \
        CP_ASYNC16(sb + SOFF_AL + ar1 * 80 + ac1 * 16, Alb + ar1 * lda + ka + ac1 * 8); \
        CP_ASYNC16(sb + SOFF_BH + br0 * 272 + bc0 * 16, Bhb + (ka + br0) * ldb + bc0 * 8); \
        CP_ASYNC16(sb + SOFF_BH + br1 * 272 + bc1 * 16, Bhb + (ka + br1) * ldb + bc1 * 8); \
        CP_ASYNC16(sb + SOFF_BL + br0 * 272 + bc0 * 16, Blb + (ka + br0) * ldb + bc0 * 8); \
        CP_ASYNC16(sb + SOFF_BL + br1 * 272 + bc1 * 16, Blb + (ka + br1) * ldb + bc1 * 8); \
        CP_COMMIT();                                                               \
    }

    LOAD_STAGE(0, 0);
    LOAD_STAGE(1, 1);

    float acc[4][4][4];
#pragma unroll
    for (int i = 0; i < 4; i++)
#pragma unroll
        for (int j = 0; j < 4; j++)
#pragma unroll
            for (int r = 0; r < 4; r++) acc[i][j][r] = 0.f;

    // lane-derived ldmatrix offsets
    int lrow = (lane & 7) + ((lane >> 3) & 1) * 8;
    int lcol8 = (lane >> 4) * 8;

    for (int it = 0; it < nk; ++it) {
        if (it < nk - 1) { CP_WAIT1(); } else { CP_WAIT0(); }
        __syncthreads();
        uint32_t sb = sbase + (it & 1) * STAGE_B;
        uint32_t aAh = sb, aAl = sb + SOFF_AL, aBh = sb + SOFF_BH, aBl = sb + SOFF_BL;

#pragma unroll
        for (int ks = 0; ks < 2; ks++) {
            uint32_t ah[4][4], al[4][4];
            uint32_t bh[4][2], bl[4][2];
#pragma unroll
            for (int i = 0; i < 4; i++) {
                int r = wm * 64 + i * 16 + lrow;
                uint32_t off = (uint32_t)r * 80 + (ks * 16 + lcol8) * 2;
                ldsm_x4(ah[i], aAh + off);
                ldsm_x4(al[i], aAl + off);
            }
#pragma unroll
            for (int jj = 0; jj < 2; jj++) {
                int kr = ks * 16 + lrow;
                uint32_t off = (uint32_t)kr * 272 + (wn * 32 + jj * 16 + lcol8) * 2;
                uint32_t t[4];
                ldsm_x4_t(t, aBh + off);
                bh[jj * 2][0] = t[0]; bh[jj * 2][1] = t[1];
                bh[jj * 2 + 1][0] = t[2]; bh[jj * 2 + 1][1] = t[3];
                ldsm_x4_t(t, aBl + off);
                bl[jj * 2][0] = t[0]; bl[jj * 2][1] = t[1];
                bl[jj * 2 + 1][0] = t[2]; bl[jj * 2 + 1][1] = t[3];
            }
#pragma unroll
            for (int i = 0; i < 4; i++)
#pragma unroll
                for (int j = 0; j < 4; j++) {
                    mma_bf16(acc[i][j], ah[i], bh[j][0], bh[j][1]);
                    mma_bf16(acc[i][j], ah[i], bl[j][0], bl[j][1]);
                    mma_bf16(acc[i][j], al[i], bh[j][0], bh[j][1]);
                }
        }
        __syncthreads();
        if (it + 2 < nk) LOAD_STAGE(it + 2, it & 1);
    }

    // epilogue
    int g = lane >> 2, c2 = (lane & 3) * 2;
#pragma unroll
    for (int i = 0; i < 4; i++) {
        long long row0 = m0 + wm * 64 + i * 16 + g;
        long long row1 = row0 + 8;
        float t0 = 0.f, t1 = 0.f;
        if (EPI == 2) {
            int hh = ((int)row0 >> 7) & 127, ww = (int)row0 & 127;
            int rel = hh - ww; rel = rel < -7 ? -7 : (rel > 7 ? 7 : rel);
            t0 = btab[rel + 7];
            hh = ((int)row1 >> 7) & 127; ww = (int)row1 & 127;
            rel = hh - ww; rel = rel < -7 ? -7 : (rel > 7 ? 7 : rel);
            t1 = btab[rel + 7];
        }
#pragma unroll
        for (int j = 0; j < 4; j++) {
            int col = n0 + wn * 32 + j * 8 + c2;
            float b0 = 0.f, b1 = 0.f, cs0 = 0.f, cs1 = 0.f;
            if (EPI == 2) {
                b0 = bias[col]; b1 = bias[col + 1];
                cs0 = colsum[col]; cs1 = colsum[col + 1];
            }
            float2 v0, v1;
            v0.x = acc[i][j][0] + b0 + t0 * cs0;
            v0.y = acc[i][j][1] + b1 + t0 * cs1;
            v1.x = acc[i][j][2] + b0 + t1 * cs0;
            v1.y = acc[i][j][3] + b1 + t1 * cs1;
            *(float2*)&C[row0 * ldc + col] = v0;
            *(float2*)&C[row1 * ldc + col] = v1;
        }
    }
}

// ---------------- K feature pass ----------------------------------------------
__global__ __launch_bounds__(512, 1) void dd_k_kernel() {
    int z = blockIdx.y;
    int b = z >> 3, hd = z & 7;
    long long m0 = (long long)blockIdx.x * 128;
    const float* A = g_QKV + ((long long)b * NSEQ + m0) * QKVLD + 512 + hd * DHEAD;

    __shared__ float As[64][132];
    __shared__ float Bs[16][256];
    __shared__ float red[128 * 4];
    __shared__ float rss[128];
    __shared__ float redm[16];

    int tid = threadIdx.x;
    int tx = tid & 31, ty = tid >> 5;

#pragma unroll
    for (int i = 0; i < 4; i++) {
        int idx = tid + i * 512;
        int m = idx >> 4, kq = idx & 15;
        float4 v = *(const float4*)&A[(long long)m * QKVLD + kq * 4];
        As[kq * 4 + 0][m] = v.x; As[kq * 4 + 1][m] = v.y;
        As[kq * 4 + 2][m] = v.z; As[kq * 4 + 3][m] = v.w;
    }
    __syncthreads();

    {
        int r = tid >> 2, p = tid & 3;
        float s = 0.f;
        for (int k = p * 16; k < p * 16 + 16; k++) { float x = As[k][r]; s += x * x; }
        red[r * 4 + p] = s;
    }
    __syncthreads();
    if (tid < 128) rss[tid] = 0.0625f * (red[tid * 4] + red[tid * 4 + 1] + red[tid * 4 + 2] + red[tid * 4 + 3]);

    float acc[8][8];
#pragma unroll
    for (int i = 0; i < 8; i++)
#pragma unroll
        for (int j = 0; j < 8; j++) acc[i][j] = 0.f;

    for (int k0 = 0; k0 < 64; k0 += 16) {
        __syncthreads();
#pragma unroll
        for (int i = 0; i < 2; i++) {
            int idx = tid + i * 512;
            int k = idx >> 6, nq = idx & 63;
            *(float4*)&Bs[k][nq * 4] = *(const float4*)&g_projT[(k0 + k) * NF + nq * 4];
        }
        __syncthreads();
#pragma unroll
        for (int k = 0; k < 16; k++) {
            float4 a0 = *(const float4*)&As[k0 + k][ty * 8];
            float4 a1 = *(const float4*)&As[k0 + k][ty * 8 + 4];
            float4 b0 = *(const float4*)&Bs[k][tx * 8];
            float4 b1 = *(const float4*)&Bs[k][tx * 8 + 4];
            float av[8] = {a0.x, a0.y, a0.z, a0.w, a1.x, a1.y, a1.z, a1.w};
            float bv[8] = {b0.x, b0.y, b0.z, b0.w, b1.x, b1.y, b1.z, b1.w};
#pragma unroll
            for (int i = 0; i < 8; i++)
#pragma unroll
                for (int j = 0; j < 8; j++) acc[i][j] += av[i] * bv[j];
        }
    }

    const float DN = 0.35355339059327373f;
    float* KPp = g_KP + ((long long)z * NSEQ + m0) * NF;
    float mx = __int_as_float(0xff800000);
#pragma unroll
    for (int i = 0; i < 8; i++) {
        int m = ty * 8 + i;
        float d = rss[m];
        float4 v0, v1; float dd;
        dd = acc[i][0] * DN; mx = fmaxf(mx, dd); v0.x = dd - d;
        dd = acc[i][1] * DN; mx = fmaxf(mx, dd); v0.y = dd - d;
        dd = acc[i][2] * DN; mx = fmaxf(mx, dd); v0.z = dd - d;
        dd = acc[i][3] * DN; mx = fmaxf(mx, dd); v0.w = dd - d;
        dd = acc[i][4] * DN; mx = fmaxf(mx, dd); v1.x = dd - d;
        dd = acc[i][5] * DN; mx = fmaxf(mx, dd); v1.y = dd - d;
        dd = acc[i][6] * DN; mx = fmaxf(mx, dd); v1.z = dd - d;
        dd = acc[i][7] * DN; mx = fmaxf(mx, dd); v1.w = dd - d;
        *(float4*)&KPp[(long long)m * NF + tx * 8] = v0;
        *(float4*)&KPp[(long long)m * NF + tx * 8 + 4] = v1;
    }
#pragma unroll
    for (int o = 16; o > 0; o >>= 1) mx = fmaxf(mx, __shfl_xor_sync(0xffffffff, mx, o));
    if ((tid & 31) == 0) redm[tid >> 5] = mx;
    __syncthreads();
    if (tid == 0) {
        float m2 = redm[0];
#pragma unroll
        for (int i = 1; i < 16; i++) m2 = fmaxf(m2, redm[i]);
        atomicMaxFloat(&g_kmax[z], m2);
    }
}

// ---------------- ctx partials -------------------------------------------------
__global__ __launch_bounds__(256, 2) void ctx_part_kernel() {
    int z = blockIdx.y, ch = blockIdx.x;
    int b = z >> 3, hd = z & 7;
    const float* KPp = g_KP + ((long long)z * NSEQ + (long long)ch * CHROWS) * NF;
    const float* Vp  = g_QKV + ((long long)b * NSEQ + (long long)ch * CHROWS) * QKVLD + 1024 + hd * DHEAD;
    float km = g_kmax[z];

    __shared__ float Ks[16][260];
    __shared__ float Vs[16][68];

    int tid = threadIdx.x;
    int tx = tid & 7, ty = tid >> 3;

    float acc[8][8];
#pragma unroll
    for (int i = 0; i < 8; i++)
#pragma unroll
        for (int j = 0; j < 8; j++) acc[i][j] = 0.f;
    float ks_acc = 0.f;

    for (int r0 = 0; r0 < CHROWS; r0 += 16) {
        __syncthreads();
#pragma unroll
        for (int i = 0; i < 4; i++) {
            int idx = tid + i * 256;
            int r = idx >> 6, cq = idx & 63;
            float4 v = *(const float4*)&KPp[((long long)(r0 + r)) * NF + cq * 4];
            v.x = 0.0625f * (__expf(v.x - km) + 1e-4f);
            v.y = 0.0625f * (__expf(v.y - km) + 1e-4f);
            v.z = 0.0625f * (__expf(v.z - km) + 1e-4f);
            v.w = 0.0625f * (__expf(v.w - km) + 1e-4f);
            *(float4*)&Ks[r][cq * 4] = v;
        }
        {
            int r = tid >> 4, nq = tid & 15;
            *(float4*)&Vs[r][nq * 4] = *(const float4*)&Vp[((long long)(r0 + r)) * QKVLD + nq * 4];
        }
        __syncthreads();
#pragma unroll
        for (int r = 0; r < 16; r++) ks_acc += Ks[r][tid];
#pragma unroll
        for (int r = 0; r < 16; r++) {
            float4 a0 = *(const float4*)&Ks[r][ty * 8];
            float4 a1 = *(const float4*)&Ks[r][ty * 8 + 4];
            float4 b0 = *(const float4*)&Vs[r][tx * 8];
            float4 b1 = *(const float4*)&Vs[r][tx * 8 + 4];
            float av[8] = {a0.x, a0.y, a0.z, a0.w, a1.x, a1.y, a1.z, a1.w};
            float bv[8] = {b0.x, b0.y, b0.z, b0.w, b1.x, b1.y, b1.z, b1.w};
#pragma unroll
            for (int i = 0; i < 8; i++)
#pragma unroll
                for (int j = 0; j < 8; j++) acc[i][j] += av[i] * bv[j];
        }
    }

    long long base = ((long long)(z * NCHUNK + ch)) * (NF * DHEAD);
#pragma unroll
    for (int i = 0; i < 8; i++) {
        int f = ty * 8 + i;
        *(float4*)&g_ctxP[base + (long long)f * DHEAD + tx * 8] =
            make_float4(acc[i][0], acc[i][1], acc[i][2], acc[i][3]);
        *(float4*)&g_ctxP[base + (long long)f * DHEAD + tx * 8 + 4] =
            make_float4(acc[i][4], acc[i][5], acc[i][6], acc[i][7]);
    }
    g_ksumP[(z * NCHUNK + ch) * NF + tid] = ks_acc;
}

__global__ void ctx_reduce() {
    int idx = blockIdx.x * 256 + threadIdx.x;
    int z = idx >> 14, fd = idx & 16383;
    float s = 0.f;
#pragma unroll
    for (int c = 0; c < NCHUNK; c++)
        s += g_ctxP[((long long)(z * NCHUNK + c)) * 16384 + fd];
    g_ctx[(long long)z * 16384 + fd] = s;
}

__global__ void ksum_reduce() {
    int z = blockIdx.x, f = threadIdx.x;
    float s = 0.f;
#pragma unroll
    for (int c = 0; c < NCHUNK; c++) s += g_ksumP[(z * NCHUNK + c) * NF + f];
    g_ksum[z * NF + f] = s;
}

// ---------------- fused Q features + attention --------------------------------
#define QPP 260
__global__ __launch_bounds__(512, 1) void fused_attn_kernel() {
    extern __shared__ float smemf[];
    float* qp     = smemf;
    float* qs     = qp + 128 * QPP;
    float* pb     = qs + 64 * 132;
    float* cs     = pb + 16 * 256;
    float* ks     = cs + 16 * 68;
    float* rowsub = ks + 256;
    float* sdinv  = rowsub + 128;
    float* red    = sdinv + 128;

    int z = blockIdx.y;
    int b = z >> 3, hd = z & 7;
    long long m0 = (long long)blockIdx.x * 128;
    const float* Aq = g_QKV + ((long long)b * NSEQ + m0) * QKVLD + hd * DHEAD;

    int tid = threadIdx.x;

#pragma unroll
    for (int i = 0; i < 4; i++) {
        int idx = tid + i * 512;
        int m = idx >> 4, kq = idx & 15;
        float4 v = *(const float4*)&Aq[(long long)m * QKVLD + kq * 4];
        qs[(kq * 4 + 0) * 132 + m] = v.x; qs[(kq * 4 + 1) * 132 + m] = v.y;
        qs[(kq * 4 + 2) * 132 + m] = v.z; qs[(kq * 4 + 3) * 132 + m] = v.w;
    }
    if (tid < 256) ks[tid] = g_ksum[z * NF + tid];
    __syncthreads();

    {
        int r = tid >> 2, p = tid & 3;
        float s = 0.f;
        for (int k = p * 16; k < p * 16 + 16; k++) { float x = qs[k * 132 + r]; s += x * x; }
        red[r * 4 + p] = s;
    }
    __syncthreads();
    if (tid < 128) rowsub[tid] = 0.0625f * (red[tid * 4] + red[tid * 4 + 1] + red[tid * 4 + 2] + red[tid * 4 + 3]);

    int tx = tid & 31, ty = tid >> 5;
    {
        float acc[8][8];
#pragma unroll
        for (int i = 0; i < 8; i++)
#pragma unroll
            for (int j = 0; j < 8; j++) acc[i][j] = 0.f;
        for (int k0 = 0; k0 < 64; k0 += 16) {
            __syncthreads();
#pragma unroll
            for (int i = 0; i < 2; i++) {
                int idx = tid + i * 512;
                int k = idx >> 6, nq = idx & 63;
                *(float4*)&pb[k * 256 + nq * 4] = *(const float4*)&g_projT[(k0 + k) * NF + nq * 4];
            }
            __syncthreads();
#pragma unroll
            for (int k = 0; k < 16; k++) {
                float4 a0 = *(const float4*)&qs[(k0 + k) * 132 + ty * 8];
                float4 a1 = *(const float4*)&qs[(k0 + k) * 132 + ty * 8 + 4];
                float4 b0 = *(const float4*)&pb[k * 256 + tx * 8];
                float4 b1 = *(const float4*)&pb[k * 256 + tx * 8 + 4];
                float av[8] = {a0.x, a0.y, a0.z, a0.w, a1.x, a1.y, a1.z, a1.w};
                float bv[8] = {b0.x, b0.y, b0.z, b0.w, b1.x, b1.y, b1.z, b1.w};
#pragma unroll
                for (int i = 0; i < 8; i++)
#pragma unroll
                    for (int j = 0; j < 8; j++) acc[i][j] += av[i] * bv[j];
            }
        }
        const float DN = 0.35355339059327373f;
        __syncthreads();
#pragma unroll
        for (int i = 0; i < 8; i++) {
            int m = ty * 8 + i;
            *(float4*)&qp[m * QPP + tx * 8] =
                make_float4(acc[i][0] * DN, acc[i][1] * DN, acc[i][2] * DN, acc[i][3] * DN);
            *(float4*)&qp[m * QPP + tx * 8 + 4] =
                make_float4(acc[i][4] * DN, acc[i][5] * DN, acc[i][6] * DN, acc[i][7] * DN);
        }
    }
    __syncthreads();

    {
        int r = tid >> 2, p = tid & 3;
        float mx = __int_as_float(0xff800000);
        for (int f = p * 64; f < p * 64 + 64; f++) mx = fmaxf(mx, qp[r * QPP + f]);
        red[r * 4 + p] = mx;
    }
    __syncthreads();
    if (tid < 128) {
        float m = fmaxf(fmaxf(red[tid * 4], red[tid * 4 + 1]), fmaxf(red[tid * 4 + 2], red[tid * 4 + 3]));
        rowsub[tid] += m;
    }
    __syncthreads();

#pragma unroll
    for (int i = 0; i < 64; i++) {
        int idx = i * 512 + tid;
        int r = idx >> 8, f = idx & 255;
        float v = qp[r * QPP + f];
        qp[r * QPP + f] = 0.0625f * (__expf(v - rowsub[r]) + 1e-4f);
    }
    __syncthreads();

    {
        int r = tid >> 2, p = tid & 3;
        float s = 0.f;
        for (int f = p * 64; f < p * 64 + 64; f++) s += qp[r * QPP + f] * ks[f];
        red[r * 4 + p] = s;
    }
    __syncthreads();
    if (tid < 128)
        sdinv[tid] = 1.0f / (red[tid * 4] + red[tid * 4 + 1] + red[tid * 4 + 2] + red[tid * 4 + 3]);

    int tx2 = tid & 15, ty2 = tid >> 4;
    float acc2[4][4];
#pragma unroll
    for (int i = 0; i < 4; i++)
#pragma unroll
        for (int j = 0; j < 4; j++) acc2[i][j] = 0.f;

    const float* ctxp = g_ctx + (long long)z * NF * DHEAD;
    for (int f0 = 0; f0 < NF; f0 += 16) {
        __syncthreads();
        if (tid < 256) {
            int k = tid >> 4, nq = tid & 15;
            *(float4*)&cs[k * 68 + nq * 4] = *(const float4*)&ctxp[(long long)(f0 + k) * DHEAD + nq * 4];
        }
        __syncthreads();
#pragma unroll
        for (int k = 0; k < 16; k++) {
            float a0 = qp[(ty2 * 4 + 0) * QPP + f0 + k];
            float a1 = qp[(ty2 * 4 + 1) * QPP + f0 + k];
            float a2 = qp[(ty2 * 4 + 2) * QPP + f0 + k];
            float a3 = qp[(ty2 * 4 + 3) * QPP + f0 + k];
            float4 b4 = *(const float4*)&cs[k * 68 + tx2 * 4];
            float bv[4] = {b4.x, b4.y, b4.z, b4.w};
            float av[4] = {a0, a1, a2, a3};
#pragma unroll
            for (int i = 0; i < 4; i++)
#pragma unroll
                for (int j = 0; j < 4; j++) acc2[i][j] += av[i] * bv[j];
        }
    }

#pragma unroll
    for (int i = 0; i < 4; i++) {
        int m = ty2 * 4 + i;
        float s = sdinv[m];
        long long base = ((long long)b * NSEQ + m0 + m) * INNERD + hd * DHEAD + tx2 * 4;
        float vv[4] = {acc2[i][0] * s, acc2[i][1] * s, acc2[i][2] * s, acc2[i][3] * s};
        __nv_bfloat16 h[4], l[4];
#pragma unroll
        for (int j = 0; j < 4; j++) {
            h[j] = __float2bfloat16(vv[j]);
            l[j] = __float2bfloat16(vv[j] - __bfloat162float(h[j]));
        }
        *(__nv_bfloat162*)&g_ATTh[base]     = __nv_bfloat162(h[0], h[1]);
        *(__nv_bfloat162*)&g_ATTh[base + 2] = __nv_bfloat162(h[2], h[3]);
        *(__nv_bfloat162*)&g_ATTl[base]     = __nv_bfloat162(l[0], l[1]);
        *(__nv_bfloat162*)&g_ATTl[base + 2] = __nv_bfloat162(l[2], l[3]);
    }
}

#define SMEM_ATTN ((128 * QPP + 64 * 132 + 16 * 256 + 16 * 68 + 256 + 128 + 128 + 512) * 4)

// ---------------- launcher ----------------------------------------------------
extern "C" void kernel_launch(void* const* d_in, const int* in_sizes, int n_in,
                              void* d_out, int out_size) {
    const float* x    = (const float*)d_in[0];
    const float* Wq   = (const float*)d_in[1];
    const float* Wk   = (const float*)d_in[2];
    const float* Wv   = (const float*)d_in[3];
    const float* Wo   = (const float*)d_in[4];
    const float* bo   = (const float*)d_in[5];
    const float* proj = (const float*)d_in[6];
    const float* Wp   = (const float*)d_in[7];
    const float* bp   = (const float*)d_in[8];
    const float* btab = (const float*)d_in[9];
    float* out = (float*)d_out;

    static bool attr_set = false;
    if (!attr_set) {
        cudaFuncSetAttribute(fused_attn_kernel, cudaFuncAttributeMaxDynamicSharedMemorySize, SMEM_ATTN);
        cudaFuncSetAttribute(mma_gemm<0>, cudaFuncAttributeMaxDynamicSharedMemorySize, SMEM_MMA);
        cudaFuncSetAttribute(mma_gemm<2>, cudaFuncAttributeMaxDynamicSharedMemorySize, SMEM_MMA);
        attr_set = true;
    }

    float *pQKV, *pWoWp, *pB2, *pCS;
    __nv_bfloat16 *pXh, *pXl, *pWch, *pWcl, *pATTh, *pATTl, *pWoWph, *pWoWpl;
    cudaGetSymbolAddress((void**)&pQKV,   g_QKV);
    cudaGetSymbolAddress((void**)&pWoWp,  g_WoWp);
    cudaGetSymbolAddress((void**)&pB2,    g_bias2);
    cudaGetSymbolAddress((void**)&pCS,    g_colsum);
    cudaGetSymbolAddress((void**)&pXh,    g_Xh);
    cudaGetSymbolAddress((void**)&pXl,    g_Xl);
    cudaGetSymbolAddress((void**)&pWch,   g_Wch);
    cudaGetSymbolAddress((void**)&pWcl,   g_Wcl);
    cudaGetSymbolAddress((void**)&pATTh,  g_ATTh);
    cudaGetSymbolAddress((void**)&pATTl,  g_ATTl);
    cudaGetSymbolAddress((void**)&pWoWph, g_WoWph);
    cudaGetSymbolAddress((void**)&pWoWpl, g_WoWpl);

    init_kernel<<<1, 32>>>();
    transpose_proj<<<64, 256>>>(proj);
    bias2_kernel<<<1, 256>>>(bo, Wp, bp);
    split_x_kernel<<<TOK * CDIM / 1024, 256>>>(x);
    pack_w_kernel<<<CDIM * QKVLD / 256, 256>>>(Wq, Wk, Wv);

    // WoWp = Wo @ Wp (fp32), then split
    sgemm128<<<dim3(CDIM / 128, INNERD / 128), 256>>>(Wo, Wp, pWoWp, CDIM, CDIM, CDIM, CDIM);
    split_wowp_kernel<<<INNERD * CDIM / 256, 256>>>();

    // QKV fused tensor GEMM: [65536,256] @ [256,1536]
    mma_gemm<0><<<dim3(QKVLD / 128, TOK / 128), 256, SMEM_MMA>>>(
        pXh, pXl, pWch, pWcl, pQKV, CDIM, CDIM, QKVLD, QKVLD,
        nullptr, nullptr, nullptr);

    dd_k_kernel<<<dim3(NSEQ / 128, NZ), 512>>>();
    ctx_part_kernel<<<dim3(NCHUNK, NZ), 256>>>();
    ctx_reduce<<<(NZ * NF * DHEAD) / 256, 256>>>();
    ksum_reduce<<<NZ, 256>>>();
    fused_attn_kernel<<<dim3(NSEQ / 128, NZ), 512, SMEM_ATTN>>>();

    // out = ATT @ WoWp + bias2 + rel*colsum  (tensor GEMM)
    mma_gemm<2><<<dim3(CDIM / 128, TOK / 128), 256, SMEM_MMA>>>(
        pATTh, pATTl, pWoWph, pWoWpl, out, INNERD, INNERD, CDIM, CDIM,
        pB2, btab, pCS);

    (void)in_sizes; (void)n_in; (void)out_size;
}

// round 8
// speedup vs baseline: 2.1021x; 1.1558x over previous
#include <cuda_runtime.h>
#include <cuda_bf16.h>
#include <math.h>
#include <stdint.h>

#define TOK    65536
#define NSEQ   16384
#define CDIM   256
#define INNERD 512
#define QKVLD  1536
#define NHEAD  8
#define DHEAD  64
#define NF     256
#define NZ     32
#define NCHUNK 16
#define CHROWS (NSEQ / NCHUNK)   // 1024

// ---------------- scratch (static device globals) ----------------------------
__device__ float g_QKV[(long long)TOK * QKVLD];          // Q|K|V fp32
__device__ float g_KP[(long long)NZ * NSEQ * NF];
__device__ __nv_bfloat16 g_Xh[(long long)TOK * CDIM];
__device__ __nv_bfloat16 g_Xl[(long long)TOK * CDIM];
__device__ __nv_bfloat16 g_Wch[CDIM * QKVLD];
__device__ __nv_bfloat16 g_Wcl[CDIM * QKVLD];
__device__ __nv_bfloat16 g_ATTh[(long long)TOK * INNERD];
__device__ __nv_bfloat16 g_ATTl[(long long)TOK * INNERD];
__device__ __nv_bfloat16 g_WoWph[INNERD * CDIM];
__device__ __nv_bfloat16 g_WoWpl[INNERD * CDIM];
__device__ __nv_bfloat16 g_QKh[(long long)TOK * 1024];   // Q|K bf16 hi
__device__ __nv_bfloat16 g_QKl[(long long)TOK * 1024];   // Q|K bf16 lo
__device__ __nv_bfloat16 g_Ph[DHEAD * NF];               // DN*projT hi
__device__ __nv_bfloat16 g_Pl[DHEAD * NF];               // DN*projT lo
__device__ float g_rssq[(long long)NZ * NSEQ];           // 0.0625*sumsq(q)
__device__ float g_rssk[(long long)NZ * NSEQ];
__device__ float g_kmax[NZ];
__device__ float g_ctxP[(long long)NZ * NCHUNK * NF * DHEAD];
__device__ float g_ctx[NZ * NF * DHEAD];
__device__ float g_ksumP[NZ * NCHUNK * NF];
__device__ float g_ksum[NZ * NF];
__device__ float g_WoWp[INNERD * CDIM];
__device__ float g_bias2[CDIM];
__device__ float g_colsum[CDIM];

// ---------------- ptx helpers -------------------------------------------------
__device__ __forceinline__ uint32_t smem_u32(const void* p) {
    uint32_t a;
    asm("{ .reg .u64 t; cvta.to.shared.u64 t, %1; cvt.u32.u64 %0, t; }" : "=r"(a) : "l"(p));
    return a;
}
#define CP_ASYNC16(dst, src) \
    asm volatile("cp.async.cg.shared.global [%0], [%1], 16;\n" :: "r"(dst), "l"(src))
#define CP_COMMIT() asm volatile("cp.async.commit_group;\n")
#define CP_WAIT1()  asm volatile("cp.async.wait_group 1;\n")
#define CP_WAIT0()  asm volatile("cp.async.wait_group 0;\n")

__device__ __forceinline__ void ldsm_x4(uint32_t (&r)[4], uint32_t a) {
    asm volatile("ldmatrix.sync.aligned.m8n8.x4.shared.b16 {%0,%1,%2,%3}, [%4];"
                 : "=r"(r[0]), "=r"(r[1]), "=r"(r[2]), "=r"(r[3]) : "r"(a));
}
__device__ __forceinline__ void ldsm_x4_t(uint32_t (&r)[4], uint32_t a) {
    asm volatile("ldmatrix.sync.aligned.m8n8.x4.trans.shared.b16 {%0,%1,%2,%3}, [%4];"
                 : "=r"(r[0]), "=r"(r[1]), "=r"(r[2]), "=r"(r[3]) : "r"(a));
}
__device__ __forceinline__ void mma_bf16(float (&d)[4], const uint32_t (&a)[4],
                                         uint32_t b0, uint32_t b1) {
    asm volatile("mma.sync.aligned.m16n8k16.row.col.f32.bf16.bf16.f32 "
                 "{%0,%1,%2,%3},{%4,%5,%6,%7},{%8,%9},{%0,%1,%2,%3};"
                 : "+f"(d[0]), "+f"(d[1]), "+f"(d[2]), "+f"(d[3])
                 : "r"(a[0]), "r"(a[1]), "r"(a[2]), "r"(a[3]), "r"(b0), "r"(b1));
}

__device__ __forceinline__ void atomicMaxFloat(float* addr, float val) {
    if (val >= 0.f) atomicMax((int*)addr, __float_as_int(val));
    else            atomicMin((unsigned int*)addr, (unsigned int)__float_as_int(val));
}

// ---------------- small prep kernels ------------------------------------------
__global__ void init_kernel() {
    int t = threadIdx.x;
    if (t < NZ) g_kmax[t] = __int_as_float(0xff800000);
}

// projT = (dn * proj)^T, split hi/lo
__global__ void transpose_proj_split(const float* __restrict__ proj) {
    int t = blockIdx.x * 256 + threadIdx.x;
    int d = t >> 8, f = t & 255;
    const float DN = 0.35355339059327373f;
    float v = proj[f * DHEAD + d] * DN;
    __nv_bfloat16 h = __float2bfloat16(v);
    g_Ph[d * NF + f] = h;
    g_Pl[d * NF + f] = __float2bfloat16(v - __bfloat162float(h));
}

__global__ void bias2_kernel(const float* __restrict__ bo,
                             const float* __restrict__ Wp,
                             const float* __restrict__ bp) {
    int n = threadIdx.x;
    float s = 0.f, cs = 0.f;
    for (int c = 0; c < CDIM; c++) {
        float w = Wp[c * CDIM + n];
        s += bo[c] * w;
        cs += w;
    }
    g_bias2[n] = s + bp[n];
    g_colsum[n] = cs;
}

__global__ void split_x_kernel(const float* __restrict__ x) {
    long long i = (long long)blockIdx.x * 256 + threadIdx.x;
    float4 v = *(const float4*)&x[i * 4];
    float vv[4] = {v.x, v.y, v.z, v.w};
#pragma unroll
    for (int j = 0; j < 4; j++) {
        __nv_bfloat16 h = __float2bfloat16(vv[j]);
        g_Xh[i * 4 + j] = h;
        g_Xl[i * 4 + j] = __float2bfloat16(vv[j] - __bfloat162float(h));
    }
}

__global__ void pack_w_kernel(const float* __restrict__ Wq,
                              const float* __restrict__ Wk,
                              const float* __restrict__ Wv) {
    int i = blockIdx.x * 256 + threadIdx.x;
    int c = i / QKVLD, n = i % QKVLD;
    float v = (n < 512) ? Wq[c * 512 + n]
            : (n < 1024) ? Wk[c * 512 + n - 512]
                         : Wv[c * 512 + n - 1024];
    __nv_bfloat16 h = __float2bfloat16(v);
    g_Wch[i] = h;
    g_Wcl[i] = __float2bfloat16(v - __bfloat162float(h));
}

__global__ void split_wowp_kernel() {
    int i = blockIdx.x * 256 + threadIdx.x;
    float v = g_WoWp[i];
    __nv_bfloat16 h = __float2bfloat16(v);
    g_WoWph[i] = h;
    g_WoWpl[i] = __float2bfloat16(v - __bfloat162float(h));
}

// split Q|K (cols 0..1023 of QKV) into bf16 hi/lo + per-(token,head) diag sums
// grid = TOK blocks, 256 threads; thread t covers cols [t*4, t*4+4)
__global__ __launch_bounds__(256) void split_qk_kernel() {
    long long tok = blockIdx.x;
    int t = threadIdx.x;
    const float* src = g_QKV + tok * QKVLD;
    float4 v = *(const float4*)&src[t * 4];
    float vv[4] = {v.x, v.y, v.z, v.w};
    __nv_bfloat16 h[4], l[4];
#pragma unroll
    for (int j = 0; j < 4; j++) {
        h[j] = __float2bfloat16(vv[j]);
        l[j] = __float2bfloat16(vv[j] - __bfloat162float(h[j]));
    }
    long long o = tok * 1024 + t * 4;
    *(__nv_bfloat162*)&g_QKh[o]     = __nv_bfloat162(h[0], h[1]);
    *(__nv_bfloat162*)&g_QKh[o + 2] = __nv_bfloat162(h[2], h[3]);
    *(__nv_bfloat162*)&g_QKl[o]     = __nv_bfloat162(l[0], l[1]);
    *(__nv_bfloat162*)&g_QKl[o + 2] = __nv_bfloat162(l[2], l[3]);

    float s = vv[0]*vv[0] + vv[1]*vv[1] + vv[2]*vv[2] + vv[3]*vv[3];
#pragma unroll
    for (int off = 8; off > 0; off >>= 1)
        s += __shfl_down_sync(0xffffffff, s, off, 16);
    if ((t & 15) == 0) {
        int head = t >> 4;                 // 0-7 Q, 8-15 K
        int b = (int)(tok >> 14), nloc = (int)(tok & (NSEQ - 1));
        int z = b * 8 + (head & 7);
        float r = 0.0625f * s;
        if (head < 8) g_rssq[(long long)z * NSEQ + nloc] = r;
        else          g_rssk[(long long)z * NSEQ + nloc] = r;
    }
}

// ---------------- fp32 sgemm128 (small WoWp product only) ---------------------
__global__ __launch_bounds__(256, 2) void sgemm128(
    const float* __restrict__ A, const float* __restrict__ B, float* __restrict__ C,
    int lda, int ldb, int ldc, int K)
{
    __shared__ float As[2][16][132];
    __shared__ float Bs[2][16][128];
    int tid = threadIdx.x;
    int tx = tid & 15, ty = tid >> 4;
    long long m0 = (long long)blockIdx.y * 128;
    int n0 = blockIdx.x * 128;
    const float* Ab = A + m0 * lda;
    const float* Bb = B + n0;

#pragma unroll
    for (int i = 0; i < 2; i++) {
        int idx = tid + i * 256;
        int m = idx >> 2, kq = idx & 3;
        float4 v = *(const float4*)&Ab[(long long)m * lda + kq * 4];
        As[0][kq * 4 + 0][m] = v.x; As[0][kq * 4 + 1][m] = v.y;
        As[0][kq * 4 + 2][m] = v.z; As[0][kq * 4 + 3][m] = v.w;
    }
#pragma unroll
    for (int i = 0; i < 2; i++) {
        int idx = tid + i * 256;
        int k = idx >> 5, nq = idx & 31;
        *(float4*)&Bs[0][k][nq * 4] = *(const float4*)&Bb[(long long)k * ldb + nq * 4];
    }
    __syncthreads();

    float acc[8][8];
#pragma unroll
    for (int i = 0; i < 8; i++)
#pragma unroll
        for (int j = 0; j < 8; j++) acc[i][j] = 0.f;

    int nk = K >> 4, buf = 0;
    for (int it = 0; it < nk; ++it) {
        float4 pa[2], pbv[2];
        bool nxt = (it + 1 < nk);
        if (nxt) {
            int k0 = (it + 1) << 4;
#pragma unroll
            for (int i = 0; i < 2; i++) {
                int idx = tid + i * 256;
                int m = idx >> 2, kq = idx & 3;
                pa[i] = *(const float4*)&Ab[(long long)m * lda + k0 + kq * 4];
            }
#pragma unroll
            for (int i = 0; i < 2; i++) {
                int idx = tid + i * 256;
                int k = idx >> 5, nq = idx & 31;
                pbv[i] = *(const float4*)&Bb[(long long)(k0 + k) * ldb + nq * 4];
            }
        }
#pragma unroll
        for (int k = 0; k < 16; k++) {
            float4 a0 = *(const float4*)&As[buf][k][ty * 4];
            float4 a1 = *(const float4*)&As[buf][k][ty * 4 + 64];
            float4 b0 = *(const float4*)&Bs[buf][k][tx * 4];
            float4 b1 = *(const float4*)&Bs[buf][k][tx * 4 + 64];
            float av[8] = {a0.x, a0.y, a0.z, a0.w, a1.x, a1.y, a1.z, a1.w};
            float bv[8] = {b0.x, b0.y, b0.z, b0.w, b1.x, b1.y, b1.z, b1.w};
#pragma unroll
            for (int i = 0; i < 8; i++)
#pragma unroll
                for (int j = 0; j < 8; j++) acc[i][j] += av[i] * bv[j];
        }
        if (nxt) {
            int nb = buf ^ 1;
#pragma unroll
            for (int i = 0; i < 2; i++) {
                int idx = tid + i * 256;
                int m = idx >> 2, kq = idx & 3;
                As[nb][kq * 4 + 0][m] = pa[i].x; As[nb][kq * 4 + 1][m] = pa[i].y;
                As[nb][kq * 4 + 2][m] = pa[i].z; As[nb][kq * 4 + 3][m] = pa[i].w;
            }
#pragma unroll
            for (int i = 0; i < 2; i++) {
                int idx = tid + i * 256;
                int k = idx >> 5, nq = idx & 31;
                *(float4*)&Bs[nb][k][nq * 4] = pbv[i];
            }
            __syncthreads();
            buf = nb;
        }
    }
#pragma unroll
    for (int i = 0; i < 8; i++) {
        long long gm = m0 + (i < 4 ? ty * 4 + i : 64 + ty * 4 + (i - 4));
        *(float4*)&C[gm * ldc + n0 + tx * 4] =
            make_float4(acc[i][0], acc[i][1], acc[i][2], acc[i][3]);
        *(float4*)&C[gm * ldc + n0 + tx * 4 + 64] =
            make_float4(acc[i][4], acc[i][5], acc[i][6], acc[i][7]);
    }
}

// ---------------- bf16-split tensor-core GEMM ---------------------------------
#define SOFF_AL 10240
#define SOFF_BH 20480
#define SOFF_BL 29184
#define STAGE_B 37888
#define SMEM_MMA (2 * STAGE_B)

template <int EPI>
__global__ __launch_bounds__(256) void mma_gemm(
    const __nv_bfloat16* __restrict__ Ah, const __nv_bfloat16* __restrict__ Al,
    const __nv_bfloat16* __restrict__ Bh, const __nv_bfloat16* __restrict__ Bl,
    float* __restrict__ C, int K, int lda, int ldb, int ldc,
    const float* __restrict__ bias, const float* __restrict__ btab,
    const float* __restrict__ colsum)
{
    extern __shared__ char smem[];
    uint32_t sbase = smem_u32(smem);

    int tid = threadIdx.x;
    int lane = tid & 31, wid = tid >> 5;
    int wm = wid & 1, wn = wid >> 1;
    long long m0 = (long long)blockIdx.y * 128;
    int n0 = blockIdx.x * 128;

    const __nv_bfloat16* Ahb = Ah + m0 * lda;
    const __nv_bfloat16* Alb = Al + m0 * lda;
    const __nv_bfloat16* Bhb = Bh + n0;
    const __nv_bfloat16* Blb = Bl + n0;

    int nk = K >> 5;

    int ar0 = tid >> 2, ac0 = tid & 3;
    int ar1 = (tid + 256) >> 2, ac1 = tid & 3;
    int br0 = tid >> 4, bc0 = tid & 15;
    int br1 = (tid + 256) >> 4, bc1 = tid & 15;

#define LOAD_STAGE(kt, s)                                                          \
    {                                                                              \
        uint32_t sb = sbase + (s) * STAGE_B;                                       \
        long long ka = (long long)(kt) * 32;                                       \
        CP_ASYNC16(sb + ar0 * 80 + ac0 * 16, Ahb + ar0 * lda + ka + ac0 * 8);      \
        CP_ASYNC16(sb + ar1 * 80 + ac1 * 16, Ahb + ar1 * lda + ka + ac1 * 8);      \
        CP_ASYNC16(sb + SOFF_AL + ar0 * 80 + ac0 * 16, Alb + ar0 * lda + ka + ac0 * 8); \
        CP_ASYNC16(sb + SOFF_AL + ar1 * 80 + ac1 * 16, Alb + ar1 * lda + ka + ac1 * 8); \
        CP_ASYNC16(sb + SOFF_BH + br0 * 272 + bc0 * 16, Bhb + (ka + br0) * ldb + bc0 * 8); \
        CP_ASYNC16(sb + SOFF_BH + br1 * 272 + bc1 * 16, Bhb + (ka + br1) * ldb + bc1 * 8); \
        CP_ASYNC16(sb + SOFF_BL + br0 * 272 + bc0 * 16, Blb + (ka + br0) * ldb + bc0 * 8); \
        CP_ASYNC16(sb + SOFF_BL + br1 * 272 + bc1 * 16, Blb + (ka + br1) * ldb + bc1 * 8); \
        CP_COMMIT();                                                               \
    }

    LOAD_STAGE(0, 0);
    LOAD_STAGE(1, 1);

    float acc[4][4][4];
#pragma unroll
    for (int i = 0; i < 4; i++)
#pragma unroll
        for (int j = 0; j < 4; j++)
#pragma unroll
            for (int r = 0; r < 4; r++) acc[i][j][r] = 0.f;

    int lrow = (lane & 7) + ((lane >> 3) & 1) * 8;
    int lcol8 = (lane >> 4) * 8;

    for (int it = 0; it < nk; ++it) {
        if (it < nk - 1) { CP_WAIT1(); } else { CP_WAIT0(); }
        __syncthreads();
        uint32_t sb = sbase + (it & 1) * STAGE_B;
        uint32_t aAh = sb, aAl = sb + SOFF_AL, aBh = sb + SOFF_BH, aBl = sb + SOFF_BL;

#pragma unroll
        for (int ks = 0; ks < 2; ks++) {
            uint32_t ah[4][4], al[4][4];
            uint32_t bh[4][2], bl[4][2];
#pragma unroll
            for (int i = 0; i < 4; i++) {
                int r = wm * 64 + i * 16 + lrow;
                uint32_t off = (uint32_t)r * 80 + (ks * 16 + lcol8) * 2;
                ldsm_x4(ah[i], aAh + off);
                ldsm_x4(al[i], aAl + off);
            }
#pragma unroll
            for (int jj = 0; jj < 2; jj++) {
                int kr = ks * 16 + lrow;
                uint32_t off = (uint32_t)kr * 272 + (wn * 32 + jj * 16 + lcol8) * 2;
                uint32_t t[4];
                ldsm_x4_t(t, aBh + off);
                bh[jj * 2][0] = t[0]; bh[jj * 2][1] = t[1];
                bh[jj * 2 + 1][0] = t[2]; bh[jj * 2 + 1][1] = t[3];
                ldsm_x4_t(t, aBl + off);
                bl[jj * 2][0] = t[0]; bl[jj * 2][1] = t[1];
                bl[jj * 2 + 1][0] = t[2]; bl[jj * 2 + 1][1] = t[3];
            }
#pragma unroll
            for (int i = 0; i < 4; i++)
#pragma unroll
                for (int j = 0; j < 4; j++) {
                    mma_bf16(acc[i][j], ah[i], bh[j][0], bh[j][1]);
                    mma_bf16(acc[i][j], ah[i], bl[j][0], bl[j][1]);
                    mma_bf16(acc[i][j], al[i], bh[j][0], bh[j][1]);
                }
        }
        __syncthreads();
        if (it + 2 < nk) LOAD_STAGE(it + 2, it & 1);
    }

    int g = lane >> 2, c2 = (lane & 3) * 2;
#pragma unroll
    for (int i = 0; i < 4; i++) {
        long long row0 = m0 + wm * 64 + i * 16 + g;
        long long row1 = row0 + 8;
        float t0 = 0.f, t1 = 0.f;
        if (EPI == 2) {
            int hh = ((int)row0 >> 7) & 127, ww = (int)row0 & 127;
            int rel = hh - ww; rel = rel < -7 ? -7 : (rel > 7 ? 7 : rel);
            t0 = btab[rel + 7];
            hh = ((int)row1 >> 7) & 127; ww = (int)row1 & 127;
            rel = hh - ww; rel = rel < -7 ? -7 : (rel > 7 ? 7 : rel);
            t1 = btab[rel + 7];
        }
#pragma unroll
        for (int j = 0; j < 4; j++) {
            int col = n0 + wn * 32 + j * 8 + c2;
            float b0 = 0.f, b1 = 0.f, cs0 = 0.f, cs1 = 0.f;
            if (EPI == 2) {
                b0 = bias[col]; b1 = bias[col + 1];
                cs0 = colsum[col]; cs1 = colsum[col + 1];
            }
            float2 v0, v1;
            v0.x = acc[i][j][0] + b0 + t0 * cs0;
            v0.y = acc[i][j][1] + b1 + t0 * cs1;
            v1.x = acc[i][j][2] + b0 + t1 * cs0;
            v1.y = acc[i][j][3] + b1 + t1 * cs1;
            *(float2*)&C[row0 * ldc + col] = v0;
            *(float2*)&C[row1 * ldc + col] = v1;
        }
    }
}

// ---------------- K feature pass: batched bf16-split tensor GEMM --------------
// KP[z][n][f] = dn*k_h(n)@projT - diag(n); atomicMax raw dd per z.
// grid (NF/128=2, NSEQ/128, NZ), 256 thr, tile 128x128, K=64.
__global__ __launch_bounds__(256) void ddk_mma() {
    extern __shared__ char smem[];
    __shared__ float redm[8];
    uint32_t sbase = smem_u32(smem);

    int tid = threadIdx.x;
    int lane = tid & 31, wid = tid >> 5;
    int wm = wid & 1, wn = wid >> 1;
    int z = blockIdx.z, b = z >> 3, hd = z & 7;
    long long m0 = (long long)blockIdx.y * 128;
    int n0 = blockIdx.x * 128;

    const __nv_bfloat16* Ahb = g_QKh + ((long long)b * NSEQ + m0) * 1024 + 512 + hd * 64;
    const __nv_bfloat16* Alb = g_QKl + ((long long)b * NSEQ + m0) * 1024 + 512 + hd * 64;
    const __nv_bfloat16* Bhb = g_Ph + n0;
    const __nv_bfloat16* Blb = g_Pl + n0;
    const int lda = 1024, ldb = NF;

    int ar0 = tid >> 2, ac0 = tid & 3;
    int ar1 = (tid + 256) >> 2, ac1 = tid & 3;
    int br0 = tid >> 4, bc0 = tid & 15;
    int br1 = (tid + 256) >> 4, bc1 = tid & 15;

#define DDK_LOAD(kt, s)                                                            \
    {                                                                              \
        uint32_t sb = sbase + (s) * STAGE_B;                                       \
        long long ka = (long long)(kt) * 32;                                       \
        CP_ASYNC16(sb + ar0 * 80 + ac0 * 16, Ahb + ar0 * lda + ka + ac0 * 8);      \
        CP_ASYNC16(sb + ar1 * 80 + ac1 * 16, Ahb + ar1 * lda + ka + ac1 * 8);      \
        CP_ASYNC16(sb + SOFF_AL + ar0 * 80 + ac0 * 16, Alb + ar0 * lda + ka + ac0 * 8); \
        CP_ASYNC16(sb + SOFF_AL + ar1 * 80 + ac1 * 16, Alb + ar1 * lda + ka + ac1 * 8); \
        CP_ASYNC16(sb + SOFF_BH + br0 * 272 + bc0 * 16, Bhb + (ka + br0) * ldb + bc0 * 8); \
        CP_ASYNC16(sb + SOFF_BH + br1 * 272 + bc1 * 16, Bhb + (ka + br1) * ldb + bc1 * 8); \
        CP_ASYNC16(sb + SOFF_BL + br0 * 272 + bc0 * 16, Blb + (ka + br0) * ldb + bc0 * 8); \
        CP_ASYNC16(sb + SOFF_BL + br1 * 272 + bc1 * 16, Blb + (ka + br1) * ldb + bc1 * 8); \
        CP_COMMIT();                                                               \
    }

    DDK_LOAD(0, 0);
    DDK_LOAD(1, 1);

    float acc[4][4][4];
#pragma unroll
    for (int i = 0; i < 4; i++)
#pragma unroll
        for (int j = 0; j < 4; j++)
#pragma unroll
            for (int r = 0; r < 4; r++) acc[i][j][r] = 0.f;

    int lrow = (lane & 7) + ((lane >> 3) & 1) * 8;
    int lcol8 = (lane >> 4) * 8;

    for (int it = 0; it < 2; ++it) {
        if (it == 0) { CP_WAIT1(); } else { CP_WAIT0(); }
        __syncthreads();
        uint32_t sb = sbase + (it & 1) * STAGE_B;
        uint32_t aAh = sb, aAl = sb + SOFF_AL, aBh = sb + SOFF_BH, aBl = sb + SOFF_BL;

#pragma unroll
        for (int ks = 0; ks < 2; ks++) {
            uint32_t ah[4][4], al[4][4];
            uint32_t bh[4][2], bl[4][2];
#pragma unroll
            for (int i = 0; i < 4; i++) {
                int r = wm * 64 + i * 16 + lrow;
                uint32_t off = (uint32_t)r * 80 + (ks * 16 + lcol8) * 2;
                ldsm_x4(ah[i], aAh + off);
                ldsm_x4(al[i], aAl + off);
            }
#pragma unroll
            for (int jj = 0; jj < 2; jj++) {
                int kr = ks * 16 + lrow;
                uint32_t off = (uint32_t)kr * 272 + (wn * 32 + jj * 16 + lcol8) * 2;
                uint32_t t[4];
                ldsm_x4_t(t, aBh + off);
                bh[jj * 2][0] = t[0]; bh[jj * 2][1] = t[1];
                bh[jj * 2 + 1][0] = t[2]; bh[jj * 2 + 1][1] = t[3];
                ldsm_x4_t(t, aBl + off);
                bl[jj * 2][0] = t[0]; bl[jj * 2][1] = t[1];
                bl[jj * 2 + 1][0] = t[2]; bl[jj * 2 + 1][1] = t[3];
            }
#pragma unroll
            for (int i = 0; i < 4; i++)
#pragma unroll
                for (int j = 0; j < 4; j++) {
                    mma_bf16(acc[i][j], ah[i], bh[j][0], bh[j][1]);
                    mma_bf16(acc[i][j], ah[i], bl[j][0], bl[j][1]);
                    mma_bf16(acc[i][j], al[i], bh[j][0], bh[j][1]);
                }
        }
        __syncthreads();
    }

    // epilogue: max(raw dd), store dd - diag
    float mx = __int_as_float(0xff800000);
#pragma unroll
    for (int i = 0; i < 4; i++)
#pragma unroll
        for (int j = 0; j < 4; j++)
#pragma unroll
            for (int r = 0; r < 4; r++) mx = fmaxf(mx, acc[i][j][r]);

    int g = lane >> 2, c2 = (lane & 3) * 2;
#pragma unroll
    for (int i = 0; i < 4; i++) {
        long long row0 = m0 + wm * 64 + i * 16 + g;
        long long row1 = row0 + 8;
        float rs0 = g_rssk[(long long)z * NSEQ + row0];
        float rs1 = g_rssk[(long long)z * NSEQ + row1];
#pragma unroll
        for (int j = 0; j < 4; j++) {
            int col = n0 + wn * 32 + j * 8 + c2;
            float2 v0 = make_float2(acc[i][j][0] - rs0, acc[i][j][1] - rs0);
            float2 v1 = make_float2(acc[i][j][2] - rs1, acc[i][j][3] - rs1);
            *(float2*)&g_KP[((long long)z * NSEQ + row0) * NF + col] = v0;
            *(float2*)&g_KP[((long long)z * NSEQ + row1) * NF + col] = v1;
        }
    }
#pragma unroll
    for (int o = 16; o > 0; o >>= 1) mx = fmaxf(mx, __shfl_xor_sync(0xffffffff, mx, o));
    if (lane == 0) redm[wid] = mx;
    __syncthreads();
    if (tid == 0) {
        float m2 = redm[0];
#pragma unroll
        for (int i = 1; i < 8; i++) m2 = fmaxf(m2, redm[i]);
        atomicMaxFloat(&g_kmax[z], m2);
    }
}

// ---------------- ctx partials -------------------------------------------------
__global__ __launch_bounds__(256, 2) void ctx_part_kernel() {
    int z = blockIdx.y, ch = blockIdx.x;
    int b = z >> 3, hd = z & 7;
    const float* KPp = g_KP + ((long long)z * NSEQ + (long long)ch * CHROWS) * NF;
    const float* Vp  = g_QKV + ((long long)b * NSEQ + (long long)ch * CHROWS) * QKVLD + 1024 + hd * DHEAD;
    float km = g_kmax[z];

    __shared__ float Ks[16][260];
    __shared__ float Vs[16][68];

    int tid = threadIdx.x;
    int tx = tid & 7, ty = tid >> 3;

    float acc[8][8];
#pragma unroll
    for (int i = 0; i < 8; i++)
#pragma unroll
        for (int j = 0; j < 8; j++) acc[i][j] = 0.f;
    float ks_acc = 0.f;

    for (int r0 = 0; r0 < CHROWS; r0 += 16) {
        __syncthreads();
#pragma unroll
        for (int i = 0; i < 4; i++) {
            int idx = tid + i * 256;
            int r = idx >> 6, cq = idx & 63;
            float4 v = *(const float4*)&KPp[((long long)(r0 + r)) * NF + cq * 4];
            v.x = 0.0625f * (__expf(v.x - km) + 1e-4f);
            v.y = 0.0625f * (__expf(v.y - km) + 1e-4f);
            v.z = 0.0625f * (__expf(v.z - km) + 1e-4f);
            v.w = 0.0625f * (__expf(v.w - km) + 1e-4f);
            *(float4*)&Ks[r][cq * 4] = v;
        }
        {
            int r = tid >> 4, nq = tid & 15;
            *(float4*)&Vs[r][nq * 4] = *(const float4*)&Vp[((long long)(r0 + r)) * QKVLD + nq * 4];
        }
        __syncthreads();
#pragma unroll
        for (int r = 0; r < 16; r++) ks_acc += Ks[r][tid];
#pragma unroll
        for (int r = 0; r < 16; r++) {
            float4 a0 = *(const float4*)&Ks[r][ty * 8];
            float4 a1 = *(const float4*)&Ks[r][ty * 8 + 4];
            float4 b0 = *(const float4*)&Vs[r][tx * 8];
            float4 b1 = *(const float4*)&Vs[r][tx * 8 + 4];
            float av[8] = {a0.x, a0.y, a0.z, a0.w, a1.x, a1.y, a1.z, a1.w};
            float bv[8] = {b0.x, b0.y, b0.z, b0.w, b1.x, b1.y, b1.z, b1.w};
#pragma unroll
            for (int i = 0; i < 8; i++)
#pragma unroll
                for (int j = 0; j < 8; j++) acc[i][j] += av[i] * bv[j];
        }
    }

    long long base = ((long long)(z * NCHUNK + ch)) * (NF * DHEAD);
#pragma unroll
    for (int i = 0; i < 8; i++) {
        int f = ty * 8 + i;
        *(float4*)&g_ctxP[base + (long long)f * DHEAD + tx * 8] =
            make_float4(acc[i][0], acc[i][1], acc[i][2], acc[i][3]);
        *(float4*)&g_ctxP[base + (long long)f * DHEAD + tx * 8 + 4] =
            make_float4(acc[i][4], acc[i][5], acc[i][6], acc[i][7]);
    }
    g_ksumP[(z * NCHUNK + ch) * NF + tid] = ks_acc;
}

__global__ void ctx_reduce() {
    int idx = blockIdx.x * 256 + threadIdx.x;
    int z = idx >> 14, fd = idx & 16383;
    float s = 0.f;
#pragma unroll
    for (int c = 0; c < NCHUNK; c++)
        s += g_ctxP[((long long)(z * NCHUNK + c)) * 16384 + fd];
    g_ctx[(long long)z * 16384 + fd] = s;
}

__global__ void ksum_reduce() {
    int z = blockIdx.x, f = threadIdx.x;
    float s = 0.f;
#pragma unroll
    for (int c = 0; c < NCHUNK; c++) s += g_ksumP[(z * NCHUNK + c) * NF + f];
    g_ksum[z * NF + f] = s;
}

// ---------------- fused Q features + attention --------------------------------
// phase1: dd = (Qh+Ql)@(DN*projT hi/lo) via mma -> qp smem
// then rowmax/exp/dinv, phase2 qp@ctx fp32.
#define QPP 260
#define FA_QP    0
#define FA_QH    133120
#define FA_QL    (FA_QH + 18432)
#define FA_PBH   (FA_QL + 18432)
#define FA_PBL   (FA_PBH + 8448)
#define FA_CS    (FA_PBL + 8448)
#define FA_KS    (FA_CS + 4352)
#define FA_RSUB  (FA_KS + 1024)
#define FA_DINV  (FA_RSUB + 512)
#define FA_RED   (FA_DINV + 512)
#define SMEM_ATTN (FA_RED + 2048)

__global__ __launch_bounds__(512, 1) void fused_attn_kernel() {
    extern __shared__ char smemc[];
    float* qp     = (float*)(smemc + FA_QP);
    __nv_bfloat16* qh = (__nv_bfloat16*)(smemc + FA_QH);   // [128][72]
    __nv_bfloat16* ql = (__nv_bfloat16*)(smemc + FA_QL);
    __nv_bfloat16* pbh = (__nv_bfloat16*)(smemc + FA_PBH); // [16][264]
    __nv_bfloat16* pbl = (__nv_bfloat16*)(smemc + FA_PBL);
    float* cs     = (float*)(smemc + FA_CS);
    float* ks     = (float*)(smemc + FA_KS);
    float* rowsub = (float*)(smemc + FA_RSUB);
    float* sdinv  = (float*)(smemc + FA_DINV);
    float* red    = (float*)(smemc + FA_RED);

    int z = blockIdx.y;
    int b = z >> 3, hd = z & 7;
    long long m0 = (long long)blockIdx.x * 128;
    int tid = threadIdx.x;

    // load Q hi/lo tiles [128 rows x 64]
    long long Aq = ((long long)b * NSEQ + m0) * 1024 + hd * 64;
#pragma unroll
    for (int i = 0; i < 2; i++) {
        int idx = tid + i * 512;
        int row = idx >> 3, ch = idx & 7;
        *(uint4*)(qh + row * 72 + ch * 8) = *(const uint4*)(g_QKh + Aq + (long long)row * 1024 + ch * 8);
        *(uint4*)(ql + row * 72 + ch * 8) = *(const uint4*)(g_QKl + Aq + (long long)row * 1024 + ch * 8);
    }
    if (tid < 256) ks[tid] = g_ksum[z * NF + tid];
    if (tid < 128) rowsub[tid] = g_rssq[(long long)z * NSEQ + m0 + tid];
    __syncthreads();

    // phase1 mma: 16 warps 4m x 4n, warp tile 32x64
    {
        int lane = tid & 31, wid = tid >> 5;
        int wm = wid & 3, wn = wid >> 2;
        int lrow = (lane & 7) + ((lane >> 3) & 1) * 8;
        int lcol8 = (lane >> 4) * 8;
        uint32_t qhB = smem_u32(qh), qlB = smem_u32(ql);
        uint32_t pbhB = smem_u32(pbh), pblB = smem_u32(pbl);

        float acc[2][8][4];
#pragma unroll
        for (int i = 0; i < 2; i++)
#pragma unroll
            for (int j = 0; j < 8; j++)
#pragma unroll
                for (int r = 0; r < 4; r++) acc[i][j][r] = 0.f;

        for (int c0 = 0; c0 < 64; c0 += 16) {
            __syncthreads();
            {
                int row = tid >> 5, c16 = tid & 31;
                *(uint4*)(pbh + row * 264 + c16 * 8) = *(const uint4*)(g_Ph + (c0 + row) * NF + c16 * 8);
                *(uint4*)(pbl + row * 264 + c16 * 8) = *(const uint4*)(g_Pl + (c0 + row) * NF + c16 * 8);
            }
            __syncthreads();
            uint32_t ah[2][4], al[2][4];
#pragma unroll
            for (int i = 0; i < 2; i++) {
                int r = wm * 32 + i * 16 + lrow;
                uint32_t off = (uint32_t)r * 144 + (c0 + lcol8) * 2;
                ldsm_x4(ah[i], qhB + off);
                ldsm_x4(al[i], qlB + off);
            }
#pragma unroll
            for (int jj = 0; jj < 4; jj++) {
                uint32_t offb = (uint32_t)lrow * 528 + (wn * 64 + jj * 16 + lcol8) * 2;
                uint32_t th[4], tl[4];
                ldsm_x4_t(th, pbhB + offb);
                ldsm_x4_t(tl, pblB + offb);
#pragma unroll
                for (int i = 0; i < 2; i++) {
                    mma_bf16(acc[i][jj * 2],     ah[i], th[0], th[1]);
                    mma_bf16(acc[i][jj * 2],     ah[i], tl[0], tl[1]);
                    mma_bf16(acc[i][jj * 2],     al[i], th[0], th[1]);
                    mma_bf16(acc[i][jj * 2 + 1], ah[i], th[2], th[3]);
                    mma_bf16(acc[i][jj * 2 + 1], ah[i], tl[2], tl[3]);
                    mma_bf16(acc[i][jj * 2 + 1], al[i], th[2], th[3]);
                }
            }
        }
        __syncthreads();
        int g = lane >> 2, c2 = (lane & 3) * 2;
#pragma unroll
        for (int i = 0; i < 2; i++) {
            int r0 = wm * 32 + i * 16 + g, r1 = r0 + 8;
#pragma unroll
            for (int j = 0; j < 8; j++) {
                int col = wn * 64 + j * 8 + c2;
                qp[r0 * QPP + col]     = acc[i][j][0];
                qp[r0 * QPP + col + 1] = acc[i][j][1];
                qp[r1 * QPP + col]     = acc[i][j][2];
                qp[r1 * QPP + col + 1] = acc[i][j][3];
            }
        }
    }
    __syncthreads();

    // row max (raw dd), rowsub = diag + max
    {
        int r = tid >> 2, p = tid & 3;
        float mx = __int_as_float(0xff800000);
        for (int f = p * 64; f < p * 64 + 64; f++) mx = fmaxf(mx, qp[r * QPP + f]);
        red[r * 4 + p] = mx;
    }
    __syncthreads();
    if (tid < 128) {
        float m = fmaxf(fmaxf(red[tid * 4], red[tid * 4 + 1]), fmaxf(red[tid * 4 + 2], red[tid * 4 + 3]));
        rowsub[tid] += m;
    }
    __syncthreads();

#pragma unroll
    for (int i = 0; i < 64; i++) {
        int idx = i * 512 + tid;
        int r = idx >> 8, f = idx & 255;
        float v = qp[r * QPP + f];
        qp[r * QPP + f] = 0.0625f * (__expf(v - rowsub[r]) + 1e-4f);
    }
    __syncthreads();

    {
        int r = tid >> 2, p = tid & 3;
        float s = 0.f;
        for (int f = p * 64; f < p * 64 + 64; f++) s += qp[r * QPP + f] * ks[f];
        red[r * 4 + p] = s;
    }
    __syncthreads();
    if (tid < 128)
        sdinv[tid] = 1.0f / (red[tid * 4] + red[tid * 4 + 1] + red[tid * 4 + 2] + red[tid * 4 + 3]);

    int tx2 = tid & 15, ty2 = tid >> 4;
    float acc2[4][4];
#pragma unroll
    for (int i = 0; i < 4; i++)
#pragma unroll
        for (int j = 0; j < 4; j++) acc2[i][j] = 0.f;

    const float* ctxp = g_ctx + (long long)z * NF * DHEAD;
    for (int f0 = 0; f0 < NF; f0 += 16) {
        __syncthreads();
        if (tid < 256) {
            int k = tid >> 4, nq = tid & 15;
            *(float4*)&cs[k * 68 + nq * 4] = *(const float4*)&ctxp[(long long)(f0 + k) * DHEAD + nq * 4];
        }
        __syncthreads();
#pragma unroll
        for (int k = 0; k < 16; k++) {
            float a0 = qp[(ty2 * 4 + 0) * QPP + f0 + k];
            float a1 = qp[(ty2 * 4 + 1) * QPP + f0 + k];
            float a2 = qp[(ty2 * 4 + 2) * QPP + f0 + k];
            float a3 = qp[(ty2 * 4 + 3) * QPP + f0 + k];
            float4 b4 = *(const float4*)&cs[k * 68 + tx2 * 4];
            float bv[4] = {b4.x, b4.y, b4.z, b4.w};
            float av[4] = {a0, a1, a2, a3};
#pragma unroll
            for (int i = 0; i < 4; i++)
#pragma unroll
                for (int j = 0; j < 4; j++) acc2[i][j] += av[i] * bv[j];
        }
    }

#pragma unroll
    for (int i = 0; i < 4; i++) {
        int m = ty2 * 4 + i;
        float s = sdinv[m];
        long long base = ((long long)b * NSEQ + m0 + m) * INNERD + hd * DHEAD + tx2 * 4;
        float vv[4] = {acc2[i][0] * s, acc2[i][1] * s, acc2[i][2] * s, acc2[i][3] * s};
        __nv_bfloat16 h[4], l[4];
#pragma unroll
        for (int j = 0; j < 4; j++) {
            h[j] = __float2bfloat16(vv[j]);
            l[j] = __float2bfloat16(vv[j] - __bfloat162float(h[j]));
        }
        *(__nv_bfloat162*)&g_ATTh[base]     = __nv_bfloat162(h[0], h[1]);
        *(__nv_bfloat162*)&g_ATTh[base + 2] = __nv_bfloat162(h[2], h[3]);
        *(__nv_bfloat162*)&g_ATTl[base]     = __nv_bfloat162(l[0], l[1]);
        *(__nv_bfloat162*)&g_ATTl[base + 2] = __nv_bfloat162(l[2], l[3]);
    }
}

// ---------------- launcher ----------------------------------------------------
extern "C" void kernel_launch(void* const* d_in, const int* in_sizes, int n_in,
                              void* d_out, int out_size) {
    const float* x    = (const float*)d_in[0];
    const float* Wq   = (const float*)d_in[1];
    const float* Wk   = (const float*)d_in[2];
    const float* Wv   = (const float*)d_in[3];
    const float* Wo   = (const float*)d_in[4];
    const float* bo   = (const float*)d_in[5];
    const float* proj = (const float*)d_in[6];
    const float* Wp   = (const float*)d_in[7];
    const float* bp   = (const float*)d_in[8];
    const float* btab = (const float*)d_in[9];
    float* out = (float*)d_out;

    static bool attr_set = false;
    if (!attr_set) {
        cudaFuncSetAttribute(fused_attn_kernel, cudaFuncAttributeMaxDynamicSharedMemorySize, SMEM_ATTN);
        cudaFuncSetAttribute(mma_gemm<0>, cudaFuncAttributeMaxDynamicSharedMemorySize, SMEM_MMA);
        cudaFuncSetAttribute(mma_gemm<2>, cudaFuncAttributeMaxDynamicSharedMemorySize, SMEM_MMA);
        cudaFuncSetAttribute(ddk_mma, cudaFuncAttributeMaxDynamicSharedMemorySize, SMEM_MMA);
        attr_set = true;
    }

    float *pQKV, *pWoWp, *pB2, *pCS;
    __nv_bfloat16 *pXh, *pXl, *pWch, *pWcl, *pATTh, *pATTl, *pWoWph, *pWoWpl;
    cudaGetSymbolAddress((void**)&pQKV,   g_QKV);
    cudaGetSymbolAddress((void**)&pWoWp,  g_WoWp);
    cudaGetSymbolAddress((void**)&pB2,    g_bias2);
    cudaGetSymbolAddress((void**)&pCS,    g_colsum);
    cudaGetSymbolAddress((void**)&pXh,    g_Xh);
    cudaGetSymbolAddress((void**)&pXl,    g_Xl);
    cudaGetSymbolAddress((void**)&pWch,   g_Wch);
    cudaGetSymbolAddress((void**)&pWcl,   g_Wcl);
    cudaGetSymbolAddress((void**)&pATTh,  g_ATTh);
    cudaGetSymbolAddress((void**)&pATTl,  g_ATTl);
    cudaGetSymbolAddress((void**)&pWoWph, g_WoWph);
    cudaGetSymbolAddress((void**)&pWoWpl, g_WoWpl);

    init_kernel<<<1, 32>>>();
    transpose_proj_split<<<64, 256>>>(proj);
    bias2_kernel<<<1, 256>>>(bo, Wp, bp);
    split_x_kernel<<<TOK * CDIM / 1024, 256>>>(x);
    pack_w_kernel<<<CDIM * QKVLD / 256, 256>>>(Wq, Wk, Wv);

    // WoWp = Wo @ Wp (fp32), then split
    sgemm128<<<dim3(CDIM / 128, INNERD / 128), 256>>>(Wo, Wp, pWoWp, CDIM, CDIM, CDIM, CDIM);
    split_wowp_kernel<<<INNERD * CDIM / 256, 256>>>();

    // QKV fused tensor GEMM: [65536,256] @ [256,1536]
    mma_gemm<0><<<dim3(QKVLD / 128, TOK / 128), 256, SMEM_MMA>>>(
        pXh, pXl, pWch, pWcl, pQKV, CDIM, CDIM, QKVLD, QKVLD,
        nullptr, nullptr, nullptr);

    // split Q|K into bf16 hi/lo + diag sums
    split_qk_kernel<<<TOK, 256>>>();

    // K feature pass on tensor cores
    ddk_mma<<<dim3(NF / 128, NSEQ / 128, NZ), 256, SMEM_MMA>>>();

    ctx_part_kernel<<<dim3(NCHUNK, NZ), 256>>>();
    ctx_reduce<<<(NZ * NF * DHEAD) / 256, 256>>>();
    ksum_reduce<<<NZ, 256>>>();
    fused_attn_kernel<<<dim3(NSEQ / 128, NZ), 512, SMEM_ATTN>>>();

    // out = ATT @ WoWp + bias2 + rel*colsum  (tensor GEMM)
    mma_gemm<2><<<dim3(CDIM / 128, TOK / 128), 256, SMEM_MMA>>>(
        pATTh, pATTl, pWoWph, pWoWpl, out, INNERD, INNERD, CDIM, CDIM,
        pB2, btab, pCS);

    (void)in_sizes; (void)n_in; (void)out_size;
}

// round 15
// speedup vs baseline: 2.2670x; 1.0785x over previous
#include <cuda_runtime.h>
#include <cuda_bf16.h>
#include <math.h>
#include <stdint.h>

#define TOK    65536
#define NSEQ   16384
#define CDIM   256
#define INNERD 512
#define QKVLD  1536
#define NHEAD  8
#define DHEAD  64
#define NF     256
#define NZ     32
#define NCHUNK 16
#define CHROWS (NSEQ / NCHUNK)   // 1024

// ---------------- scratch (static device globals) ----------------------------
__device__ float g_QKV[(long long)TOK * QKVLD];          // Q|K|V fp32
__device__ __nv_bfloat16 g_KPh[(long long)NZ * NSEQ * NF]; // E hi
__device__ __nv_bfloat16 g_KPl[(long long)NZ * NSEQ * NF]; // E lo
__device__ __nv_bfloat16 g_Xh[(long long)TOK * CDIM];
__device__ __nv_bfloat16 g_Xl[(long long)TOK * CDIM];
__device__ __nv_bfloat16 g_Wch[CDIM * QKVLD];
__device__ __nv_bfloat16 g_Wcl[CDIM * QKVLD];
__device__ __nv_bfloat16 g_ATTh[(long long)TOK * INNERD];
__device__ __nv_bfloat16 g_ATTl[(long long)TOK * INNERD];
__device__ __nv_bfloat16 g_WoWph[INNERD * CDIM];
__device__ __nv_bfloat16 g_WoWpl[INNERD * CDIM];
__device__ __nv_bfloat16 g_QKh[(long long)TOK * 1024];
__device__ __nv_bfloat16 g_QKl[(long long)TOK * 1024];
__device__ __nv_bfloat16 g_VTh[(long long)4 * 512 * NSEQ]; // V^T per batch
__device__ __nv_bfloat16 g_VTl[(long long)4 * 512 * NSEQ];
__device__ __nv_bfloat16 g_Ph[DHEAD * NF];
__device__ __nv_bfloat16 g_Pl[DHEAD * NF];
__device__ float g_rssq[(long long)NZ * NSEQ];
__device__ float g_rssk[(long long)NZ * NSEQ];
__device__ float g_kmax[NZ];
__device__ float g_ctxP[(long long)NZ * NCHUNK * NF * DHEAD]; // partials [d][f]
__device__ float g_ctx[NZ * NF * DHEAD];                      // final [f][d]
__device__ float g_ksumP[NZ * NCHUNK * NF];
__device__ float g_ksum[NZ * NF];
__device__ float g_vsumP[1024 * 2048];                        // deterministic vsum partials
__device__ float g_vsum[4 * 512];
__device__ float g_WoWp[INNERD * CDIM];
__device__ float g_bias2[CDIM];
__device__ float g_colsum[CDIM];

// ---------------- ptx helpers -------------------------------------------------
__device__ __forceinline__ uint32_t smem_u32(const void* p) {
    uint32_t a;
    asm("{ .reg .u64 t; cvta.to.shared.u64 t, %1; cvt.u32.u64 %0, t; }" : "=r"(a) : "l"(p));
    return a;
}
#define CP_ASYNC16(dst, src) \
    asm volatile("cp.async.cg.shared.global [%0], [%1], 16;\n" :: "r"(dst), "l"(src))
#define CP_COMMIT() asm volatile("cp.async.commit_group;\n")
#define CP_WAIT1()  asm volatile("cp.async.wait_group 1;\n")
#define CP_WAIT0()  asm volatile("cp.async.wait_group 0;\n")

__device__ __forceinline__ void ldsm_x4(uint32_t (&r)[4], uint32_t a) {
    asm volatile("ldmatrix.sync.aligned.m8n8.x4.shared.b16 {%0,%1,%2,%3}, [%4];"
                 : "=r"(r[0]), "=r"(r[1]), "=r"(r[2]), "=r"(r[3]) : "r"(a));
}
__device__ __forceinline__ void ldsm_x4_t(uint32_t (&r)[4], uint32_t a) {
    asm volatile("ldmatrix.sync.aligned.m8n8.x4.trans.shared.b16 {%0,%1,%2,%3}, [%4];"
                 : "=r"(r[0]), "=r"(r[1]), "=r"(r[2]), "=r"(r[3]) : "r"(a));
}
__device__ __forceinline__ void mma_bf16(float (&d)[4], const uint32_t (&a)[4],
                                         uint32_t b0, uint32_t b1) {
    asm volatile("mma.sync.aligned.m16n8k16.row.col.f32.bf16.bf16.f32 "
                 "{%0,%1,%2,%3},{%4,%5,%6,%7},{%8,%9},{%0,%1,%2,%3};"
                 : "+f"(d[0]), "+f"(d[1]), "+f"(d[2]), "+f"(d[3])
                 : "r"(a[0]), "r"(a[1]), "r"(a[2]), "r"(a[3]), "r"(b0), "r"(b1));
}

__device__ __forceinline__ void atomicMaxFloat(float* addr, float val) {
    if (val >= 0.f) atomicMax((int*)addr, __float_as_int(val));
    else            atomicMin((unsigned int*)addr, (unsigned int)__float_as_int(val));
}

// ---------------- small prep kernels ------------------------------------------
__global__ void init_kernel() {
    int t = threadIdx.x;
    if (t < NZ) g_kmax[t] = __int_as_float(0xff800000);
}

__global__ void transpose_proj_split(const float* __restrict__ proj) {
    int t = blockIdx.x * 256 + threadIdx.x;
    int d = t >> 8, f = t & 255;
    const float DN = 0.35355339059327373f;
    float v = proj[f * DHEAD + d] * DN;
    __nv_bfloat16 h = __float2bfloat16(v);
    g_Ph[d * NF + f] = h;
    g_Pl[d * NF + f] = __float2bfloat16(v - __bfloat162float(h));
}

__global__ void bias2_kernel(const float* __restrict__ bo,
                             const float* __restrict__ Wp,
                             const float* __restrict__ bp) {
    int n = threadIdx.x;
    float s = 0.f, cs = 0.f;
    for (int c = 0; c < CDIM; c++) {
        float w = Wp[c * CDIM + n];
        s += bo[c] * w;
        cs += w;
    }
    g_bias2[n] = s + bp[n];
    g_colsum[n] = cs;
}

__global__ void split_x_kernel(const float* __restrict__ x) {
    long long i = (long long)blockIdx.x * 256 + threadIdx.x;
    float4 v = *(const float4*)&x[i * 4];
    float vv[4] = {v.x, v.y, v.z, v.w};
#pragma unroll
    for (int j = 0; j < 4; j++) {
        __nv_bfloat16 h = __float2bfloat16(vv[j]);
        g_Xh[i * 4 + j] = h;
        g_Xl[i * 4 + j] = __float2bfloat16(vv[j] - __bfloat162float(h));
    }
}

__global__ void pack_w_kernel(const float* __restrict__ Wq,
                              const float* __restrict__ Wk,
                              const float* __restrict__ Wv) {
    int i = blockIdx.x * 256 + threadIdx.x;
    int c = i / QKVLD, n = i % QKVLD;
    float v = (n < 512) ? Wq[c * 512 + n]
            : (n < 1024) ? Wk[c * 512 + n - 512]
                         : Wv[c * 512 + n - 1024];
    __nv_bfloat16 h = __float2bfloat16(v);
    g_Wch[i] = h;
    g_Wcl[i] = __float2bfloat16(v - __bfloat162float(h));
}

__global__ void split_wowp_kernel() {
    int i = blockIdx.x * 256 + threadIdx.x;
    float v = g_WoWp[i];
    __nv_bfloat16 h = __float2bfloat16(v);
    g_WoWph[i] = h;
    g_WoWpl[i] = __float2bfloat16(v - __bfloat162float(h));
}

// split Q|K + per-(token,head) diag sums
__global__ __launch_bounds__(256) void split_qk_kernel() {
    long long tok = blockIdx.x;
    int t = threadIdx.x;
    const float* src = g_QKV + tok * QKVLD;
    float4 v = *(const float4*)&src[t * 4];
    float vv[4] = {v.x, v.y, v.z, v.w};
    __nv_bfloat16 h[4], l[4];
#pragma unroll
    for (int j = 0; j < 4; j++) {
        h[j] = __float2bfloat16(vv[j]);
        l[j] = __float2bfloat16(vv[j] - __bfloat162float(h[j]));
    }
    long long o = tok * 1024 + t * 4;
    *(__nv_bfloat162*)&g_QKh[o]     = __nv_bfloat162(h[0], h[1]);
    *(__nv_bfloat162*)&g_QKh[o + 2] = __nv_bfloat162(h[2], h[3]);
    *(__nv_bfloat162*)&g_QKl[o]     = __nv_bfloat162(l[0], l[1]);
    *(__nv_bfloat162*)&g_QKl[o + 2] = __nv_bfloat162(l[2], l[3]);

    float s = vv[0]*vv[0] + vv[1]*vv[1] + vv[2]*vv[2] + vv[3]*vv[3];
#pragma unroll
    for (int off = 8; off > 0; off >>= 1)
        s += __shfl_down_sync(0xffffffff, s, off, 16);
    if ((t & 15) == 0) {
        int head = t >> 4;
        int b = (int)(tok >> 14), nloc = (int)(tok & (NSEQ - 1));
        int z = b * 8 + (head & 7);
        float r = 0.0625f * s;
        if (head < 8) g_rssq[(long long)z * NSEQ + nloc] = r;
        else          g_rssk[(long long)z * NSEQ + nloc] = r;
    }
}

// transpose V -> VT bf16 hi/lo + deterministic column-sum partials
// grid (NSEQ/64, 512/64, 4), 256 thr
__global__ __launch_bounds__(256) void vt_kernel() {
    __shared__ float Vs[64 * 65];
    int n0 = blockIdx.x * 64, c0 = blockIdx.y * 64, b = blockIdx.z;
    int t = threadIdx.x;
#pragma unroll
    for (int i = 0; i < 4; i++) {
        int idx = t + i * 256;
        int r = idx >> 4, cq = idx & 15;
        float4 v = *(const float4*)&g_QKV[((long long)(b * NSEQ + n0 + r)) * QKVLD + 1024 + c0 + cq * 4];
        Vs[r * 65 + cq * 4 + 0] = v.x; Vs[r * 65 + cq * 4 + 1] = v.y;
        Vs[r * 65 + cq * 4 + 2] = v.z; Vs[r * 65 + cq * 4 + 3] = v.w;
    }
    __syncthreads();
#pragma unroll
    for (int i = 0; i < 8; i++) {
        int idx = t + i * 256;
        int c = idx >> 5, nq = idx & 31;
        float v0 = Vs[(nq * 2) * 65 + c], v1 = Vs[(nq * 2 + 1) * 65 + c];
        __nv_bfloat16 h0 = __float2bfloat16(v0), h1 = __float2bfloat16(v1);
        __nv_bfloat16 l0 = __float2bfloat16(v0 - __bfloat162float(h0));
        __nv_bfloat16 l1 = __float2bfloat16(v1 - __bfloat162float(h1));
        long long o = ((long long)(b * 512 + c0 + c)) * NSEQ + n0 + nq * 2;
        *(__nv_bfloat162*)&g_VTh[o] = __nv_bfloat162(h0, h1);
        *(__nv_bfloat162*)&g_VTl[o] = __nv_bfloat162(l0, l1);
    }
    // vsum partials: 4 threads per column
    int p = t >> 6, c = t & 63;
    float s = 0.f;
    for (int n = p * 16; n < p * 16 + 16; n++) s += Vs[n * 65 + c];
    g_vsumP[(long long)(blockIdx.x * 4 + p) * 2048 + b * 512 + c0 + c] = s;
}

__global__ void vsum_reduce() {
    int col = blockIdx.x * 256 + threadIdx.x;   // 2048
    float s = 0.f;
    for (int k = 0; k < 1024; k++) s += g_vsumP[(long long)k * 2048 + col];
    g_vsum[col] = s;
}

// ---------------- fp32 sgemm128 (WoWp product only) ---------------------------
__global__ __launch_bounds__(256, 2) void sgemm128(
    const float* __restrict__ A, const float* __restrict__ B, float* __restrict__ C,
    int lda, int ldb, int ldc, int K)
{
    __shared__ float As[2][16][132];
    __shared__ float Bs[2][16][128];
    int tid = threadIdx.x;
    int tx = tid & 15, ty = tid >> 4;
    long long m0 = (long long)blockIdx.y * 128;
    int n0 = blockIdx.x * 128;
    const float* Ab = A + m0 * lda;
    const float* Bb = B + n0;

#pragma unroll
    for (int i = 0; i < 2; i++) {
        int idx = tid + i * 256;
        int m = idx >> 2, kq = idx & 3;
        float4 v = *(const float4*)&Ab[(long long)m * lda + kq * 4];
        As[0][kq * 4 + 0][m] = v.x; As[0][kq * 4 + 1][m] = v.y;
        As[0][kq * 4 + 2][m] = v.z; As[0][kq * 4 + 3][m] = v.w;
    }
#pragma unroll
    for (int i = 0; i < 2; i++) {
        int idx = tid + i * 256;
        int k = idx >> 5, nq = idx & 31;
        *(float4*)&Bs[0][k][nq * 4] = *(const float4*)&Bb[(long long)k * ldb + nq * 4];
    }
    __syncthreads();

    float acc[8][8];
#pragma unroll
    for (int i = 0; i < 8; i++)
#pragma unroll
        for (int j = 0; j < 8; j++) acc[i][j] = 0.f;

    int nk = K >> 4, buf = 0;
    for (int it = 0; it < nk; ++it) {
        float4 pa[2], pbv[2];
        bool nxt = (it + 1 < nk);
        if (nxt) {
            int k0 = (it + 1) << 4;
#pragma unroll
            for (int i = 0; i < 2; i++) {
                int idx = tid + i * 256;
                int m = idx >> 2, kq = idx & 3;
                pa[i] = *(const float4*)&Ab[(long long)m * lda + k0 + kq * 4];
            }
#pragma unroll
            for (int i = 0; i < 2; i++) {
                int idx = tid + i * 256;
                int k = idx >> 5, nq = idx & 31;
                pbv[i] = *(const float4*)&Bb[(long long)(k0 + k) * ldb + nq * 4];
            }
        }
#pragma unroll
        for (int k = 0; k < 16; k++) {
            float4 a0 = *(const float4*)&As[buf][k][ty * 4];
            float4 a1 = *(const float4*)&As[buf][k][ty * 4 + 64];
            float4 b0 = *(const float4*)&Bs[buf][k][tx * 4];
            float4 b1 = *(const float4*)&Bs[buf][k][tx * 4 + 64];
            float av[8] = {a0.x, a0.y, a0.z, a0.w, a1.x, a1.y, a1.z, a1.w};
            float bv[8] = {b0.x, b0.y, b0.z, b0.w, b1.x, b1.y, b1.z, b1.w};
#pragma unroll
            for (int i = 0; i < 8; i++)
#pragma unroll
                for (int j = 0; j < 8; j++) acc[i][j] += av[i] * bv[j];
        }
        if (nxt) {
            int nb = buf ^ 1;
#pragma unroll
            for (int i = 0; i < 2; i++) {
                int idx = tid + i * 256;
                int m = idx >> 2, kq = idx & 3;
                As[nb][kq * 4 + 0][m] = pa[i].x; As[nb][kq * 4 + 1][m] = pa[i].y;
                As[nb][kq * 4 + 2][m] = pa[i].z; As[nb][kq * 4 + 3][m] = pa[i].w;
            }
#pragma unroll
            for (int i = 0; i < 2; i++) {
                int idx = tid + i * 256;
                int k = idx >> 5, nq = idx & 31;
                *(float4*)&Bs[nb][k][nq * 4] = pbv[i];
            }
            __syncthreads();
            buf = nb;
        }
    }
#pragma unroll
    for (int i = 0; i < 8; i++) {
        long long gm = m0 + (i < 4 ? ty * 4 + i : 64 + ty * 4 + (i - 4));
        *(float4*)&C[gm * ldc + n0 + tx * 4] =
            make_float4(acc[i][0], acc[i][1], acc[i][2], acc[i][3]);
        *(float4*)&C[gm * ldc + n0 + tx * 4 + 64] =
            make_float4(acc[i][4], acc[i][5], acc[i][6], acc[i][7]);
    }
}

// ---------------- bf16-split tensor-core GEMM ---------------------------------
#define SOFF_AL 10240
#define SOFF_BH 20480
#define SOFF_BL 29184
#define STAGE_B 37888
#define SMEM_MMA (2 * STAGE_B)

template <int EPI>
__global__ __launch_bounds__(256) void mma_gemm(
    const __nv_bfloat16* __restrict__ Ah, const __nv_bfloat16* __restrict__ Al,
    const __nv_bfloat16* __restrict__ Bh, const __nv_bfloat16* __restrict__ Bl,
    float* __restrict__ C, int K, int lda, int ldb, int ldc,
    const float* __restrict__ bias, const float* __restrict__ btab,
    const float* __restrict__ colsum)
{
    extern __shared__ char smem[];
    uint32_t sbase = smem_u32(smem);

    int tid = threadIdx.x;
    int lane = tid & 31, wid = tid >> 5;
    int wm = wid & 1, wn = wid >> 1;
    long long m0 = (long long)blockIdx.y * 128;
    int n0 = blockIdx.x * 128;

    const __nv_bfloat16* Ahb = Ah + m0 * lda;
    const __nv_bfloat16* Alb = Al + m0 * lda;
    const __nv_bfloat16* Bhb = Bh + n0;
    const __nv_bfloat16* Blb = Bl + n0;

    int nk = K >> 5;

    int ar0 = tid >> 2, ac0 = tid & 3;
    int ar1 = (tid + 256) >> 2, ac1 = tid & 3;
    int br0 = tid >> 4, bc0 = tid & 15;
    int br1 = (tid + 256) >> 4, bc1 = tid & 15;

#define LOAD_STAGE(kt, s)                                                          \
    {                                                                              \
        uint32_t sb = sbase + (s) * STAGE_B;                                       \
        long long ka = (long long)(kt) * 32;                                       \
        CP_ASYNC16(sb + ar0 * 80 + ac0 * 16, Ahb + ar0 * lda + ka + ac0 * 8);      \
        CP_ASYNC16(sb + ar1 * 80 + ac1 * 16, Ahb + ar1 * lda + ka + ac1 * 8);      \
        CP_ASYNC16(sb + SOFF_AL + ar0 * 80 + ac0 * 16, Alb + ar0 * lda + ka + ac0 * 8); \
        CP_ASYNC16(sb + SOFF_AL + ar1 * 80 + ac1 * 16, Alb + ar1 * lda + ka + ac1 * 8); \
        CP_ASYNC16(sb + SOFF_BH + br0 * 272 + bc0 * 16, Bhb + (ka + br0) * ldb + bc0 * 8); \
        CP_ASYNC16(sb + SOFF_BH + br1 * 272 + bc1 * 16, Bhb + (ka + br1) * ldb + bc1 * 8); \
        CP_ASYNC16(sb + SOFF_BL + br0 * 272 + bc0 * 16, Blb + (ka + br0) * ldb + bc0 * 8); \
        CP_ASYNC16(sb + SOFF_BL + br1 * 272 + bc1 * 16, Blb + (ka + br1) * ldb + bc1 * 8); \
        CP_COMMIT();                                                               \
    }

    LOAD_STAGE(0, 0);
    LOAD_STAGE(1, 1);

    float acc[4][4][4];
#pragma unroll
    for (int i = 0; i < 4; i++)
#pragma unroll
        for (int j = 0; j < 4; j++)
#pragma unroll
            for (int r = 0; r < 4; r++) acc[i][j][r] = 0.f;

    int lrow = (lane & 7) + ((lane >> 3) & 1) * 8;
    int lcol8 = (lane >> 4) * 8;

    for (int it = 0; it < nk; ++it) {
        if (it < nk - 1) { CP_WAIT1(); } else { CP_WAIT0(); }
        __syncthreads();
        uint32_t sb = sbase + (it & 1) * STAGE_B;
        uint32_t aAh = sb, aAl = sb + SOFF_AL, aBh = sb + SOFF_BH, aBl = sb + SOFF_BL;

#pragma unroll
        for (int ks = 0; ks < 2; ks++) {
            uint32_t ah[4][4], al[4][4];
            uint32_t bh[4][2], bl[4][2];
#pragma unroll
            for (int i = 0; i < 4; i++) {
                int r = wm * 64 + i * 16 + lrow;
                uint32_t off = (uint32_t)r * 80 + (ks * 16 + lcol8) * 2;
                ldsm_x4(ah[i], aAh + off);
                ldsm_x4(al[i], aAl + off);
            }
#pragma unroll
            for (int jj = 0; jj < 2; jj++) {
                int kr = ks * 16 + lrow;
                uint32_t off = (uint32_t)kr * 272 + (wn * 32 + jj * 16 + lcol8) * 2;
                uint32_t t[4];
                ldsm_x4_t(t, aBh + off);
                bh[jj * 2][0] = t[0]; bh[jj * 2][1] = t[1];
                bh[jj * 2 + 1][0] = t[2]; bh[jj * 2 + 1][1] = t[3];
                ldsm_x4_t(t, aBl + off);
                bl[jj * 2][0] = t[0]; bl[jj * 2][1] = t[1];
                bl[jj * 2 + 1][0] = t[2]; bl[jj * 2 + 1][1] = t[3];
            }
#pragma unroll
            for (int i = 0; i < 4; i++)
#pragma unroll
                for (int j = 0; j < 4; j++) {
                    mma_bf16(acc[i][j], ah[i], bh[j][0], bh[j][1]);
                    mma_bf16(acc[i][j], ah[i], bl[j][0], bl[j][1]);
                    mma_bf16(acc[i][j], al[i], bh[j][0], bh[j][1]);
                }
        }
        __syncthreads();
        if (it + 2 < nk) LOAD_STAGE(it + 2, it & 1);
    }

    int g = lane >> 2, c2 = (lane & 3) * 2;
#pragma unroll
    for (int i = 0; i < 4; i++) {
        long long row0 = m0 + wm * 64 + i * 16 + g;
        long long row1 = row0 + 8;
        float t0 = 0.f, t1 = 0.f;
        if (EPI == 2) {
            int hh = ((int)row0 >> 7) & 127, ww = (int)row0 & 127;
            int rel = hh - ww; rel = rel < -7 ? -7 : (rel > 7 ? 7 : rel);
            t0 = btab[rel + 7];
            hh = ((int)row1 >> 7) & 127; ww = (int)row1 & 127;
            rel = hh - ww; rel = rel < -7 ? -7 : (rel > 7 ? 7 : rel);
            t1 = btab[rel + 7];
        }
#pragma unroll
        for (int j = 0; j < 4; j++) {
            int col = n0 + wn * 32 + j * 8 + c2;
            float b0 = 0.f, b1 = 0.f, cs0 = 0.f, cs1 = 0.f;
            if (EPI == 2) {
                b0 = bias[col]; b1 = bias[col + 1];
                cs0 = colsum[col]; cs1 = colsum[col + 1];
            }
            float2 v0, v1;
            v0.x = acc[i][j][0] + b0 + t0 * cs0;
            v0.y = acc[i][j][1] + b1 + t0 * cs1;
            v1.x = acc[i][j][2] + b0 + t1 * cs0;
            v1.y = acc[i][j][3] + b1 + t1 * cs1;
            *(float2*)&C[row0 * ldc + col] = v0;
            *(float2*)&C[row1 * ldc + col] = v1;
        }
    }
}

// ---------------- K feature pass: dd mma -> exp -> E bf16 hi/lo ---------------
__global__ __launch_bounds__(256) void ddk_mma() {
    extern __shared__ char smem[];
    __shared__ float redm[8];
    uint32_t sbase = smem_u32(smem);

    int tid = threadIdx.x;
    int lane = tid & 31, wid = tid >> 5;
    int wm = wid & 1, wn = wid >> 1;
    int z = blockIdx.z, b = z >> 3, hd = z & 7;
    long long m0 = (long long)blockIdx.y * 128;
    int n0 = blockIdx.x * 128;

    const __nv_bfloat16* Ahb = g_QKh + ((long long)b * NSEQ + m0) * 1024 + 512 + hd * 64;
    const __nv_bfloat16* Alb = g_QKl + ((long long)b * NSEQ + m0) * 1024 + 512 + hd * 64;
    const __nv_bfloat16* Bhb = g_Ph + n0;
    const __nv_bfloat16* Blb = g_Pl + n0;
    const int lda = 1024, ldb = NF;

    int ar0 = tid >> 2, ac0 = tid & 3;
    int ar1 = (tid + 256) >> 2, ac1 = tid & 3;
    int br0 = tid >> 4, bc0 = tid & 15;
    int br1 = (tid + 256) >> 4, bc1 = tid & 15;

#define DDK_LOAD(kt, s)                                                            \
    {                                                                              \
        uint32_t sb = sbase + (s) * STAGE_B;                                       \
        long long ka = (long long)(kt) * 32;                                       \
        CP_ASYNC16(sb + ar0 * 80 + ac0 * 16, Ahb + ar0 * lda + ka + ac0 * 8);      \
        CP_ASYNC16(sb + ar1 * 80 + ac1 * 16, Ahb + ar1 * lda + ka + ac1 * 8);      \
        CP_ASYNC16(sb + SOFF_AL + ar0 * 80 + ac0 * 16, Alb + ar0 * lda + ka + ac0 * 8); \
        CP_ASYNC16(sb + SOFF_AL + ar1 * 80 + ac1 * 16, Alb + ar1 * lda + ka + ac1 * 8); \
        CP_ASYNC16(sb + SOFF_BH + br0 * 272 + bc0 * 16, Bhb + (ka + br0) * ldb + bc0 * 8); \
        CP_ASYNC16(sb + SOFF_BH + br1 * 272 + bc1 * 16, Bhb + (ka + br1) * ldb + bc1 * 8); \
        CP_ASYNC16(sb + SOFF_BL + br0 * 272 + bc0 * 16, Blb + (ka + br0) * ldb + bc0 * 8); \
        CP_ASYNC16(sb + SOFF_BL + br1 * 272 + bc1 * 16, Blb + (ka + br1) * ldb + bc1 * 8); \
        CP_COMMIT();                                                               \
    }

    DDK_LOAD(0, 0);
    DDK_LOAD(1, 1);

    float acc[4][4][4];
#pragma unroll
    for (int i = 0; i < 4; i++)
#pragma unroll
        for (int j = 0; j < 4; j++)
#pragma unroll
            for (int r = 0; r < 4; r++) acc[i][j][r] = 0.f;

    int lrow = (lane & 7) + ((lane >> 3) & 1) * 8;
    int lcol8 = (lane >> 4) * 8;

    for (int it = 0; it < 2; ++it) {
        if (it == 0) { CP_WAIT1(); } else { CP_WAIT0(); }
        __syncthreads();
        uint32_t sb = sbase + (it & 1) * STAGE_B;
        uint32_t aAh = sb, aAl = sb + SOFF_AL, aBh = sb + SOFF_BH, aBl = sb + SOFF_BL;

#pragma unroll
        for (int ks = 0; ks < 2; ks++) {
            uint32_t ah[4][4], al[4][4];
            uint32_t bh[4][2], bl[4][2];
#pragma unroll
            for (int i = 0; i < 4; i++) {
                int r = wm * 64 + i * 16 + lrow;
                uint32_t off = (uint32_t)r * 80 + (ks * 16 + lcol8) * 2;
                ldsm_x4(ah[i], aAh + off);
                ldsm_x4(al[i], aAl + off);
            }
#pragma unroll
            for (int jj = 0; jj < 2; jj++) {
                int kr = ks * 16 + lrow;
                uint32_t off = (uint32_t)kr * 272 + (wn * 32 + jj * 16 + lcol8) * 2;
                uint32_t t[4];
                ldsm_x4_t(t, aBh + off);
                bh[jj * 2][0] = t[0]; bh[jj * 2][1] = t[1];
                bh[jj * 2 + 1][0] = t[2]; bh[jj * 2 + 1][1] = t[3];
                ldsm_x4_t(t, aBl + off);
                bl[jj * 2][0] = t[0]; bl[jj * 2][1] = t[1];
                bl[jj * 2 + 1][0] = t[2]; bl[jj * 2 + 1][1] = t[3];
            }
#pragma unroll
            for (int i = 0; i < 4; i++)
#pragma unroll
                for (int j = 0; j < 4; j++) {
                    mma_bf16(acc[i][j], ah[i], bh[j][0], bh[j][1]);
                    mma_bf16(acc[i][j], ah[i], bl[j][0], bl[j][1]);
                    mma_bf16(acc[i][j], al[i], bh[j][0], bh[j][1]);
                }
        }
        __syncthreads();
    }

    // raw-dd max
    float mx = __int_as_float(0xff800000);
#pragma unroll
    for (int i = 0; i < 4; i++)
#pragma unroll
        for (int j = 0; j < 4; j++)
#pragma unroll
            for (int r = 0; r < 4; r++) mx = fmaxf(mx, acc[i][j][r]);

    // epilogue: E = exp(dd - diag - 20), write bf16 hi/lo
    int g = lane >> 2, c2 = (lane & 3) * 2;
#pragma unroll
    for (int i = 0; i < 4; i++) {
        long long row0 = m0 + wm * 64 + i * 16 + g;
        long long row1 = row0 + 8;
        float rs0 = g_rssk[(long long)z * NSEQ + row0] + 20.f;
        float rs1 = g_rssk[(long long)z * NSEQ + row1] + 20.f;
#pragma unroll
        for (int j = 0; j < 4; j++) {
            int col = n0 + wn * 32 + j * 8 + c2;
            float e00 = __expf(acc[i][j][0] - rs0);
            float e01 = __expf(acc[i][j][1] - rs0);
            float e10 = __expf(acc[i][j][2] - rs1);
            float e11 = __expf(acc[i][j][3] - rs1);
            __nv_bfloat16 h00 = __float2bfloat16(e00), h01 = __float2bfloat16(e01);
            __nv_bfloat16 h10 = __float2bfloat16(e10), h11 = __float2bfloat16(e11);
            __nv_bfloat16 l00 = __float2bfloat16(e00 - __bfloat162float(h00));
            __nv_bfloat16 l01 = __float2bfloat16(e01 - __bfloat162float(h01));
            __nv_bfloat16 l10 = __float2bfloat16(e10 - __bfloat162float(h10));
            __nv_bfloat16 l11 = __float2bfloat16(e11 - __bfloat162float(h11));
            long long o0 = ((long long)z * NSEQ + row0) * NF + col;
            long long o1 = ((long long)z * NSEQ + row1) * NF + col;
            *(__nv_bfloat162*)&g_KPh[o0] = __nv_bfloat162(h00, h01);
            *(__nv_bfloat162*)&g_KPh[o1] = __nv_bfloat162(h10, h11);
            *(__nv_bfloat162*)&g_KPl[o0] = __nv_bfloat162(l00, l01);
            *(__nv_bfloat162*)&g_KPl[o1] = __nv_bfloat162(l10, l11);
        }
    }
#pragma unroll
    for (int o = 16; o > 0; o >>= 1) mx = fmaxf(mx, __shfl_xor_sync(0xffffffff, mx, o));
    if (lane == 0) redm[wid] = mx;
    __syncthreads();
    if (tid == 0) {
        float m2 = redm[0];
#pragma unroll
        for (int i = 1; i < 8; i++) m2 = fmaxf(m2, redm[i]);
        atomicMaxFloat(&g_kmax[z], m2);
    }
}

// ---------------- ctx via tensor cores: ctxT[d][f] = V^T @ E ------------------
// grid (NCHUNK, NZ), 256 thr; per-block K = 1024.
#define CT_AH 0
#define CT_AL 5120
#define CT_BH 10240
#define CT_BL 27136
#define CT_STAGE 44032
#define SMEM_CTX (2 * CT_STAGE)

__global__ __launch_bounds__(256) void ctx_mma() {
    extern __shared__ char smem[];
    uint32_t sbase = smem_u32(smem);
    int tid = threadIdx.x;
    int lane = tid & 31, wid = tid >> 5;
    int wm = wid & 1, wn = wid >> 1;
    int ch = blockIdx.x, z = blockIdx.y;
    int b = z >> 3, hd = z & 7;
    long long nbase = (long long)ch * CHROWS;

    const __nv_bfloat16* Ah = g_VTh + ((long long)(b * 512 + hd * 64)) * NSEQ;
    const __nv_bfloat16* Al = g_VTl + ((long long)(b * 512 + hd * 64)) * NSEQ;
    const __nv_bfloat16* Bh = g_KPh + (long long)z * NSEQ * NF;
    const __nv_bfloat16* Bl = g_KPl + (long long)z * NSEQ * NF;

    int ar = tid >> 2, asg = tid & 3;

#define CTX_LOAD(kt, s)                                                              \
    {                                                                                \
        uint32_t sb = sbase + (s) * CT_STAGE;                                        \
        long long ka = nbase + (long long)(kt) * 32;                                 \
        CP_ASYNC16(sb + CT_AH + ar * 80 + asg * 16, Ah + (long long)ar * NSEQ + ka + asg * 8); \
        CP_ASYNC16(sb + CT_AL + ar * 80 + asg * 16, Al + (long long)ar * NSEQ + ka + asg * 8); \
        _Pragma("unroll")                                                            \
        for (int ii = 0; ii < 4; ii++) {                                             \
            int idx = tid + ii * 256;                                                \
            int r = idx >> 5, sg = idx & 31;                                         \
            CP_ASYNC16(sb + CT_BH + r * 528 + sg * 16, Bh + (ka + r) * NF + sg * 8); \
            CP_ASYNC16(sb + CT_BL + r * 528 + sg * 16, Bl + (ka + r) * NF + sg * 8); \
        }                                                                            \
        CP_COMMIT();                                                                 \
    }

    CTX_LOAD(0, 0);
    CTX_LOAD(1, 1);

    float acc[2][8][4];
#pragma unroll
    for (int i = 0; i < 2; i++)
#pragma unroll
        for (int j = 0; j < 8; j++)
#pragma unroll
            for (int r = 0; r < 4; r++) acc[i][j][r] = 0.f;
    float ks_acc = 0.f;

    int lrow = (lane & 7) + ((lane >> 3) & 1) * 8;
    int lcol8 = (lane >> 4) * 8;
    const int NKK = CHROWS / 32;   // 32

    for (int it = 0; it < NKK; ++it) {
        if (it < NKK - 1) { CP_WAIT1(); } else { CP_WAIT0(); }
        __syncthreads();
        uint32_t sb = sbase + (it & 1) * CT_STAGE;
        uint32_t aAh = sb + CT_AH, aAl = sb + CT_AL, aBh = sb + CT_BH, aBl = sb + CT_BL;

        // ksum partial: f = tid over the 32-row E tile
        {
            const __nv_bfloat16* eh = (const __nv_bfloat16*)(smem + (it & 1) * CT_STAGE + CT_BH);
            const __nv_bfloat16* el = (const __nv_bfloat16*)(smem + (it & 1) * CT_STAGE + CT_BL);
#pragma unroll
            for (int r = 0; r < 32; r++)
                ks_acc += __bfloat162float(eh[r * 264 + tid]) + __bfloat162float(el[r * 264 + tid]);
        }

#pragma unroll
        for (int ks = 0; ks < 2; ks++) {
            uint32_t ah[2][4], al[2][4];
#pragma unroll
            for (int i = 0; i < 2; i++) {
                int r = wm * 32 + i * 16 + lrow;
                uint32_t off = (uint32_t)r * 80 + (ks * 16 + lcol8) * 2;
                ldsm_x4(ah[i], aAh + off);
                ldsm_x4(al[i], aAl + off);
            }
#pragma unroll
            for (int jj = 0; jj < 4; jj++) {
                int kr = ks * 16 + lrow;
                uint32_t off = (uint32_t)kr * 528 + (wn * 64 + jj * 16 + lcol8) * 2;
                uint32_t th[4], tl[4];
                ldsm_x4_t(th, aBh + off);
                ldsm_x4_t(tl, aBl + off);
#pragma unroll
                for (int i = 0; i < 2; i++) {
                    mma_bf16(acc[i][jj * 2],     ah[i], th[0], th[1]);
                    mma_bf16(acc[i][jj * 2],     ah[i], tl[0], tl[1]);
                    mma_bf16(acc[i][jj * 2],     al[i], th[0], th[1]);
                    mma_bf16(acc[i][jj * 2 + 1], ah[i], th[2], th[3]);
                    mma_bf16(acc[i][jj * 2 + 1], ah[i], tl[2], tl[3]);
                    mma_bf16(acc[i][jj * 2 + 1], al[i], th[2], th[3]);
                }
            }
        }
        __syncthreads();
        if (it + 2 < NKK) CTX_LOAD(it + 2, it & 1);
    }

    long long base = ((long long)(z * NCHUNK + ch)) * (NF * DHEAD);
    int g = lane >> 2, c2 = (lane & 3) * 2;
#pragma unroll
    for (int i = 0; i < 2; i++) {
        int d0 = wm * 32 + i * 16 + g, d1 = d0 + 8;
#pragma unroll
        for (int j = 0; j < 8; j++) {
            int f = wn * 64 + j * 8 + c2;
            *(float2*)&g_ctxP[base + d0 * 256 + f] = make_float2(acc[i][j][0], acc[i][j][1]);
            *(float2*)&g_ctxP[base + d1 * 256 + f] = make_float2(acc[i][j][2], acc[i][j][3]);
        }
    }
    g_ksumP[(z * NCHUNK + ch) * NF + tid] = ks_acc;
}

// ---------------- reduces with scale + eps corrections -------------------------
__global__ void ctx_reduce() {
    int idx = blockIdx.x * 256 + threadIdx.x;   // NZ*16384
    int z = idx >> 14, r = idx & 16383;
    int d = r >> 8, f = r & 255;
    float sc = __expf(20.f - g_kmax[z]);
    float s = 0.f;
#pragma unroll
    for (int c = 0; c < NCHUNK; c++)
        s += g_ctxP[((long long)(z * NCHUNK + c)) * 16384 + d * 256 + f];
    float vs = g_vsum[(z >> 3) * 512 + (z & 7) * 64 + d];
    g_ctx[(long long)z * 16384 + f * 64 + d] = 0.0625f * (sc * s + 1e-4f * vs);
}

__global__ void ksum_reduce() {
    int z = blockIdx.x, f = threadIdx.x;
    float sc = __expf(20.f - g_kmax[z]);
    float s = 0.f;
#pragma unroll
    for (int c = 0; c < NCHUNK; c++) s += g_ksumP[(z * NCHUNK + c) * NF + f];
    g_ksum[z * NF + f] = 0.0625f * (sc * s + 1e-4f * 16384.f);
}

// ---------------- fused Q features + attention --------------------------------
#define QPP 260
#define FA_QP    0
#define FA_QH    133120
#define FA_QL    (FA_QH + 18432)
#define FA_PBH   (FA_QL + 18432)
#define FA_PBL   (FA_PBH + 8448)
#define FA_CS    (FA_PBL + 8448)
#define FA_KS    (FA_CS + 4352)
#define FA_RSUB  (FA_KS + 1024)
#define FA_DINV  (FA_RSUB + 512)
#define FA_RED   (FA_DINV + 512)
#define SMEM_ATTN (FA_RED + 2048)

__global__ __launch_bounds__(512, 1) void fused_attn_kernel() {
    extern __shared__ char smemc[];
    float* qp     = (float*)(smemc + FA_QP);
    __nv_bfloat16* qh = (__nv_bfloat16*)(smemc + FA_QH);
    __nv_bfloat16* ql = (__nv_bfloat16*)(smemc + FA_QL);
    __nv_bfloat16* pbh = (__nv_bfloat16*)(smemc + FA_PBH);
    __nv_bfloat16* pbl = (__nv_bfloat16*)(smemc + FA_PBL);
    float* cs     = (float*)(smemc + FA_CS);
    float* ks     = (float*)(smemc + FA_KS);
    float* rowsub = (float*)(smemc + FA_RSUB);
    float* sdinv  = (float*)(smemc + FA_DINV);
    float* red    = (float*)(smemc + FA_RED);

    int z = blockIdx.y;
    int b = z >> 3, hd = z & 7;
    long long m0 = (long long)blockIdx.x * 128;
    int tid = threadIdx.x;

    long long Aq = ((long long)b * NSEQ + m0) * 1024 + hd * 64;
#pragma unroll
    for (int i = 0; i < 2; i++) {
        int idx = tid + i * 512;
        int row = idx >> 3, ch = idx & 7;
        *(uint4*)(qh + row * 72 + ch * 8) = *(const uint4*)(g_QKh + Aq + (long long)row * 1024 + ch * 8);
        *(uint4*)(ql + row * 72 + ch * 8) = *(const uint4*)(g_QKl + Aq + (long long)row * 1024 + ch * 8);
    }
    if (tid < 256) ks[tid] = g_ksum[z * NF + tid];
    if (tid < 128) rowsub[tid] = g_rssq[(long long)z * NSEQ + m0 + tid];
    __syncthreads();

    {
        int lane = tid & 31, wid = tid >> 5;
        int wm = wid & 3, wn = wid >> 2;
        int lrow = (lane & 7) + ((lane >> 3) & 1) * 8;
        int lcol8 = (lane >> 4) * 8;
        uint32_t qhB = smem_u32(qh), qlB = smem_u32(ql);
        uint32_t pbhB = smem_u32(pbh), pblB = smem_u32(pbl);

        float acc[2][8][4];
#pragma unroll
        for (int i = 0; i < 2; i++)
#pragma unroll
            for (int j = 0; j < 8; j++)
#pragma unroll
                for (int r = 0; r < 4; r++) acc[i][j][r] = 0.f;

        for (int c0 = 0; c0 < 64; c0 += 16) {
            __syncthreads();
            {
                int row = tid >> 5, c16 = tid & 31;
                *(uint4*)(pbh + row * 264 + c16 * 8) = *(const uint4*)(g_Ph + (c0 + row) * NF + c16 * 8);
                *(uint4*)(pbl + row * 264 + c16 * 8) = *(const uint4*)(g_Pl + (c0 + row) * NF + c16 * 8);
            }
            __syncthreads();
            uint32_t ah[2][4], al[2][4];
#pragma unroll
            for (int i = 0; i < 2; i++) {
                int r = wm * 32 + i * 16 + lrow;
                uint32_t off = (uint32_t)r * 144 + (c0 + lcol8) * 2;
                ldsm_x4(ah[i], qhB + off);
                ldsm_x4(al[i], qlB + off);
            }
#pragma unroll
            for (int jj = 0; jj < 4; jj++) {
                uint32_t offb = (uint32_t)lrow * 528 + (wn * 64 + jj * 16 + lcol8) * 2;
                uint32_t th[4], tl[4];
                ldsm_x4_t(th, pbhB + offb);
                ldsm_x4_t(tl, pblB + offb);
#pragma unroll
                for (int i = 0; i < 2; i++) {
                    mma_bf16(acc[i][jj * 2],     ah[i], th[0], th[1]);
                    mma_bf16(acc[i][jj * 2],     ah[i], tl[0], tl[1]);
                    mma_bf16(acc[i][jj * 2],     al[i], th[0], th[1]);
                    mma_bf16(acc[i][jj * 2 + 1], ah[i], th[2], th[3]);
                    mma_bf16(acc[i][jj * 2 + 1], ah[i], tl[2], tl[3]);
                    mma_bf16(acc[i][jj * 2 + 1], al[i], th[2], th[3]);
                }
            }
        }
        __syncthreads();
        int g = lane >> 2, c2 = (lane & 3) * 2;
#pragma unroll
        for (int i = 0; i < 2; i++) {
            int r0 = wm * 32 + i * 16 + g, r1 = r0 + 8;
#pragma unroll
            for (int j = 0; j < 8; j++) {
                int col = wn * 64 + j * 8 + c2;
                qp[r0 * QPP + col]     = acc[i][j][0];
                qp[r0 * QPP + col + 1] = acc[i][j][1];
                qp[r1 * QPP + col]     = acc[i][j][2];
                qp[r1 * QPP + col + 1] = acc[i][j][3];
            }
        }
    }
    __syncthreads();

    {
        int r = tid >> 2, p = tid & 3;
        float mx = __int_as_float(0xff800000);
        for (int f = p * 64; f < p * 64 + 64; f++) mx = fmaxf(mx, qp[r * QPP + f]);
        red[r * 4 + p] = mx;
    }
    __syncthreads();
    if (tid < 128) {
        float m = fmaxf(fmaxf(red[tid * 4], red[tid * 4 + 1]), fmaxf(red[tid * 4 + 2], red[tid * 4 + 3]));
        rowsub[tid] += m;
    }
    __syncthreads();

#pragma unroll
    for (int i = 0; i < 64; i++) {
        int idx = i * 512 + tid;
        int r = idx >> 8, f = idx & 255;
        float v = qp[r * QPP + f];
        qp[r * QPP + f] = 0.0625f * (__expf(v - rowsub[r]) + 1e-4f);
    }
    __syncthreads();

    {
        int r = tid >> 2, p = tid & 3;
        float s = 0.f;
        for (int f = p * 64; f < p * 64 + 64; f++) s += qp[r * QPP + f] * ks[f];
        red[r * 4 + p] = s;
    }
    __syncthreads();
    if (tid < 128)
        sdinv[tid] = 1.0f / (red[tid * 4] + red[tid * 4 + 1] + red[tid * 4 + 2] + red[tid * 4 + 3]);

    int tx2 = tid & 15, ty2 = tid >> 4;
    float acc2[4][4];
#pragma unroll
    for (int i = 0; i < 4; i++)
#pragma unroll
        for (int j = 0; j < 4; j++) acc2[i][j] = 0.f;

    const float* ctxp = g_ctx + (long long)z * NF * DHEAD;
    for (int f0 = 0; f0 < NF; f0 += 16) {
        __syncthreads();
        if (tid < 256) {
            int k = tid >> 4, nq = tid & 15;
            *(float4*)&cs[k * 68 + nq * 4] = *(const float4*)&ctxp[(long long)(f0 + k) * DHEAD + nq * 4];
        }
        __syncthreads();
#pragma unroll
        for (int k = 0; k < 16; k++) {
            float a0 = qp[(ty2 * 4 + 0) * QPP + f0 + k];
            float a1 = qp[(ty2 * 4 + 1) * QPP + f0 + k];
            float a2 = qp[(ty2 * 4 + 2) * QPP + f0 + k];
            float a3 = qp[(ty2 * 4 + 3) * QPP + f0 + k];
            float4 b4 = *(const float4*)&cs[k * 68 + tx2 * 4];
            float bv[4] = {b4.x, b4.y, b4.z, b4.w};
            float av[4] = {a0, a1, a2, a3};
#pragma unroll
            for (int i = 0; i < 4; i++)
#pragma unroll
                for (int j = 0; j < 4; j++) acc2[i][j] += av[i] * bv[j];
        }
    }

#pragma unroll
    for (int i = 0; i < 4; i++) {
        int m = ty2 * 4 + i;
        float s = sdinv[m];
        long long base = ((long long)b * NSEQ + m0 + m) * INNERD + hd * DHEAD + tx2 * 4;
        float vv[4] = {acc2[i][0] * s, acc2[i][1] * s, acc2[i][2] * s, acc2[i][3] * s};
        __nv_bfloat16 h[4], l[4];
#pragma unroll
        for (int j = 0; j < 4; j++) {
            h[j] = __float2bfloat16(vv[j]);
            l[j] = __float2bfloat16(vv[j] - __bfloat162float(h[j]));
        }
        *(__nv_bfloat162*)&g_ATTh[base]     = __nv_bfloat162(h[0], h[1]);
        *(__nv_bfloat162*)&g_ATTh[base + 2] = __nv_bfloat162(h[2], h[3]);
        *(__nv_bfloat162*)&g_ATTl[base]     = __nv_bfloat162(l[0], l[1]);
        *(__nv_bfloat162*)&g_ATTl[base + 2] = __nv_bfloat162(l[2], l[3]);
    }
}

// ---------------- launcher ----------------------------------------------------
extern "C" void kernel_launch(void* const* d_in, const int* in_sizes, int n_in,
                              void* d_out, int out_size) {
    const float* x    = (const float*)d_in[0];
    const float* Wq   = (const float*)d_in[1];
    const float* Wk   = (const float*)d_in[2];
    const float* Wv   = (const float*)d_in[3];
    const float* Wo   = (const float*)d_in[4];
    const float* bo   = (const float*)d_in[5];
    const float* proj = (const float*)d_in[6];
    const float* Wp   = (const float*)d_in[7];
    const float* bp   = (const float*)d_in[8];
    const float* btab = (const float*)d_in[9];
    float* out = (float*)d_out;

    static bool attr_set = false;
    if (!attr_set) {
        cudaFuncSetAttribute(fused_attn_kernel, cudaFuncAttributeMaxDynamicSharedMemorySize, SMEM_ATTN);
        cudaFuncSetAttribute(mma_gemm<0>, cudaFuncAttributeMaxDynamicSharedMemorySize, SMEM_MMA);
        cudaFuncSetAttribute(mma_gemm<2>, cudaFuncAttributeMaxDynamicSharedMemorySize, SMEM_MMA);
        cudaFuncSetAttribute(ddk_mma, cudaFuncAttributeMaxDynamicSharedMemorySize, SMEM_MMA);
        cudaFuncSetAttribute(ctx_mma, cudaFuncAttributeMaxDynamicSharedMemorySize, SMEM_CTX);
        attr_set = true;
    }

    float *pQKV, *pWoWp, *pB2, *pCS;
    __nv_bfloat16 *pXh, *pXl, *pWch, *pWcl, *pATTh, *pATTl, *pWoWph, *pWoWpl;
    cudaGetSymbolAddress((void**)&pQKV,   g_QKV);
    cudaGetSymbolAddress((void**)&pWoWp,  g_WoWp);
    cudaGetSymbolAddress((void**)&pB2,    g_bias2);
    cudaGetSymbolAddress((void**)&pCS,    g_colsum);
    cudaGetSymbolAddress((void**)&pXh,    g_Xh);
    cudaGetSymbolAddress((void**)&pXl,    g_Xl);
    cudaGetSymbolAddress((void**)&pWch,   g_Wch);
    cudaGetSymbolAddress((void**)&pWcl,   g_Wcl);
    cudaGetSymbolAddress((void**)&pATTh,  g_ATTh);
    cudaGetSymbolAddress((void**)&pATTl,  g_ATTl);
    cudaGetSymbolAddress((void**)&pWoWph, g_WoWph);
    cudaGetSymbolAddress((void**)&pWoWpl, g_WoWpl);

    init_kernel<<<1, 32>>>();
    transpose_proj_split<<<64, 256>>>(proj);
    bias2_kernel<<<1, 256>>>(bo, Wp, bp);
    split_x_kernel<<<TOK * CDIM / 1024, 256>>>(x);
    pack_w_kernel<<<CDIM * QKVLD / 256, 256>>>(Wq, Wk, Wv);

    sgemm128<<<dim3(CDIM / 128, INNERD / 128), 256>>>(Wo, Wp, pWoWp, CDIM, CDIM, CDIM, CDIM);
    split_wowp_kernel<<<INNERD * CDIM / 256, 256>>>();

    // QKV fused tensor GEMM
    mma_gemm<0><<<dim3(QKVLD / 128, TOK / 128), 256, SMEM_MMA>>>(
        pXh, pXl, pWch, pWcl, pQKV, CDIM, CDIM, QKVLD, QKVLD,
        nullptr, nullptr, nullptr);

    split_qk_kernel<<<TOK, 256>>>();
    vt_kernel<<<dim3(NSEQ / 64, 8, 4), 256>>>();
    vsum_reduce<<<8, 256>>>();

    // K features: dd mma + exp -> E bf16
    ddk_mma<<<dim3(NF / 128, NSEQ / 128, NZ), 256, SMEM_MMA>>>();

    // ctx on tensor cores + reduces with scale/eps
    ctx_mma<<<dim3(NCHUNK, NZ), 256, SMEM_CTX>>>();
    ksum_reduce<<<NZ, 256>>>();
    ctx_reduce<<<(NZ * NF * DHEAD) / 256, 256>>>();

    fused_attn_kernel<<<dim3(NSEQ / 128, NZ), 512, SMEM_ATTN>>>();

    // out = ATT @ WoWp + bias2 + rel*colsum
    mma_gemm<2><<<dim3(CDIM / 128, TOK / 128), 256, SMEM_MMA>>>(
        pATTh, pATTl, pWoWph, pWoWpl, out, INNERD, INNERD, CDIM, CDIM,
        pB2, btab, pCS);

    (void)in_sizes; (void)n_in; (void)out_size;
}

// round 17
// speedup vs baseline: 2.4889x; 1.0979x over previous
#include <cuda_runtime.h>
#include <cuda_bf16.h>
#include <math.h>
#include <stdint.h>

#define TOK    65536
#define NSEQ   16384
#define CDIM   256
#define INNERD 512
#define QKVLD  1536
#define NHEAD  8
#define DHEAD  64
#define NF     256
#define NZ     32
#define NCHUNK 16
#define CHROWS (NSEQ / NCHUNK)   // 1024

// ---------------- scratch (static device globals) ----------------------------
__device__ float g_QKV[(long long)TOK * QKVLD];          // Q|K|V fp32
__device__ __nv_bfloat16 g_KPh[(long long)NZ * NSEQ * NF]; // E hi
__device__ __nv_bfloat16 g_KPl[(long long)NZ * NSEQ * NF]; // E lo
__device__ __nv_bfloat16 g_Xh[(long long)TOK * CDIM];
__device__ __nv_bfloat16 g_Xl[(long long)TOK * CDIM];
__device__ __nv_bfloat16 g_Wch[CDIM * QKVLD];
__device__ __nv_bfloat16 g_Wcl[CDIM * QKVLD];
__device__ __nv_bfloat16 g_ATTh[(long long)TOK * INNERD];
__device__ __nv_bfloat16 g_ATTl[(long long)TOK * INNERD];
__device__ __nv_bfloat16 g_WoWph[INNERD * CDIM];
__device__ __nv_bfloat16 g_WoWpl[INNERD * CDIM];
__device__ __nv_bfloat16 g_QKh[(long long)TOK * 1024];
__device__ __nv_bfloat16 g_QKl[(long long)TOK * 1024];
__device__ __nv_bfloat16 g_VTh[(long long)4 * 512 * NSEQ]; // V^T per batch
__device__ __nv_bfloat16 g_VTl[(long long)4 * 512 * NSEQ];
__device__ __nv_bfloat16 g_Ph[DHEAD * NF];
__device__ __nv_bfloat16 g_Pl[DHEAD * NF];
__device__ __nv_bfloat16 g_ctxh[(long long)NZ * NF * DHEAD]; // ctx bf16 hi [f][d]
__device__ __nv_bfloat16 g_ctxl[(long long)NZ * NF * DHEAD]; // ctx bf16 lo
__device__ float g_rssq[(long long)NZ * NSEQ];
__device__ float g_rssk[(long long)NZ * NSEQ];
__device__ float g_kmax[NZ];
__device__ float g_ctxP[(long long)NZ * NCHUNK * NF * DHEAD]; // partials [d][f]
__device__ float g_ksumP[NZ * NCHUNK * NF];
__device__ float g_ksum[NZ * NF];
__device__ float g_vsumP[1024 * 2048];                        // deterministic vsum partials
__device__ float g_vsum[4 * 512];
__device__ float g_WoWp[INNERD * CDIM];
__device__ float g_bias2[CDIM];
__device__ float g_colsum[CDIM];

// ---------------- ptx helpers -------------------------------------------------
__device__ __forceinline__ uint32_t smem_u32(const void* p) {
    uint32_t a;
    asm("{ .reg .u64 t; cvta.to.shared.u64 t, %1; cvt.u32.u64 %0, t; }" : "=r"(a) : "l"(p));
    return a;
}
#define CP_ASYNC16(dst, src) \
    asm volatile("cp.async.cg.shared.global [%0], [%1], 16;\n" :: "r"(dst), "l"(src))
#define CP_COMMIT() asm volatile("cp.async.commit_group;\n")
#define CP_WAIT1()  asm volatile("cp.async.wait_group 1;\n")
#define CP_WAIT0()  asm volatile("cp.async.wait_group 0;\n")

__device__ __forceinline__ void ldsm_x4(uint32_t (&r)[4], uint32_t a) {
    asm volatile("ldmatrix.sync.aligned.m8n8.x4.shared.b16 {%0,%1,%2,%3}, [%4];"
                 : "=r"(r[0]), "=r"(r[1]), "=r"(r[2]), "=r"(r[3]) : "r"(a));
}
__device__ __forceinline__ void ldsm_x4_t(uint32_t (&r)[4], uint32_t a) {
    asm volatile("ldmatrix.sync.aligned.m8n8.x4.trans.shared.b16 {%0,%1,%2,%3}, [%4];"
                 : "=r"(r[0]), "=r"(r[1]), "=r"(r[2]), "=r"(r[3]) : "r"(a));
}
__device__ __forceinline__ void mma_bf16(float (&d)[4], const uint32_t (&a)[4],
                                         uint32_t b0, uint32_t b1) {
    asm volatile("mma.sync.aligned.m16n8k16.row.col.f32.bf16.bf16.f32 "
                 "{%0,%1,%2,%3},{%4,%5,%6,%7},{%8,%9},{%0,%1,%2,%3};"
                 : "+f"(d[0]), "+f"(d[1]), "+f"(d[2]), "+f"(d[3])
                 : "r"(a[0]), "r"(a[1]), "r"(a[2]), "r"(a[3]), "r"(b0), "r"(b1));
}

__device__ __forceinline__ void atomicMaxFloat(float* addr, float val) {
    if (val >= 0.f) atomicMax((int*)addr, __float_as_int(val));
    else            atomicMin((unsigned int*)addr, (unsigned int)__float_as_int(val));
}

// ---------------- small prep kernels ------------------------------------------
__global__ void init_kernel() {
    int t = threadIdx.x;
    if (t < NZ) g_kmax[t] = __int_as_float(0xff800000);
}

__global__ void transpose_proj_split(const float* __restrict__ proj) {
    int t = blockIdx.x * 256 + threadIdx.x;
    int d = t >> 8, f = t & 255;
    const float DN = 0.35355339059327373f;
    float v = proj[f * DHEAD + d] * DN;
    __nv_bfloat16 h = __float2bfloat16(v);
    g_Ph[d * NF + f] = h;
    g_Pl[d * NF + f] = __float2bfloat16(v - __bfloat162float(h));
}

__global__ void bias2_kernel(const float* __restrict__ bo,
                             const float* __restrict__ Wp,
                             const float* __restrict__ bp) {
    int n = threadIdx.x;
    float s = 0.f, cs = 0.f;
    for (int c = 0; c < CDIM; c++) {
        float w = Wp[c * CDIM + n];
        s += bo[c] * w;
        cs += w;
    }
    g_bias2[n] = s + bp[n];
    g_colsum[n] = cs;
}

__global__ void split_x_kernel(const float* __restrict__ x) {
    long long i = (long long)blockIdx.x * 256 + threadIdx.x;
    float4 v = *(const float4*)&x[i * 4];
    float vv[4] = {v.x, v.y, v.z, v.w};
#pragma unroll
    for (int j = 0; j < 4; j++) {
        __nv_bfloat16 h = __float2bfloat16(vv[j]);
        g_Xh[i * 4 + j] = h;
        g_Xl[i * 4 + j] = __float2bfloat16(vv[j] - __bfloat162float(h));
    }
}

__global__ void pack_w_kernel(const float* __restrict__ Wq,
                              const float* __restrict__ Wk,
                              const float* __restrict__ Wv) {
    int i = blockIdx.x * 256 + threadIdx.x;
    int c = i / QKVLD, n = i % QKVLD;
    float v = (n < 512) ? Wq[c * 512 + n]
            : (n < 1024) ? Wk[c * 512 + n - 512]
                         : Wv[c * 512 + n - 1024];
    __nv_bfloat16 h = __float2bfloat16(v);
    g_Wch[i] = h;
    g_Wcl[i] = __float2bfloat16(v - __bfloat162float(h));
}

__global__ void split_wowp_kernel() {
    int i = blockIdx.x * 256 + threadIdx.x;
    float v = g_WoWp[i];
    __nv_bfloat16 h = __float2bfloat16(v);
    g_WoWph[i] = h;
    g_WoWpl[i] = __float2bfloat16(v - __bfloat162float(h));
}

// split Q|K + per-(token,head) diag sums
__global__ __launch_bounds__(256) void split_qk_kernel() {
    long long tok = blockIdx.x;
    int t = threadIdx.x;
    const float* src = g_QKV + tok * QKVLD;
    float4 v = *(const float4*)&src[t * 4];
    float vv[4] = {v.x, v.y, v.z, v.w};
    __nv_bfloat16 h[4], l[4];
#pragma unroll
    for (int j = 0; j < 4; j++) {
        h[j] = __float2bfloat16(vv[j]);
        l[j] = __float2bfloat16(vv[j] - __bfloat162float(h[j]));
    }
    long long o = tok * 1024 + t * 4;
    *(__nv_bfloat162*)&g_QKh[o]     = __nv_bfloat162(h[0], h[1]);
    *(__nv_bfloat162*)&g_QKh[o + 2] = __nv_bfloat162(h[2], h[3]);
    *(__nv_bfloat162*)&g_QKl[o]     = __nv_bfloat162(l[0], l[1]);
    *(__nv_bfloat162*)&g_QKl[o + 2] = __nv_bfloat162(l[2], l[3]);

    float s = vv[0]*vv[0] + vv[1]*vv[1] + vv[2]*vv[2] + vv[3]*vv[3];
#pragma unroll
    for (int off = 8; off > 0; off >>= 1)
        s += __shfl_down_sync(0xffffffff, s, off, 16);
    if ((t & 15) == 0) {
        int head = t >> 4;
        int b = (int)(tok >> 14), nloc = (int)(tok & (NSEQ - 1));
        int z = b * 8 + (head & 7);
        float r = 0.0625f * s;
        if (head < 8) g_rssq[(long long)z * NSEQ + nloc] = r;
        else          g_rssk[(long long)z * NSEQ + nloc] = r;
    }
}

// transpose V -> VT bf16 hi/lo + deterministic column-sum partials
// grid (NSEQ/64, 512/64, 4), 256 thr
__global__ __launch_bounds__(256) void vt_kernel() {
    __shared__ float Vs[64 * 65];
    int n0 = blockIdx.x * 64, c0 = blockIdx.y * 64, b = blockIdx.z;
    int t = threadIdx.x;
#pragma unroll
    for (int i = 0; i < 4; i++) {
        int idx = t + i * 256;
        int r = idx >> 4, cq = idx & 15;
        float4 v = *(const float4*)&g_QKV[((long long)(b * NSEQ + n0 + r)) * QKVLD + 1024 + c0 + cq * 4];
        Vs[r * 65 + cq * 4 + 0] = v.x; Vs[r * 65 + cq * 4 + 1] = v.y;
        Vs[r * 65 + cq * 4 + 2] = v.z; Vs[r * 65 + cq * 4 + 3] = v.w;
    }
    __syncthreads();
#pragma unroll
    for (int i = 0; i < 8; i++) {
        int idx = t + i * 256;
        int c = idx >> 5, nq = idx & 31;
        float v0 = Vs[(nq * 2) * 65 + c], v1 = Vs[(nq * 2 + 1) * 65 + c];
        __nv_bfloat16 h0 = __float2bfloat16(v0), h1 = __float2bfloat16(v1);
        __nv_bfloat16 l0 = __float2bfloat16(v0 - __bfloat162float(h0));
        __nv_bfloat16 l1 = __float2bfloat16(v1 - __bfloat162float(h1));
        long long o = ((long long)(b * 512 + c0 + c)) * NSEQ + n0 + nq * 2;
        *(__nv_bfloat162*)&g_VTh[o] = __nv_bfloat162(h0, h1);
        *(__nv_bfloat162*)&g_VTl[o] = __nv_bfloat162(l0, l1);
    }
    // vsum partials: 4 threads per column
    int p = t >> 6, c = t & 63;
    float s = 0.f;
    for (int n = p * 16; n < p * 16 + 16; n++) s += Vs[n * 65 + c];
    g_vsumP[(long long)(blockIdx.x * 4 + p) * 2048 + b * 512 + c0 + c] = s;
}

__global__ void vsum_reduce() {
    int col = blockIdx.x * 256 + threadIdx.x;   // 2048
    float s = 0.f;
    for (int k = 0; k < 1024; k++) s += g_vsumP[(long long)k * 2048 + col];
    g_vsum[col] = s;
}

// ---------------- fp32 sgemm128 (WoWp product only) ---------------------------
__global__ __launch_bounds__(256, 2) void sgemm128(
    const float* __restrict__ A, const float* __restrict__ B, float* __restrict__ C,
    int lda, int ldb, int ldc, int K)
{
    __shared__ float As[2][16][132];
    __shared__ float Bs[2][16][128];
    int tid = threadIdx.x;
    int tx = tid & 15, ty = tid >> 4;
    long long m0 = (long long)blockIdx.y * 128;
    int n0 = blockIdx.x * 128;
    const float* Ab = A + m0 * lda;
    const float* Bb = B + n0;

#pragma unroll
    for (int i = 0; i < 2; i++) {
        int idx = tid + i * 256;
        int m = idx >> 2, kq = idx & 3;
        float4 v = *(const float4*)&Ab[(long long)m * lda + kq * 4];
        As[0][kq * 4 + 0][m] = v.x; As[0][kq * 4 + 1][m] = v.y;
        As[0][kq * 4 + 2][m] = v.z; As[0][kq * 4 + 3][m] = v.w;
    }
#pragma unroll
    for (int i = 0; i < 2; i++) {
        int idx = tid + i * 256;
        int k = idx >> 5, nq = idx & 31;
        *(float4*)&Bs[0][k][nq * 4] = *(const float4*)&Bb[(long long)k * ldb + nq * 4];
    }
    __syncthreads();

    float acc[8][8];
#pragma unroll
    for (int i = 0; i < 8; i++)
#pragma unroll
        for (int j = 0; j < 8; j++) acc[i][j] = 0.f;

    int nk = K >> 4, buf = 0;
    for (int it = 0; it < nk; ++it) {
        float4 pa[2], pbv[2];
        bool nxt = (it + 1 < nk);
        if (nxt) {
            int k0 = (it + 1) << 4;
#pragma unroll
            for (int i = 0; i < 2; i++) {
                int idx = tid + i * 256;
                int m = idx >> 2, kq = idx & 3;
                pa[i] = *(const float4*)&Ab[(long long)m * lda + k0 + kq * 4];
            }
#pragma unroll
            for (int i = 0; i < 2; i++) {
                int idx = tid + i * 256;
                int k = idx >> 5, nq = idx & 31;
                pbv[i] = *(const float4*)&Bb[(long long)(k0 + k) * ldb + nq * 4];
            }
        }
#pragma unroll
        for (int k = 0; k < 16; k++) {
            float4 a0 = *(const float4*)&As[buf][k][ty * 4];
            float4 a1 = *(const float4*)&As[buf][k][ty * 4 + 64];
            float4 b0 = *(const float4*)&Bs[buf][k][tx * 4];
            float4 b1 = *(const float4*)&Bs[buf][k][tx * 4 + 64];
            float av[8] = {a0.x, a0.y, a0.z, a0.w, a1.x, a1.y, a1.z, a1.w};
            float bv[8] = {b0.x, b0.y, b0.z, b0.w, b1.x, b1.y, b1.z, b1.w};
#pragma unroll
            for (int i = 0; i < 8; i++)
#pragma unroll
                for (int j = 0; j < 8; j++) acc[i][j] += av[i] * bv[j];
        }
        if (nxt) {
            int nb = buf ^ 1;
#pragma unroll
            for (int i = 0; i < 2; i++) {
                int idx = tid + i * 256;
                int m = idx >> 2, kq = idx & 3;
                As[nb][kq * 4 + 0][m] = pa[i].x; As[nb][kq * 4 + 1][m] = pa[i].y;
                As[nb][kq * 4 + 2][m] = pa[i].z; As[nb][kq * 4 + 3][m] = pa[i].w;
            }
#pragma unroll
            for (int i = 0; i < 2; i++) {
                int idx = tid + i * 256;
                int k = idx >> 5, nq = idx & 31;
                *(float4*)&Bs[nb][k][nq * 4] = pbv[i];
            }
            __syncthreads();
            buf = nb;
        }
    }
#pragma unroll
    for (int i = 0; i < 8; i++) {
        long long gm = m0 + (i < 4 ? ty * 4 + i : 64 + ty * 4 + (i - 4));
        *(float4*)&C[gm * ldc + n0 + tx * 4] =
            make_float4(acc[i][0], acc[i][1], acc[i][2], acc[i][3]);
        *(float4*)&C[gm * ldc + n0 + tx * 4 + 64] =
            make_float4(acc[i][4], acc[i][5], acc[i][6], acc[i][7]);
    }
}

// ---------------- bf16-split tensor-core GEMM ---------------------------------
#define SOFF_AL 10240
#define SOFF_BH 20480
#define SOFF_BL 29184
#define STAGE_B 37888
#define SMEM_MMA (2 * STAGE_B)

template <int EPI>
__global__ __launch_bounds__(256) void mma_gemm(
    const __nv_bfloat16* __restrict__ Ah, const __nv_bfloat16* __restrict__ Al,
    const __nv_bfloat16* __restrict__ Bh, const __nv_bfloat16* __restrict__ Bl,
    float* __restrict__ C, int K, int lda, int ldb, int ldc,
    const float* __restrict__ bias, const float* __restrict__ btab,
    const float* __restrict__ colsum)
{
    extern __shared__ char smem[];
    uint32_t sbase = smem_u32(smem);

    int tid = threadIdx.x;
    int lane = tid & 31, wid = tid >> 5;
    int wm = wid & 1, wn = wid >> 1;
    long long m0 = (long long)blockIdx.y * 128;
    int n0 = blockIdx.x * 128;

    const __nv_bfloat16* Ahb = Ah + m0 * lda;
    const __nv_bfloat16* Alb = Al + m0 * lda;
    const __nv_bfloat16* Bhb = Bh + n0;
    const __nv_bfloat16* Blb = Bl + n0;

    int nk = K >> 5;

    int ar0 = tid >> 2, ac0 = tid & 3;
    int ar1 = (tid + 256) >> 2, ac1 = tid & 3;
    int br0 = tid >> 4, bc0 = tid & 15;
    int br1 = (tid + 256) >> 4, bc1 = tid & 15;

#define LOAD_STAGE(kt, s)                                                          \
    {                                                                              \
        uint32_t sb = sbase + (s) * STAGE_B;                                       \
        long long ka = (long long)(kt) * 32;                                       \
        CP_ASYNC16(sb + ar0 * 80 + ac0 * 16, Ahb + ar0 * lda + ka + ac0 * 8);      \
        CP_ASYNC16(sb + ar1 * 80 + ac1 * 16, Ahb + ar1 * lda + ka + ac1 * 8);      \
        CP_ASYNC16(sb + SOFF_AL + ar0 * 80 + ac0 * 16, Alb + ar0 * lda + ka + ac0 * 8); \
        CP_ASYNC16(sb + SOFF_AL + ar1 * 80 + ac1 * 16, Alb + ar1 * lda + ka + ac1 * 8); \
        CP_ASYNC16(sb + SOFF_BH + br0 * 272 + bc0 * 16, Bhb + (ka + br0) * ldb + bc0 * 8); \
        CP_ASYNC16(sb + SOFF_BH + br1 * 272 + bc1 * 16, Bhb + (ka + br1) * ldb + bc1 * 8); \
        CP_ASYNC16(sb + SOFF_BL + br0 * 272 + bc0 * 16, Blb + (ka + br0) * ldb + bc0 * 8); \
        CP_ASYNC16(sb + SOFF_BL + br1 * 272 + bc1 * 16, Blb + (ka + br1) * ldb + bc1 * 8); \
        CP_COMMIT();                                                               \
    }

    LOAD_STAGE(0, 0);
    LOAD_STAGE(1, 1);

    float acc[4][4][4];
#pragma unroll
    for (int i = 0; i < 4; i++)
#pragma unroll
        for (int j = 0; j < 4; j++)
#pragma unroll
            for (int r = 0; r < 4; r++) acc[i][j][r] = 0.f;

    int lrow = (lane & 7) + ((lane >> 3) & 1) * 8;
    int lcol8 = (lane >> 4) * 8;

    for (int it = 0; it < nk; ++it) {
        if (it < nk - 1) { CP_WAIT1(); } else { CP_WAIT0(); }
        __syncthreads();
        uint32_t sb = sbase + (it & 1) * STAGE_B;
        uint32_t aAh = sb, aAl = sb + SOFF_AL, aBh = sb + SOFF_BH, aBl = sb + SOFF_BL;

#pragma unroll
        for (int ks = 0; ks < 2; ks++) {
            uint32_t ah[4][4], al[4][4];
            uint32_t bh[4][2], bl[4][2];
#pragma unroll
            for (int i = 0; i < 4; i++) {
                int r = wm * 64 + i * 16 + lrow;
                uint32_t off = (uint32_t)r * 80 + (ks * 16 + lcol8) * 2;
                ldsm_x4(ah[i], aAh + off);
                ldsm_x4(al[i], aAl + off);
            }
#pragma unroll
            for (int jj = 0; jj < 2; jj++) {
                int kr = ks * 16 + lrow;
                uint32_t off = (uint32_t)kr * 272 + (wn * 32 + jj * 16 + lcol8) * 2;
                uint32_t t[4];
                ldsm_x4_t(t, aBh + off);
                bh[jj * 2][0] = t[0]; bh[jj * 2][1] = t[1];
                bh[jj * 2 + 1][0] = t[2]; bh[jj * 2 + 1][1] = t[3];
                ldsm_x4_t(t, aBl + off);
                bl[jj * 2][0] = t[0]; bl[jj * 2][1] = t[1];
                bl[jj * 2 + 1][0] = t[2]; bl[jj * 2 + 1][1] = t[3];
            }
#pragma unroll
            for (int i = 0; i < 4; i++)
#pragma unroll
                for (int j = 0; j < 4; j++) {
                    mma_bf16(acc[i][j], ah[i], bh[j][0], bh[j][1]);
                    mma_bf16(acc[i][j], ah[i], bl[j][0], bl[j][1]);
                    mma_bf16(acc[i][j], al[i], bh[j][0], bh[j][1]);
                }
        }
        __syncthreads();
        if (it + 2 < nk) LOAD_STAGE(it + 2, it & 1);
    }

    int g = lane >> 2, c2 = (lane & 3) * 2;
#pragma unroll
    for (int i = 0; i < 4; i++) {
        long long row0 = m0 + wm * 64 + i * 16 + g;
        long long row1 = row0 + 8;
        float t0 = 0.f, t1 = 0.f;
        if (EPI == 2) {
            int hh = ((int)row0 >> 7) & 127, ww = (int)row0 & 127;
            int rel = hh - ww; rel = rel < -7 ? -7 : (rel > 7 ? 7 : rel);
            t0 = btab[rel + 7];
            hh = ((int)row1 >> 7) & 127; ww = (int)row1 & 127;
            rel = hh - ww; rel = rel < -7 ? -7 : (rel > 7 ? 7 : rel);
            t1 = btab[rel + 7];
        }
#pragma unroll
        for (int j = 0; j < 4; j++) {
            int col = n0 + wn * 32 + j * 8 + c2;
            float b0 = 0.f, b1 = 0.f, cs0 = 0.f, cs1 = 0.f;
            if (EPI == 2) {
                b0 = bias[col]; b1 = bias[col + 1];
                cs0 = colsum[col]; cs1 = colsum[col + 1];
            }
            float2 v0, v1;
            v0.x = acc[i][j][0] + b0 + t0 * cs0;
            v0.y = acc[i][j][1] + b1 + t0 * cs1;
            v1.x = acc[i][j][2] + b0 + t1 * cs0;
            v1.y = acc[i][j][3] + b1 + t1 * cs1;
            *(float2*)&C[row0 * ldc + col] = v0;
            *(float2*)&C[row1 * ldc + col] = v1;
        }
    }
}

// ---------------- K feature pass: dd mma -> exp -> E bf16 hi/lo ---------------
__global__ __launch_bounds__(256) void ddk_mma() {
    extern __shared__ char smem[];
    __shared__ float redm[8];
    uint32_t sbase = smem_u32(smem);

    int tid = threadIdx.x;
    int lane = tid & 31, wid = tid >> 5;
    int wm = wid & 1, wn = wid >> 1;
    int z = blockIdx.z, b = z >> 3, hd = z & 7;
    long long m0 = (long long)blockIdx.y * 128;
    int n0 = blockIdx.x * 128;

    const __nv_bfloat16* Ahb = g_QKh + ((long long)b * NSEQ + m0) * 1024 + 512 + hd * 64;
    const __nv_bfloat16* Alb = g_QKl + ((long long)b * NSEQ + m0) * 1024 + 512 + hd * 64;
    const __nv_bfloat16* Bhb = g_Ph + n0;
    const __nv_bfloat16* Blb = g_Pl + n0;
    const int lda = 1024, ldb = NF;

    int ar0 = tid >> 2, ac0 = tid & 3;
    int ar1 = (tid + 256) >> 2, ac1 = tid & 3;
    int br0 = tid >> 4, bc0 = tid & 15;
    int br1 = (tid + 256) >> 4, bc1 = tid & 15;

#define DDK_LOAD(kt, s)                                                            \
    {                                                                              \
        uint32_t sb = sbase + (s) * STAGE_B;                                       \
        long long ka = (long long)(kt) * 32;                                       \
        CP_ASYNC16(sb + ar0 * 80 + ac0 * 16, Ahb + ar0 * lda + ka + ac0 * 8);      \
        CP_ASYNC16(sb + ar1 * 80 + ac1 * 16, Ahb + ar1 * lda + ka + ac1 * 8);      \
        CP_ASYNC16(sb + SOFF_AL + ar0 * 80 + ac0 * 16, Alb + ar0 * lda + ka + ac0 * 8); \
        CP_ASYNC16(sb + SOFF_AL + ar1 * 80 + ac1 * 16, Alb + ar1 * lda + ka + ac1 * 8); \
        CP_ASYNC16(sb + SOFF_BH + br0 * 272 + bc0 * 16, Bhb + (ka + br0) * ldb + bc0 * 8); \
        CP_ASYNC16(sb + SOFF_BH + br1 * 272 + bc1 * 16, Bhb + (ka + br1) * ldb + bc1 * 8); \
        CP_ASYNC16(sb + SOFF_BL + br0 * 272 + bc0 * 16, Blb + (ka + br0) * ldb + bc0 * 8); \
        CP_ASYNC16(sb + SOFF_BL + br1 * 272 + bc1 * 16, Blb + (ka + br1) * ldb + bc1 * 8); \
        CP_COMMIT();                                                               \
    }

    DDK_LOAD(0, 0);
    DDK_LOAD(1, 1);

    float acc[4][4][4];
#pragma unroll
    for (int i = 0; i < 4; i++)
#pragma unroll
        for (int j = 0; j < 4; j++)
#pragma unroll
            for (int r = 0; r < 4; r++) acc[i][j][r] = 0.f;

    int lrow = (lane & 7) + ((lane >> 3) & 1) * 8;
    int lcol8 = (lane >> 4) * 8;

    for (int it = 0; it < 2; ++it) {
        if (it == 0) { CP_WAIT1(); } else { CP_WAIT0(); }
        __syncthreads();
        uint32_t sb = sbase + (it & 1) * STAGE_B;
        uint32_t aAh = sb, aAl = sb + SOFF_AL, aBh = sb + SOFF_BH, aBl = sb + SOFF_BL;

#pragma unroll
        for (int ks = 0; ks < 2; ks++) {
            uint32_t ah[4][4], al[4][4];
            uint32_t bh[4][2], bl[4][2];
#pragma unroll
            for (int i = 0; i < 4; i++) {
                int r = wm * 64 + i * 16 + lrow;
                uint32_t off = (uint32_t)r * 80 + (ks * 16 + lcol8) * 2;
                ldsm_x4(ah[i], aAh + off);
                ldsm_x4(al[i], aAl + off);
            }
#pragma unroll
            for (int jj = 0; jj < 2; jj++) {
                int kr = ks * 16 + lrow;
                uint32_t off = (uint32_t)kr * 272 + (wn * 32 + jj * 16 + lcol8) * 2;
                uint32_t t[4];
                ldsm_x4_t(t, aBh + off);
                bh[jj * 2][0] = t[0]; bh[jj * 2][1] = t[1];
                bh[jj * 2 + 1][0] = t[2]; bh[jj * 2 + 1][1] = t[3];
                ldsm_x4_t(t, aBl + off);
                bl[jj * 2][0] = t[0]; bl[jj * 2][1] = t[1];
                bl[jj * 2 + 1][0] = t[2]; bl[jj * 2 + 1][1] = t[3];
            }
#pragma unroll
            for (int i = 0; i < 4; i++)
#pragma unroll
                for (int j = 0; j < 4; j++) {
                    mma_bf16(acc[i][j], ah[i], bh[j][0], bh[j][1]);
                    mma_bf16(acc[i][j], ah[i], bl[j][0], bl[j][1]);
                    mma_bf16(acc[i][j], al[i], bh[j][0], bh[j][1]);
                }
        }
        __syncthreads();
    }

    // raw-dd max
    float mx = __int_as_float(0xff800000);
#pragma unroll
    for (int i = 0; i < 4; i++)
#pragma unroll
        for (int j = 0; j < 4; j++)
#pragma unroll
            for (int r = 0; r < 4; r++) mx = fmaxf(mx, acc[i][j][r]);

    // epilogue: E = exp(dd - diag - 20), write bf16 hi/lo
    int g = lane >> 2, c2 = (lane & 3) * 2;
#pragma unroll
    for (int i = 0; i < 4; i++) {
        long long row0 = m0 + wm * 64 + i * 16 + g;
        long long row1 = row0 + 8;
        float rs0 = g_rssk[(long long)z * NSEQ + row0] + 20.f;
        float rs1 = g_rssk[(long long)z * NSEQ + row1] + 20.f;
#pragma unroll
        for (int j = 0; j < 4; j++) {
            int col = n0 + wn * 32 + j * 8 + c2;
            float e00 = __expf(acc[i][j][0] - rs0);
            float e01 = __expf(acc[i][j][1] - rs0);
            float e10 = __expf(acc[i][j][2] - rs1);
            float e11 = __expf(acc[i][j][3] - rs1);
            __nv_bfloat16 h00 = __float2bfloat16(e00), h01 = __float2bfloat16(e01);
            __nv_bfloat16 h10 = __float2bfloat16(e10), h11 = __float2bfloat16(e11);
            __nv_bfloat16 l00 = __float2bfloat16(e00 - __bfloat162float(h00));
            __nv_bfloat16 l01 = __float2bfloat16(e01 - __bfloat162float(h01));
            __nv_bfloat16 l10 = __float2bfloat16(e10 - __bfloat162float(h10));
            __nv_bfloat16 l11 = __float2bfloat16(e11 - __bfloat162float(h11));
            long long o0 = ((long long)z * NSEQ + row0) * NF + col;
            long long o1 = ((long long)z * NSEQ + row1) * NF + col;
            *(__nv_bfloat162*)&g_KPh[o0] = __nv_bfloat162(h00, h01);
            *(__nv_bfloat162*)&g_KPh[o1] = __nv_bfloat162(h10, h11);
            *(__nv_bfloat162*)&g_KPl[o0] = __nv_bfloat162(l00, l01);
            *(__nv_bfloat162*)&g_KPl[o1] = __nv_bfloat162(l10, l11);
        }
    }
#pragma unroll
    for (int o = 16; o > 0; o >>= 1) mx = fmaxf(mx, __shfl_xor_sync(0xffffffff, mx, o));
    if (lane == 0) redm[wid] = mx;
    __syncthreads();
    if (tid == 0) {
        float m2 = redm[0];
#pragma unroll
        for (int i = 1; i < 8; i++) m2 = fmaxf(m2, redm[i]);
        atomicMaxFloat(&g_kmax[z], m2);
    }
}

// ---------------- ctx via tensor cores: ctxT[d][f] = V^T @ E ------------------
// grid (NCHUNK, NZ), 256 thr; per-block K = 1024.
#define CT_AH 0
#define CT_AL 5120
#define CT_BH 10240
#define CT_BL 27136
#define CT_STAGE 44032
#define SMEM_CTX (2 * CT_STAGE)

__global__ __launch_bounds__(256) void ctx_mma() {
    extern __shared__ char smem[];
    uint32_t sbase = smem_u32(smem);
    int tid = threadIdx.x;
    int lane = tid & 31, wid = tid >> 5;
    int wm = wid & 1, wn = wid >> 1;
    int ch = blockIdx.x, z = blockIdx.y;
    int b = z >> 3, hd = z & 7;
    long long nbase = (long long)ch * CHROWS;

    const __nv_bfloat16* Ah = g_VTh + ((long long)(b * 512 + hd * 64)) * NSEQ;
    const __nv_bfloat16* Al = g_VTl + ((long long)(b * 512 + hd * 64)) * NSEQ;
    const __nv_bfloat16* Bh = g_KPh + (long long)z * NSEQ * NF;
    const __nv_bfloat16* Bl = g_KPl + (long long)z * NSEQ * NF;

    int ar = tid >> 2, asg = tid & 3;

#define CTX_LOAD(kt, s)                                                              \
    {                                                                                \
        uint32_t sb = sbase + (s) * CT_STAGE;                                        \
        long long ka = nbase + (long long)(kt) * 32;                                 \
        CP_ASYNC16(sb + CT_AH + ar * 80 + asg * 16, Ah + (long long)ar * NSEQ + ka + asg * 8); \
        CP_ASYNC16(sb + CT_AL + ar * 80 + asg * 16, Al + (long long)ar * NSEQ + ka + asg * 8); \
        _Pragma("unroll")                                                            \
        for (int ii = 0; ii < 4; ii++) {                                             \
            int idx = tid + ii * 256;                                                \
            int r = idx >> 5, sg = idx & 31;                                         \
            CP_ASYNC16(sb + CT_BH + r * 528 + sg * 16, Bh + (ka + r) * NF + sg * 8); \
            CP_ASYNC16(sb + CT_BL + r * 528 + sg * 16, Bl + (ka + r) * NF + sg * 8); \
        }                                                                            \
        CP_COMMIT();                                                                 \
    }

    CTX_LOAD(0, 0);
    CTX_LOAD(1, 1);

    float acc[2][8][4];
#pragma unroll
    for (int i = 0; i < 2; i++)
#pragma unroll
        for (int j = 0; j < 8; j++)
#pragma unroll
            for (int r = 0; r < 4; r++) acc[i][j][r] = 0.f;
    float ks_acc = 0.f;

    int lrow = (lane & 7) + ((lane >> 3) & 1) * 8;
    int lcol8 = (lane >> 4) * 8;
    const int NKK = CHROWS / 32;   // 32

    for (int it = 0; it < NKK; ++it) {
        if (it < NKK - 1) { CP_WAIT1(); } else { CP_WAIT0(); }
        __syncthreads();
        uint32_t sb = sbase + (it & 1) * CT_STAGE;
        uint32_t aAh = sb + CT_AH, aAl = sb + CT_AL, aBh = sb + CT_BH, aBl = sb + CT_BL;

        // ksum partial: f = tid over the 32-row E tile
        {
            const __nv_bfloat16* eh = (const __nv_bfloat16*)(smem + (it & 1) * CT_STAGE + CT_BH);
            const __nv_bfloat16* el = (const __nv_bfloat16*)(smem + (it & 1) * CT_STAGE + CT_BL);
#pragma unroll
            for (int r = 0; r < 32; r++)
                ks_acc += __bfloat162float(eh[r * 264 + tid]) + __bfloat162float(el[r * 264 + tid]);
        }

#pragma unroll
        for (int ks = 0; ks < 2; ks++) {
            uint32_t ah[2][4], al[2][4];
#pragma unroll
            for (int i = 0; i < 2; i++) {
                int r = wm * 32 + i * 16 + lrow;
                uint32_t off = (uint32_t)r * 80 + (ks * 16 + lcol8) * 2;
                ldsm_x4(ah[i], aAh + off);
                ldsm_x4(al[i], aAl + off);
            }
#pragma unroll
            for (int jj = 0; jj < 4; jj++) {
                int kr = ks * 16 + lrow;
                uint32_t off = (uint32_t)kr * 528 + (wn * 64 + jj * 16 + lcol8) * 2;
                uint32_t th[4], tl[4];
                ldsm_x4_t(th, aBh + off);
                ldsm_x4_t(tl, aBl + off);
#pragma unroll
                for (int i = 0; i < 2; i++) {
                    mma_bf16(acc[i][jj * 2],     ah[i], th[0], th[1]);
                    mma_bf16(acc[i][jj * 2],     ah[i], tl[0], tl[1]);
                    mma_bf16(acc[i][jj * 2],     al[i], th[0], th[1]);
                    mma_bf16(acc[i][jj * 2 + 1], ah[i], th[2], th[3]);
                    mma_bf16(acc[i][jj * 2 + 1], ah[i], tl[2], tl[3]);
                    mma_bf16(acc[i][jj * 2 + 1], al[i], th[2], th[3]);
                }
            }
        }
        __syncthreads();
        if (it + 2 < NKK) CTX_LOAD(it + 2, it & 1);
    }

    long long base = ((long long)(z * NCHUNK + ch)) * (NF * DHEAD);
    int g = lane >> 2, c2 = (lane & 3) * 2;
#pragma unroll
    for (int i = 0; i < 2; i++) {
        int d0 = wm * 32 + i * 16 + g, d1 = d0 + 8;
#pragma unroll
        for (int j = 0; j < 8; j++) {
            int f = wn * 64 + j * 8 + c2;
            *(float2*)&g_ctxP[base + d0 * 256 + f] = make_float2(acc[i][j][0], acc[i][j][1]);
            *(float2*)&g_ctxP[base + d1 * 256 + f] = make_float2(acc[i][j][2], acc[i][j][3]);
        }
    }
    g_ksumP[(z * NCHUNK + ch) * NF + tid] = ks_acc;
}

// ---------------- reduces with scale + eps corrections -------------------------
// ctx final emitted as bf16 hi/lo in [f][d] layout for the phase-2 mma.
__global__ void ctx_reduce() {
    int idx = blockIdx.x * 256 + threadIdx.x;   // NZ*16384
    int z = idx >> 14, r = idx & 16383;
    int d = r >> 8, f = r & 255;
    float sc = __expf(20.f - g_kmax[z]);
    float s = 0.f;
#pragma unroll
    for (int c = 0; c < NCHUNK; c++)
        s += g_ctxP[((long long)(z * NCHUNK + c)) * 16384 + d * 256 + f];
    float vs = g_vsum[(z >> 3) * 512 + (z & 7) * 64 + d];
    float val = 0.0625f * (sc * s + 1e-4f * vs);
    __nv_bfloat16 h = __float2bfloat16(val);
    long long o = (long long)z * 16384 + f * 64 + d;
    g_ctxh[o] = h;
    g_ctxl[o] = __float2bfloat16(val - __bfloat162float(h));
}

__global__ void ksum_reduce() {
    int z = blockIdx.x, f = threadIdx.x;
    float sc = __expf(20.f - g_kmax[z]);
    float s = 0.f;
#pragma unroll
    for (int c = 0; c < NCHUNK; c++) s += g_ksumP[(z * NCHUNK + c) * NF + f];
    g_ksum[z * NF + f] = 0.0625f * (sc * s + 1e-4f * 16384.f);
}

// ---------------- fused Q features + attention --------------------------------
// phase1: dd mma -> qp (fp32 smem); max/exp/dinv; phase2: qp@ctx via bf16-split mma.
#define QPP 260
#define FA_QP    0
#define FA_QH    133120
#define FA_QL    (FA_QH + 18432)
#define FA_PBH   (FA_QL + 18432)
#define FA_PBL   (FA_PBH + 8448)
#define FA_CS    (FA_PBL + 8448)
#define FA_KS    (FA_CS + 4352)
#define FA_RSUB  (FA_KS + 1024)
#define FA_DINV  (FA_RSUB + 512)
#define FA_RED   (FA_DINV + 512)
#define SMEM_ATTN (FA_RED + 2048)

__global__ __launch_bounds__(512, 1) void fused_attn_kernel() {
    extern __shared__ char smemc[];
    float* qp     = (float*)(smemc + FA_QP);
    __nv_bfloat16* qh = (__nv_bfloat16*)(smemc + FA_QH);
    __nv_bfloat16* ql = (__nv_bfloat16*)(smemc + FA_QL);
    __nv_bfloat16* pbh = (__nv_bfloat16*)(smemc + FA_PBH);
    __nv_bfloat16* pbl = (__nv_bfloat16*)(smemc + FA_PBL);
    float* ks     = (float*)(smemc + FA_KS);
    float* rowsub = (float*)(smemc + FA_RSUB);
    float* sdinv  = (float*)(smemc + FA_DINV);
    float* red    = (float*)(smemc + FA_RED);

    int z = blockIdx.y;
    int b = z >> 3, hd = z & 7;
    long long m0 = (long long)blockIdx.x * 128;
    int tid = threadIdx.x;
    int lane = tid & 31, wid = tid >> 5;

    long long Aq = ((long long)b * NSEQ + m0) * 1024 + hd * 64;
#pragma unroll
    for (int i = 0; i < 2; i++) {
        int idx = tid + i * 512;
        int row = idx >> 3, ch = idx & 7;
        *(uint4*)(qh + row * 72 + ch * 8) = *(const uint4*)(g_QKh + Aq + (long long)row * 1024 + ch * 8);
        *(uint4*)(ql + row * 72 + ch * 8) = *(const uint4*)(g_QKl + Aq + (long long)row * 1024 + ch * 8);
    }
    if (tid < 256) ks[tid] = g_ksum[z * NF + tid];
    if (tid < 128) rowsub[tid] = g_rssq[(long long)z * NSEQ + m0 + tid];
    __syncthreads();

    // ---- phase 1: dd = Q @ (DN*projT) via bf16-split mma ----
    {
        int wm = wid & 3, wn = wid >> 2;
        int lrow = (lane & 7) + ((lane >> 3) & 1) * 8;
        int lcol8 = (lane >> 4) * 8;
        uint32_t qhB = smem_u32(qh), qlB = smem_u32(ql);
        uint32_t pbhB = smem_u32(pbh), pblB = smem_u32(pbl);

        float acc[2][8][4];
#pragma unroll
        for (int i = 0; i < 2; i++)
#pragma unroll
            for (int j = 0; j < 8; j++)
#pragma unroll
                for (int r = 0; r < 4; r++) acc[i][j][r] = 0.f;

        for (int c0 = 0; c0 < 64; c0 += 16) {
            __syncthreads();
            {
                int row = tid >> 5, c16 = tid & 31;
                *(uint4*)(pbh + row * 264 + c16 * 8) = *(const uint4*)(g_Ph + (c0 + row) * NF + c16 * 8);
                *(uint4*)(pbl + row * 264 + c16 * 8) = *(const uint4*)(g_Pl + (c0 + row) * NF + c16 * 8);
            }
            __syncthreads();
            uint32_t ah[2][4], al[2][4];
#pragma unroll
            for (int i = 0; i < 2; i++) {
                int r = wm * 32 + i * 16 + lrow;
                uint32_t off = (uint32_t)r * 144 + (c0 + lcol8) * 2;
                ldsm_x4(ah[i], qhB + off);
                ldsm_x4(al[i], qlB + off);
            }
#pragma unroll
            for (int jj = 0; jj < 4; jj++) {
                uint32_t offb = (uint32_t)lrow * 528 + (wn * 64 + jj * 16 + lcol8) * 2;
                uint32_t th[4], tl[4];
                ldsm_x4_t(th, pbhB + offb);
                ldsm_x4_t(tl, pblB + offb);
#pragma unroll
                for (int i = 0; i < 2; i++) {
                    mma_bf16(acc[i][jj * 2],     ah[i], th[0], th[1]);
                    mma_bf16(acc[i][jj * 2],     ah[i], tl[0], tl[1]);
                    mma_bf16(acc[i][jj * 2],     al[i], th[0], th[1]);
                    mma_bf16(acc[i][jj * 2 + 1], ah[i], th[2], th[3]);
                    mma_bf16(acc[i][jj * 2 + 1], ah[i], tl[2], tl[3]);
                    mma_bf16(acc[i][jj * 2 + 1], al[i], th[2], th[3]);
                }
            }
        }
        __syncthreads();
        int g = lane >> 2, c2 = (lane & 3) * 2;
#pragma unroll
        for (int i = 0; i < 2; i++) {
            int r0 = wm * 32 + i * 16 + g, r1 = r0 + 8;
#pragma unroll
            for (int j = 0; j < 8; j++) {
                int col = wn * 64 + j * 8 + c2;
                qp[r0 * QPP + col]     = acc[i][j][0];
                qp[r0 * QPP + col + 1] = acc[i][j][1];
                qp[r1 * QPP + col]     = acc[i][j][2];
                qp[r1 * QPP + col + 1] = acc[i][j][3];
            }
        }
    }
    __syncthreads();

    // row max (raw dd), rowsub = diag + max
    {
        int r = tid >> 2, p = tid & 3;
        float mx = __int_as_float(0xff800000);
        for (int f = p * 64; f < p * 64 + 64; f++) mx = fmaxf(mx, qp[r * QPP + f]);
        red[r * 4 + p] = mx;
    }
    __syncthreads();
    if (tid < 128) {
        float m = fmaxf(fmaxf(red[tid * 4], red[tid * 4 + 1]), fmaxf(red[tid * 4 + 2], red[tid * 4 + 3]));
        rowsub[tid] += m;
    }
    __syncthreads();

#pragma unroll
    for (int i = 0; i < 64; i++) {
        int idx = i * 512 + tid;
        int r = idx >> 8, f = idx & 255;
        float v = qp[r * QPP + f];
        qp[r * QPP + f] = 0.0625f * (__expf(v - rowsub[r]) + 1e-4f);
    }
    __syncthreads();

    // dinv
    {
        int r = tid >> 2, p = tid & 3;
        float s = 0.f;
        for (int f = p * 64; f < p * 64 + 64; f++) s += qp[r * QPP + f] * ks[f];
        red[r * 4 + p] = s;
    }
    __syncthreads();
    if (tid < 128)
        sdinv[tid] = 1.0f / (red[tid * 4] + red[tid * 4 + 1] + red[tid * 4 + 2] + red[tid * 4 + 3]);

    // ---- phase 2: attn = qp @ ctx via bf16-split mma ----
    // reuse qh region: qph (128 x pitch24 = 48B rows, 16B-aligned), qpl after 3072 elems
    __nv_bfloat16* qph = qh;
    __nv_bfloat16* qpl = qh + 3072;
    __nv_bfloat16* cbh = pbh;     // 16 x pitch72 (144B rows, 16B-aligned)
    __nv_bfloat16* cbl = pbl;
    const __nv_bfloat16* ctxh = g_ctxh + (long long)z * NF * DHEAD;
    const __nv_bfloat16* ctxl = g_ctxl + (long long)z * NF * DHEAD;

    int wm2 = wid & 3, wn2 = wid >> 2;
    int lrow = (lane & 7) + ((lane >> 3) & 1) * 8;
    int lcol8 = (lane >> 4) * 8;
    uint32_t qphB = smem_u32(qph), qplB = smem_u32(qpl);
    uint32_t cbhB = smem_u32(cbh), cblB = smem_u32(cbl);

    float acc2[2][2][4];
#pragma unroll
    for (int i = 0; i < 2; i++)
#pragma unroll
        for (int j = 0; j < 2; j++)
#pragma unroll
            for (int r = 0; r < 4; r++) acc2[i][j][r] = 0.f;

    for (int f0 = 0; f0 < NF; f0 += 16) {
        __syncthreads();
        // convert qp chunk [128 x 16] fp32 -> bf16 hi/lo (pitch 24)
#pragma unroll
        for (int j = 0; j < 4; j++) {
            int idx = tid + j * 512;
            int r = idx >> 4, c = idx & 15;
            float v = qp[r * QPP + f0 + c];
            __nv_bfloat16 h = __float2bfloat16(v);
            qph[r * 24 + c] = h;
            qpl[r * 24 + c] = __float2bfloat16(v - __bfloat162float(h));
        }
        // load ctx chunk [16 k x 64 d] hi/lo (pitch 72)
        {
            int k = tid >> 5, d2 = (tid & 31) * 2;
            *(__nv_bfloat162*)&cbh[k * 72 + d2] = *(const __nv_bfloat162*)&ctxh[(long long)(f0 + k) * 64 + d2];
            *(__nv_bfloat162*)&cbl[k * 72 + d2] = *(const __nv_bfloat162*)&ctxl[(long long)(f0 + k) * 64 + d2];
        }
        __syncthreads();
        uint32_t ah2[2][4], al2[2][4], th[4], tl[4];
#pragma unroll
        for (int i = 0; i < 2; i++) {
            int r = wm2 * 32 + i * 16 + lrow;
            uint32_t off = (uint32_t)(r * 48 + lcol8 * 2);
            ldsm_x4(ah2[i], qphB + off);
            ldsm_x4(al2[i], qplB + off);
        }
        {
            uint32_t offb = (uint32_t)(lrow * 144 + (wn2 * 16 + lcol8) * 2);
            ldsm_x4_t(th, cbhB + offb);
            ldsm_x4_t(tl, cblB + offb);
        }
#pragma unroll
        for (int i = 0; i < 2; i++) {
            mma_bf16(acc2[i][0], ah2[i], th[0], th[1]);
            mma_bf16(acc2[i][0], ah2[i], tl[0], tl[1]);
            mma_bf16(acc2[i][0], al2[i], th[0], th[1]);
            mma_bf16(acc2[i][1], ah2[i], th[2], th[3]);
            mma_bf16(acc2[i][1], ah2[i], tl[2], tl[3]);
            mma_bf16(acc2[i][1], al2[i], th[2], th[3]);
        }
    }

    // epilogue: *dinv, split to ATT hi/lo
    int g2 = lane >> 2, c22 = (lane & 3) * 2;
#pragma unroll
    for (int i = 0; i < 2; i++) {
        int r0 = wm2 * 32 + i * 16 + g2, r1 = r0 + 8;
        float s0 = sdinv[r0], s1 = sdinv[r1];
#pragma unroll
        for (int jn = 0; jn < 2; jn++) {
            int col = wn2 * 16 + jn * 8 + c22;
            float v00 = acc2[i][jn][0] * s0, v01 = acc2[i][jn][1] * s0;
            float v10 = acc2[i][jn][2] * s1, v11 = acc2[i][jn][3] * s1;
            __nv_bfloat16 h00 = __float2bfloat16(v00), h01 = __float2bfloat16(v01);
            __nv_bfloat16 h10 = __float2bfloat16(v10), h11 = __float2bfloat16(v11);
            __nv_bfloat16 l00 = __float2bfloat16(v00 - __bfloat162float(h00));
            __nv_bfloat16 l01 = __float2bfloat16(v01 - __bfloat162float(h01));
            __nv_bfloat16 l10 = __float2bfloat16(v10 - __bfloat162float(h10));
            __nv_bfloat16 l11 = __float2bfloat16(v11 - __bfloat162float(h11));
            long long base0 = ((long long)b * NSEQ + m0 + r0) * INNERD + hd * DHEAD + col;
            long long base1 = ((long long)b * NSEQ + m0 + r1) * INNERD + hd * DHEAD + col;
            *(__nv_bfloat162*)&g_ATTh[base0] = __nv_bfloat162(h00, h01);
            *(__nv_bfloat162*)&g_ATTh[base1] = __nv_bfloat162(h10, h11);
            *(__nv_bfloat162*)&g_ATTl[base0] = __nv_bfloat162(l00, l01);
            *(__nv_bfloat162*)&g_ATTl[base1] = __nv_bfloat162(l10, l11);
        }
    }
}

// ---------------- launcher ----------------------------------------------------
extern "C" void kernel_launch(void* const* d_in, const int* in_sizes, int n_in,
                              void* d_out, int out_size) {
    const float* x    = (const float*)d_in[0];
    const float* Wq   = (const float*)d_in[1];
    const float* Wk   = (const float*)d_in[2];
    const float* Wv   = (const float*)d_in[3];
    const float* Wo   = (const float*)d_in[4];
    const float* bo   = (const float*)d_in[5];
    const float* proj = (const float*)d_in[6];
    const float* Wp   = (const float*)d_in[7];
    const float* bp   = (const float*)d_in[8];
    const float* btab = (const float*)d_in[9];
    float* out = (float*)d_out;

    static bool attr_set = false;
    if (!attr_set) {
        cudaFuncSetAttribute(fused_attn_kernel, cudaFuncAttributeMaxDynamicSharedMemorySize, SMEM_ATTN);
        cudaFuncSetAttribute(mma_gemm<0>, cudaFuncAttributeMaxDynamicSharedMemorySize, SMEM_MMA);
        cudaFuncSetAttribute(mma_gemm<2>, cudaFuncAttributeMaxDynamicSharedMemorySize, SMEM_MMA);
        cudaFuncSetAttribute(ddk_mma, cudaFuncAttributeMaxDynamicSharedMemorySize, SMEM_MMA);
        cudaFuncSetAttribute(ctx_mma, cudaFuncAttributeMaxDynamicSharedMemorySize, SMEM_CTX);
        attr_set = true;
    }

    float *pQKV, *pWoWp, *pB2, *pCS;
    __nv_bfloat16 *pXh, *pXl, *pWch, *pWcl, *pATTh, *pATTl, *pWoWph, *pWoWpl;
    cudaGetSymbolAddress((void**)&pQKV,   g_QKV);
    cudaGetSymbolAddress((void**)&pWoWp,  g_WoWp);
    cudaGetSymbolAddress((void**)&pB2,    g_bias2);
    cudaGetSymbolAddress((void**)&pCS,    g_colsum);
    cudaGetSymbolAddress((void**)&pXh,    g_Xh);
    cudaGetSymbolAddress((void**)&pXl,    g_Xl);
    cudaGetSymbolAddress((void**)&pWch,   g_Wch);
    cudaGetSymbolAddress((void**)&pWcl,   g_Wcl);
    cudaGetSymbolAddress((void**)&pATTh,  g_ATTh);
    cudaGetSymbolAddress((void**)&pATTl,  g_ATTl);
    cudaGetSymbolAddress((void**)&pWoWph, g_WoWph);
    cudaGetSymbolAddress((void**)&pWoWpl, g_WoWpl);

    init_kernel<<<1, 32>>>();
    transpose_proj_split<<<64, 256>>>(proj);
    bias2_kernel<<<1, 256>>>(bo, Wp, bp);
    split_x_kernel<<<TOK * CDIM / 1024, 256>>>(x);
    pack_w_kernel<<<CDIM * QKVLD / 256, 256>>>(Wq, Wk, Wv);

    sgemm128<<<dim3(CDIM / 128, INNERD / 128), 256>>>(Wo, Wp, pWoWp, CDIM, CDIM, CDIM, CDIM);
    split_wowp_kernel<<<INNERD * CDIM / 256, 256>>>();

    // QKV fused tensor GEMM
    mma_gemm<0><<<dim3(QKVLD / 128, TOK / 128), 256, SMEM_MMA>>>(
        pXh, pXl, pWch, pWcl, pQKV, CDIM, CDIM, QKVLD, QKVLD,
        nullptr, nullptr, nullptr);

    split_qk_kernel<<<TOK, 256>>>();
    vt_kernel<<<dim3(NSEQ / 64, 8, 4), 256>>>();
    vsum_reduce<<<8, 256>>>();

    // K features: dd mma + exp -> E bf16
    ddk_mma<<<dim3(NF / 128, NSEQ / 128, NZ), 256, SMEM_MMA>>>();

    // ctx on tensor cores + reduces with scale/eps (ctx -> bf16 hi/lo)
    ctx_mma<<<dim3(NCHUNK, NZ), 256, SMEM_CTX>>>();
    ksum_reduce<<<NZ, 256>>>();
    ctx_reduce<<<(NZ * NF * DHEAD) / 256, 256>>>();

    fused_attn_kernel<<<dim3(NSEQ / 128, NZ), 512, SMEM_ATTN>>>();

    // out = ATT @ WoWp + bias2 + rel*colsum
    mma_gemm<2><<<dim3(CDIM / 128, TOK / 128), 256, SMEM_MMA>>>(
        pATTh, pATTl, pWoWph, pWoWpl, out, INNERD, INNERD, CDIM, CDIM,
        pB2, btab, pCS);

    (void)in_sizes; (void)n_in; (void)out_size;
}